// round 3
// baseline (speedup 1.0000x reference)
#include <cuda_runtime.h>
#include <math.h>

// Problem constants (fixed by setup_inputs)
#define BATCH   2
#define SEQ     2048
#define DIMM    2048
#define HEADS   16
#define DHEAD   128
#define INNER   2048            // HEADS*DHEAD
#define TOKENS  (BATCH*SEQ)     // 4096
#define HIST    512             // S - original_context_length (2048-1536)
#define QSCALE  0.08838834764831845f  // 1/sqrt(128)

// Scratch (static __device__ arrays — allocation-free per harness rules).
// g_q is reused as the attention-output buffer after stage 3 consumes q.
__device__ float g_q[(size_t)TOKENS * INNER];
__device__ float g_k[(size_t)TOKENS * INNER];
__device__ float g_v[(size_t)TOKENS * INNER];
__device__ float g_attn[(size_t)BATCH * HEADS * SEQ * SEQ];  // 537 MB

// ---------------------------------------------------------------------------
// Tiled fp32 GEMM: C[m,n] = sum_k A[m,k] * B(n,k or k,n) + bias[n]
//   BT=true : B indexed [n*ldb + k]  (NT — weights, K^T)
//   BT=false: B indexed [k*ldb + n]  (NN — P@V)
// Block tile 128x128, K-tile 16, 256 threads, 8x8 per thread.
// Batch offset per blockIdx.z: off = (z/HEADS)*s1 + (z%HEADS)*s2
// ---------------------------------------------------------------------------
template<bool BT>
__global__ void __launch_bounds__(256)
gemm_kernel(const float* __restrict__ A, const float* __restrict__ Bm,
            const float* __restrict__ bias, float* __restrict__ C,
            int M, int N, int K, int lda, int ldb, int ldc,
            long long sA1, long long sA2,
            long long sB1, long long sB2,
            long long sC1, long long sC2)
{
    const int z = blockIdx.z;
    const long long zb = z / HEADS, zh = z % HEADS;
    A  += zb * sA1 + zh * sA2;
    Bm += zb * sB1 + zh * sB2;
    C  += zb * sC1 + zh * sC2;

    __shared__ float As[16][132];
    __shared__ float Bs[16][132];

    const int tid  = threadIdx.x;
    const int tx   = tid & 15;
    const int ty   = tid >> 4;
    const int row0 = blockIdx.y * 128;
    const int col0 = blockIdx.x * 128;

    float acc[8][8];
    #pragma unroll
    for (int i = 0; i < 8; i++)
        #pragma unroll
        for (int j = 0; j < 8; j++) acc[i][j] = 0.f;

    for (int k0 = 0; k0 < K; k0 += 16) {
        // A tile: 128 rows x 16 k, transposed into As[k][m]
        #pragma unroll
        for (int l = 0; l < 2; l++) {
            int f  = tid + l * 256;
            int r  = f >> 2;
            int kq = (f & 3) * 4;
            float4 val = *reinterpret_cast<const float4*>(
                &A[(long long)(row0 + r) * lda + k0 + kq]);
            As[kq + 0][r] = val.x; As[kq + 1][r] = val.y;
            As[kq + 2][r] = val.z; As[kq + 3][r] = val.w;
        }
        if (BT) {
            #pragma unroll
            for (int l = 0; l < 2; l++) {
                int f  = tid + l * 256;
                int r  = f >> 2;
                int kq = (f & 3) * 4;
                float4 val = *reinterpret_cast<const float4*>(
                    &Bm[(long long)(col0 + r) * ldb + k0 + kq]);
                Bs[kq + 0][r] = val.x; Bs[kq + 1][r] = val.y;
                Bs[kq + 2][r] = val.z; Bs[kq + 3][r] = val.w;
            }
        } else {
            #pragma unroll
            for (int l = 0; l < 2; l++) {
                int f  = tid + l * 256;
                int kk = f >> 5;
                int c  = (f & 31) * 4;
                float4 val = *reinterpret_cast<const float4*>(
                    &Bm[(long long)(k0 + kk) * ldb + col0 + c]);
                *reinterpret_cast<float4*>(&Bs[kk][c]) = val;
            }
        }
        __syncthreads();

        #pragma unroll
        for (int kk = 0; kk < 16; kk++) {
            float a[8], b[8];
            *reinterpret_cast<float4*>(&a[0]) = *reinterpret_cast<float4*>(&As[kk][ty * 8]);
            *reinterpret_cast<float4*>(&a[4]) = *reinterpret_cast<float4*>(&As[kk][ty * 8 + 4]);
            *reinterpret_cast<float4*>(&b[0]) = *reinterpret_cast<float4*>(&Bs[kk][tx * 8]);
            *reinterpret_cast<float4*>(&b[4]) = *reinterpret_cast<float4*>(&Bs[kk][tx * 8 + 4]);
            #pragma unroll
            for (int i = 0; i < 8; i++)
                #pragma unroll
                for (int j = 0; j < 8; j++)
                    acc[i][j] += a[i] * b[j];
        }
        __syncthreads();
    }

    #pragma unroll
    for (int i = 0; i < 8; i++) {
        int r = row0 + ty * 8 + i;
        #pragma unroll
        for (int j = 0; j < 8; j += 4) {
            int c = col0 + tx * 8 + j;
            float4 val;
            val.x = acc[i][j]; val.y = acc[i][j + 1];
            val.z = acc[i][j + 2]; val.w = acc[i][j + 3];
            if (bias) {
                val.x += bias[c];     val.y += bias[c + 1];
                val.z += bias[c + 2]; val.w += bias[c + 3];
            }
            *reinterpret_cast<float4*>(&C[(long long)r * ldc + c]) = val;
        }
    }
}

// ---------------------------------------------------------------------------
// Fused RMSNorm (over full 2048) + RoPE + history-key scale / q softmax scale.
// grid.x = token (0..4095), grid.y = 0 (q) / 1 (k), 256 threads.
// Each thread handles 4 even/odd pairs (8 floats).
// ---------------------------------------------------------------------------
__global__ void __launch_bounds__(256)
normrope_kernel(float* __restrict__ q, float* __restrict__ k,
                const float* __restrict__ rope,
                const float* __restrict__ wq, const float* __restrict__ wk,
                const float* __restrict__ hks)
{
    const int tok = blockIdx.x;
    const int s   = tok & (SEQ - 1);
    const bool isK = (blockIdx.y == 1);
    float* x = (isK ? k : q) + (long long)tok * INNER;
    const float* w = isK ? wk : wq;
    const int tid = threadIdx.x;

    float2 vals[4];
    float ss = 0.f;
    #pragma unroll
    for (int l = 0; l < 4; l++) {
        int p = tid + 256 * l;
        float2 vv = *reinterpret_cast<const float2*>(&x[2 * p]);
        ss += vv.x * vv.x + vv.y * vv.y;
        vals[l] = vv;
    }
    #pragma unroll
    for (int off = 16; off; off >>= 1) ss += __shfl_xor_sync(0xFFFFFFFFu, ss, off);
    __shared__ float sred[8];
    if ((tid & 31) == 0) sred[tid >> 5] = ss;
    __syncthreads();
    float tot = 0.f;
    #pragma unroll
    for (int i = 0; i < 8; i++) tot += sred[i];
    const float inv = rsqrtf(tot * (1.f / (float)INNER) + 1e-5f);

    #pragma unroll
    for (int l = 0; l < 4; l++) {
        int p = tid + 256 * l;       // pair index in [0,1024)
        int h = p >> 6;              // head
        int i = p & 63;              // pair within head
        float c  = rope[(long long)s * 256 + 2 * i];
        float sn = rope[(long long)s * 256 + 128 + 2 * i + 1];
        float x1 = vals[l].x * inv * w[2 * p];
        float x2 = vals[l].y * inv * w[2 * p + 1];
        float e = x1 * c - x2 * sn;
        float o = x1 * sn + x2 * c;
        float mult;
        if (isK) {
            mult = (s < HIST) ? (1.f + 9.f / (1.f + __expf(-hks[h]))) : 1.f;
        } else {
            mult = QSCALE;           // fold 1/sqrt(dhead) into q
        }
        *reinterpret_cast<float2*>(&x[2 * p]) = make_float2(e * mult, o * mult);
    }
}

// ---------------------------------------------------------------------------
// Row softmax over 2048 entries. One block per row, 256 threads (8 vals each).
// ---------------------------------------------------------------------------
__global__ void __launch_bounds__(256)
softmax_kernel(float* __restrict__ attn)
{
    float* p = attn + (long long)blockIdx.x * SEQ;
    const int tid = threadIdx.x;
    float vals[8];
    float m = -1e30f;
    #pragma unroll
    for (int l = 0; l < 8; l++) {
        vals[l] = p[tid + 256 * l];
        m = fmaxf(m, vals[l]);
    }
    #pragma unroll
    for (int off = 16; off; off >>= 1) m = fmaxf(m, __shfl_xor_sync(0xFFFFFFFFu, m, off));
    __shared__ float sm[8], ssum[8];
    if ((tid & 31) == 0) sm[tid >> 5] = m;
    __syncthreads();
    float mm = sm[0];
    #pragma unroll
    for (int i = 1; i < 8; i++) mm = fmaxf(mm, sm[i]);

    float s = 0.f;
    #pragma unroll
    for (int l = 0; l < 8; l++) { vals[l] = __expf(vals[l] - mm); s += vals[l]; }
    #pragma unroll
    for (int off = 16; off; off >>= 1) s += __shfl_xor_sync(0xFFFFFFFFu, s, off);
    if ((tid & 31) == 0) ssum[tid >> 5] = s;
    __syncthreads();
    float tot = 0.f;
    #pragma unroll
    for (int i = 0; i < 8; i++) tot += ssum[i];
    const float inv = 1.f / tot;
    #pragma unroll
    for (int l = 0; l < 8; l++) p[tid + 256 * l] = vals[l] * inv;
}

// ---------------------------------------------------------------------------
extern "C" void kernel_launch(void* const* d_in, const int* in_sizes, int n_in,
                              void* d_out, int out_size)
{
    const float* hs   = (const float*)d_in[0];
    const float* rope = (const float*)d_in[1];
    const float* Wq   = (const float*)d_in[2];
    const float* bq   = (const float*)d_in[3];
    const float* Wk   = (const float*)d_in[4];
    const float* bk   = (const float*)d_in[5];
    const float* Wv   = (const float*)d_in[6];
    const float* bv   = (const float*)d_in[7];
    const float* nqw  = (const float*)d_in[8];
    const float* nkw  = (const float*)d_in[9];
    const float* hks  = (const float*)d_in[10];
    const float* Wo   = (const float*)d_in[11];
    const float* bo   = (const float*)d_in[12];
    float* out = (float*)d_out;

    float *q, *k, *v, *attn;
    cudaGetSymbolAddress((void**)&q,    g_q);
    cudaGetSymbolAddress((void**)&k,    g_k);
    cudaGetSymbolAddress((void**)&v,    g_v);
    cudaGetSymbolAddress((void**)&attn, g_attn);

    dim3 blk(256);

    // 1) QKV projections: [4096,2048] = X @ W^T + b
    dim3 g1(INNER / 128, TOKENS / 128, 1);
    gemm_kernel<true><<<g1, blk>>>(hs, Wq, bq, q, TOKENS, INNER, DIMM,
                                   DIMM, DIMM, INNER, 0, 0, 0, 0, 0, 0);
    gemm_kernel<true><<<g1, blk>>>(hs, Wk, bk, k, TOKENS, INNER, DIMM,
                                   DIMM, DIMM, INNER, 0, 0, 0, 0, 0, 0);
    gemm_kernel<true><<<g1, blk>>>(hs, Wv, bv, v, TOKENS, INNER, DIMM,
                                   DIMM, DIMM, INNER, 0, 0, 0, 0, 0, 0);

    // 2) RMSNorm + RoPE + scales (in place on q, k)
    normrope_kernel<<<dim3(TOKENS, 2), blk>>>(q, k, rope, nqw, nkw, hks);

    // 3) Scores: per (b,h)  S = Qh @ Kh^T   (M=N=2048, K=128)
    dim3 g2(SEQ / 128, SEQ / 128, BATCH * HEADS);
    gemm_kernel<true><<<g2, blk>>>(q, k, nullptr, attn, SEQ, SEQ, DHEAD,
                                   INNER, INNER, SEQ,
                                   (long long)SEQ * INNER, DHEAD,
                                   (long long)SEQ * INNER, DHEAD,
                                   (long long)HEADS * SEQ * SEQ, (long long)SEQ * SEQ);

    // 4) Softmax rows
    softmax_kernel<<<BATCH * HEADS * SEQ, blk>>>(attn);

    // 5) O = P @ V   (M=2048, N=128, K=2048, NN) — writes into g_q (q is dead)
    dim3 g3(DHEAD / 128, SEQ / 128, BATCH * HEADS);
    gemm_kernel<false><<<g3, blk>>>(attn, v, nullptr, q, SEQ, DHEAD, SEQ,
                                    SEQ, INNER, INNER,
                                    (long long)HEADS * SEQ * SEQ, (long long)SEQ * SEQ,
                                    (long long)SEQ * INNER, DHEAD,
                                    (long long)SEQ * INNER, DHEAD);

    // 6) Output projection: out = attn_out_flat @ Wo^T + bo
    dim3 g4(DIMM / 128, TOKENS / 128, 1);
    gemm_kernel<true><<<g4, blk>>>(q, Wo, bo, out, TOKENS, DIMM, INNER,
                                   INNER, INNER, DIMM, 0, 0, 0, 0, 0, 0);
}

// round 5
// speedup vs baseline: 1.8090x; 1.8090x over previous
#include <cuda_runtime.h>
#include <cuda_bf16.h>
#include <stdint.h>
#include <math.h>

// Problem constants
#define BATCH   2
#define SEQ     2048
#define DIMM    2048
#define HEADS   16
#define DHEAD   128
#define INNER   2048
#define TOKENS  (BATCH*SEQ)
#define HIST    512
#define QSCALE  0.08838834764831845f

// GEMM tiling
#define BM 128
#define BN 128
#define BK 32
#define ROWW 40          // smem row stride in bf16 elems (80B, conflict-free for ldmatrix)
#define NTHREADS 256

// Scratch
__device__ float g_q[(size_t)TOKENS * INNER];
__device__ float g_k[(size_t)TOKENS * INNER];
__device__ float g_v[(size_t)TOKENS * INNER];
__device__ float g_attn[(size_t)BATCH * HEADS * SEQ * SEQ];

__device__ __forceinline__ uint32_t smem_u32(const void* p) {
    uint32_t a;
    asm("{ .reg .u64 t; cvta.to.shared.u64 t, %1; cvt.u32.u64 %0, t; }" : "=r"(a) : "l"(p));
    return a;
}

#define LDSM4(r, a) \
    asm volatile("ldmatrix.sync.aligned.m8n8.x4.shared.b16 {%0,%1,%2,%3}, [%4];" \
        : "=r"((r)[0]), "=r"((r)[1]), "=r"((r)[2]), "=r"((r)[3]) : "r"(a))

#define MMA16816(d, a, b0, b1) \
    asm volatile("mma.sync.aligned.m16n8k16.row.col.f32.bf16.bf16.f32 " \
        "{%0,%1,%2,%3}, {%4,%5,%6,%7}, {%8,%9}, {%0,%1,%2,%3};" \
        : "+f"((d)[0]), "+f"((d)[1]), "+f"((d)[2]), "+f"((d)[3]) \
        : "r"((a)[0]), "r"((a)[1]), "r"((a)[2]), "r"((a)[3]), "r"(b0), "r"(b1))

__device__ __forceinline__ uint32_t packbf(float a, float b) {
    __nv_bfloat162 t = __floats2bfloat162_rn(a, b);
    return *reinterpret_cast<uint32_t*>(&t);
}

// ---------------------------------------------------------------------------
// HMMA (mma.sync) bf16 hi/lo-split GEMM: C = A @ B(^T) + bias, fp32 in/out.
//   BT=true : B global [n][k] (weights / K^T)
//   BT=false: B global [k][n] (P@V) — transposed during smem fill
// Tile 128x128xBK32, 8 warps (4M x 2N), warp tile 32x64.
// ---------------------------------------------------------------------------
template<bool BT>
__global__ void __launch_bounds__(NTHREADS)
mma_gemm(const float* __restrict__ A, const float* __restrict__ Bm,
         const float* __restrict__ bias, float* __restrict__ C,
         int K, int lda, int ldb, int ldc,
         long long sA1, long long sA2,
         long long sB1, long long sB2,
         long long sC1, long long sC2)
{
    const int z = blockIdx.z;
    const long long zb = z / HEADS, zh = z % HEADS;
    A  += zb * sA1 + zh * sA2;
    Bm += zb * sB1 + zh * sB2;
    C  += zb * sC1 + zh * sC2;

    __shared__ __align__(16) __nv_bfloat16 smAh[BM * ROWW];
    __shared__ __align__(16) __nv_bfloat16 smAl[BM * ROWW];
    __shared__ __align__(16) __nv_bfloat16 smBh[BN * ROWW];
    __shared__ __align__(16) __nv_bfloat16 smBl[BN * ROWW];

    const int tid  = threadIdx.x;
    const int wid  = tid >> 5;
    const int lane = tid & 31;
    const int row0 = blockIdx.y * BM;
    const int col0 = blockIdx.x * BN;
    const int wm   = (wid & 3) * 32;   // warp M offset in tile
    const int wn   = (wid >> 2) * 64;  // warp N offset in tile

    const uint32_t aH = smem_u32(smAh);
    const uint32_t aL = smem_u32(smAl);
    const uint32_t bH = smem_u32(smBh);
    const uint32_t bL = smem_u32(smBl);

    float acc[2][8][4];
    #pragma unroll
    for (int i = 0; i < 2; i++)
        #pragma unroll
        for (int j = 0; j < 8; j++)
            #pragma unroll
            for (int t = 0; t < 4; t++) acc[i][j][t] = 0.f;

    // ldmatrix lane address components (constant across chunks)
    const int aRow = wm + (lane & 15);
    const int aColOff = (lane >> 4) << 3;
    const int bRowBase = wn + (lane & 7) + ((lane >> 4) << 3);
    const int bColOff = ((lane >> 3) & 1) << 3;

    for (int k0 = 0; k0 < K; k0 += BK) {
        // ---- fill A tile ----
        #pragma unroll
        for (int l = 0; l < 4; l++) {
            int f  = tid + l * 256;
            int r  = f >> 3;
            int kq = (f & 7) << 2;
            float4 v = *reinterpret_cast<const float4*>(
                &A[(long long)(row0 + r) * lda + k0 + kq]);
            float h0 = __bfloat162float(__float2bfloat16_rn(v.x));
            float h1 = __bfloat162float(__float2bfloat16_rn(v.y));
            float h2 = __bfloat162float(__float2bfloat16_rn(v.z));
            float h3 = __bfloat162float(__float2bfloat16_rn(v.w));
            int o = r * ROWW + kq;
            *reinterpret_cast<uint2*>(&smAh[o]) =
                make_uint2(packbf(h0, h1), packbf(h2, h3));
            *reinterpret_cast<uint2*>(&smAl[o]) =
                make_uint2(packbf(v.x - h0, v.y - h1), packbf(v.z - h2, v.w - h3));
        }
        // ---- fill B tile ----
        if (BT) {
            #pragma unroll
            for (int l = 0; l < 4; l++) {
                int f  = tid + l * 256;
                int r  = f >> 3;
                int kq = (f & 7) << 2;
                float4 v = *reinterpret_cast<const float4*>(
                    &Bm[(long long)(col0 + r) * ldb + k0 + kq]);
                float h0 = __bfloat162float(__float2bfloat16_rn(v.x));
                float h1 = __bfloat162float(__float2bfloat16_rn(v.y));
                float h2 = __bfloat162float(__float2bfloat16_rn(v.z));
                float h3 = __bfloat162float(__float2bfloat16_rn(v.w));
                int o = r * ROWW + kq;
                *reinterpret_cast<uint2*>(&smBh[o]) =
                    make_uint2(packbf(h0, h1), packbf(h2, h3));
                *reinterpret_cast<uint2*>(&smBl[o]) =
                    make_uint2(packbf(v.x - h0, v.y - h1), packbf(v.z - h2, v.w - h3));
            }
        } else {
            // global [k][n] -> smem [n][k]
            #pragma unroll
            for (int l = 0; l < 4; l++) {
                int f  = tid + l * 256;
                int kr = f >> 5;
                int nq = (f & 31) << 2;
                float4 v = *reinterpret_cast<const float4*>(
                    &Bm[(long long)(k0 + kr) * ldb + col0 + nq]);
                float vv[4] = {v.x, v.y, v.z, v.w};
                #pragma unroll
                for (int j = 0; j < 4; j++) {
                    float h = __bfloat162float(__float2bfloat16_rn(vv[j]));
                    int o = (nq + j) * ROWW + kr;
                    smBh[o] = __float2bfloat16_rn(vv[j]);
                    smBl[o] = __float2bfloat16_rn(vv[j] - h);
                }
            }
        }
        __syncthreads();

        // ---- MMA over this chunk ----
        #pragma unroll
        for (int kk = 0; kk < BK; kk += 16) {
            uint32_t ah[2][4], al[2][4];
            #pragma unroll
            for (int mi = 0; mi < 2; mi++) {
                uint32_t off = ((aRow + mi * 16) * ROWW + kk + aColOff) * 2;
                LDSM4(ah[mi], aH + off);
                LDSM4(al[mi], aL + off);
            }
            #pragma unroll
            for (int ng = 0; ng < 4; ng++) {
                uint32_t bh[4], bl[4];
                uint32_t off = ((bRowBase + ng * 16) * ROWW + kk + bColOff) * 2;
                LDSM4(bh, bH + off);
                LDSM4(bl, bL + off);
                #pragma unroll
                for (int mi = 0; mi < 2; mi++) {
                    #pragma unroll
                    for (int s = 0; s < 2; s++) {
                        float* d = acc[mi][ng * 2 + s];
                        MMA16816(d, ah[mi], bh[s * 2], bh[s * 2 + 1]);
                        MMA16816(d, ah[mi], bl[s * 2], bl[s * 2 + 1]);
                        MMA16816(d, al[mi], bh[s * 2], bh[s * 2 + 1]);
                    }
                }
            }
        }
        __syncthreads();
    }

    // ---- epilogue ----
    #pragma unroll
    for (int mi = 0; mi < 2; mi++) {
        int r = row0 + wm + mi * 16 + (lane >> 2);
        #pragma unroll
        for (int nf = 0; nf < 8; nf++) {
            int c = col0 + wn + nf * 8 + (lane & 3) * 2;
            float b0 = 0.f, b1 = 0.f;
            if (bias) { b0 = bias[c]; b1 = bias[c + 1]; }
            float2 v0 = make_float2(acc[mi][nf][0] + b0, acc[mi][nf][1] + b1);
            float2 v1 = make_float2(acc[mi][nf][2] + b0, acc[mi][nf][3] + b1);
            *reinterpret_cast<float2*>(&C[(long long)r * ldc + c]) = v0;
            *reinterpret_cast<float2*>(&C[(long long)(r + 8) * ldc + c]) = v1;
        }
    }
}

// ---------------------------------------------------------------------------
// Fused RMSNorm + RoPE + history-key scale / q softmax scale
// ---------------------------------------------------------------------------
__global__ void __launch_bounds__(256)
normrope_kernel(float* __restrict__ q, float* __restrict__ k,
                const float* __restrict__ rope,
                const float* __restrict__ wq, const float* __restrict__ wk,
                const float* __restrict__ hks)
{
    const int tok = blockIdx.x;
    const int s   = tok & (SEQ - 1);
    const bool isK = (blockIdx.y == 1);
    float* x = (isK ? k : q) + (long long)tok * INNER;
    const float* w = isK ? wk : wq;
    const int tid = threadIdx.x;

    float2 vals[4];
    float ss = 0.f;
    #pragma unroll
    for (int l = 0; l < 4; l++) {
        int p = tid + 256 * l;
        float2 vv = *reinterpret_cast<const float2*>(&x[2 * p]);
        ss += vv.x * vv.x + vv.y * vv.y;
        vals[l] = vv;
    }
    #pragma unroll
    for (int off = 16; off; off >>= 1) ss += __shfl_xor_sync(0xFFFFFFFFu, ss, off);
    __shared__ float sred[8];
    if ((tid & 31) == 0) sred[tid >> 5] = ss;
    __syncthreads();
    float tot = 0.f;
    #pragma unroll
    for (int i = 0; i < 8; i++) tot += sred[i];
    const float inv = rsqrtf(tot * (1.f / (float)INNER) + 1e-5f);

    #pragma unroll
    for (int l = 0; l < 4; l++) {
        int p = tid + 256 * l;
        int h = p >> 6;
        int i = p & 63;
        float c  = rope[(long long)s * 256 + 2 * i];
        float sn = rope[(long long)s * 256 + 128 + 2 * i + 1];
        float x1 = vals[l].x * inv * w[2 * p];
        float x2 = vals[l].y * inv * w[2 * p + 1];
        float e = x1 * c - x2 * sn;
        float o = x1 * sn + x2 * c;
        float mult;
        if (isK) {
            mult = (s < HIST) ? (1.f + 9.f / (1.f + __expf(-hks[h]))) : 1.f;
        } else {
            mult = QSCALE;
        }
        *reinterpret_cast<float2*>(&x[2 * p]) = make_float2(e * mult, o * mult);
    }
}

// ---------------------------------------------------------------------------
// Row softmax over 2048 entries
// ---------------------------------------------------------------------------
__global__ void __launch_bounds__(256)
softmax_kernel(float* __restrict__ attn)
{
    float* p = attn + (long long)blockIdx.x * SEQ;
    const int tid = threadIdx.x;
    float vals[8];
    float m = -1e30f;
    #pragma unroll
    for (int l = 0; l < 8; l++) {
        vals[l] = p[tid + 256 * l];
        m = fmaxf(m, vals[l]);
    }
    #pragma unroll
    for (int off = 16; off; off >>= 1) m = fmaxf(m, __shfl_xor_sync(0xFFFFFFFFu, m, off));
    __shared__ float sm[8], ssum[8];
    if ((tid & 31) == 0) sm[tid >> 5] = m;
    __syncthreads();
    float mm = sm[0];
    #pragma unroll
    for (int i = 1; i < 8; i++) mm = fmaxf(mm, sm[i]);

    float s = 0.f;
    #pragma unroll
    for (int l = 0; l < 8; l++) { vals[l] = __expf(vals[l] - mm); s += vals[l]; }
    #pragma unroll
    for (int off = 16; off; off >>= 1) s += __shfl_xor_sync(0xFFFFFFFFu, s, off);
    if ((tid & 31) == 0) ssum[tid >> 5] = s;
    __syncthreads();
    float tot = 0.f;
    #pragma unroll
    for (int i = 0; i < 8; i++) tot += ssum[i];
    const float inv = 1.f / tot;
    #pragma unroll
    for (int l = 0; l < 8; l++) p[tid + 256 * l] = vals[l] * inv;
}

// ---------------------------------------------------------------------------
extern "C" void kernel_launch(void* const* d_in, const int* in_sizes, int n_in,
                              void* d_out, int out_size)
{
    const float* hs   = (const float*)d_in[0];
    const float* rope = (const float*)d_in[1];
    const float* Wq   = (const float*)d_in[2];
    const float* bq   = (const float*)d_in[3];
    const float* Wk   = (const float*)d_in[4];
    const float* bk   = (const float*)d_in[5];
    const float* Wv   = (const float*)d_in[6];
    const float* bv   = (const float*)d_in[7];
    const float* nqw  = (const float*)d_in[8];
    const float* nkw  = (const float*)d_in[9];
    const float* hks  = (const float*)d_in[10];
    const float* Wo   = (const float*)d_in[11];
    const float* bo   = (const float*)d_in[12];
    float* out = (float*)d_out;

    float *q, *k, *v, *attn;
    cudaGetSymbolAddress((void**)&q,    g_q);
    cudaGetSymbolAddress((void**)&k,    g_k);
    cudaGetSymbolAddress((void**)&v,    g_v);
    cudaGetSymbolAddress((void**)&attn, g_attn);

    dim3 blk(NTHREADS);

    // 1) QKV projections
    dim3 g1(INNER / BN, TOKENS / BM, 1);
    mma_gemm<true><<<g1, blk>>>(hs, Wq, bq, q, DIMM, DIMM, DIMM, INNER,
                                0, 0, 0, 0, 0, 0);
    mma_gemm<true><<<g1, blk>>>(hs, Wk, bk, k, DIMM, DIMM, DIMM, INNER,
                                0, 0, 0, 0, 0, 0);
    mma_gemm<true><<<g1, blk>>>(hs, Wv, bv, v, DIMM, DIMM, DIMM, INNER,
                                0, 0, 0, 0, 0, 0);

    // 2) RMSNorm + RoPE + scales
    normrope_kernel<<<dim3(TOKENS, 2), blk>>>(q, k, rope, nqw, nkw, hks);

    // 3) Scores: per (b,h)  S = Qh @ Kh^T
    dim3 g2(SEQ / BN, SEQ / BM, BATCH * HEADS);
    mma_gemm<true><<<g2, blk>>>(q, k, nullptr, attn, DHEAD, INNER, INNER, SEQ,
                                (long long)SEQ * INNER, DHEAD,
                                (long long)SEQ * INNER, DHEAD,
                                (long long)HEADS * SEQ * SEQ, (long long)SEQ * SEQ);

    // 4) Softmax rows
    softmax_kernel<<<BATCH * HEADS * SEQ, blk>>>(attn);

    // 5) O = P @ V  (NN) — into g_q (dead)
    dim3 g3(DHEAD / BN, SEQ / BM, BATCH * HEADS);
    mma_gemm<false><<<g3, blk>>>(attn, v, nullptr, q, SEQ, SEQ, INNER, INNER,
                                 (long long)HEADS * SEQ * SEQ, (long long)SEQ * SEQ,
                                 (long long)SEQ * INNER, DHEAD,
                                 (long long)SEQ * INNER, DHEAD);

    // 6) Output projection
    dim3 g4(DIMM / BN, TOKENS / BM, 1);
    mma_gemm<true><<<g4, blk>>>(q, Wo, bo, out, INNER, INNER, INNER, DIMM,
                                0, 0, 0, 0, 0, 0);
}

// round 7
// speedup vs baseline: 2.1595x; 1.1937x over previous
#include <cuda_runtime.h>
#include <cuda_bf16.h>
#include <stdint.h>
#include <math.h>

// Problem constants
#define BATCH   2
#define SEQ     2048
#define DIMM    2048
#define HEADS   16
#define DHEAD   128
#define INNER   2048
#define TOKENS  (BATCH*SEQ)
#define HIST    512
#define QSCALE  0.08838834764831845f

// GEMM tiling
#define BM 128
#define BN 128
#define BK 32
#define NTHREADS 256

// Dynamic smem layout (two stages)
#define OFFAH   0
#define OFFAL   10240
#define OFFBH   20480
#define OFFBL_BT 30720
#define OFFBL_NN 29184
#define STAGE_SZ 40960
#define SMEM_TOTAL 81920

// fp32 scratch
__device__ float g_q[(size_t)TOKENS * INNER];
__device__ float g_k[(size_t)TOKENS * INNER];
__device__ float g_attn[(size_t)BATCH * HEADS * SEQ * SEQ];
// bf16 hi/lo scratch
__device__ __nv_bfloat16 g_ah[(size_t)TOKENS * INNER];   // hs, later attn-out
__device__ __nv_bfloat16 g_al[(size_t)TOKENS * INNER];
__device__ __nv_bfloat16 g_wh[(size_t)INNER * DIMM];     // current weight
__device__ __nv_bfloat16 g_wl[(size_t)INNER * DIMM];
__device__ __nv_bfloat16 g_qh[(size_t)TOKENS * INNER];
__device__ __nv_bfloat16 g_ql[(size_t)TOKENS * INNER];
__device__ __nv_bfloat16 g_kh[(size_t)TOKENS * INNER];
__device__ __nv_bfloat16 g_kl[(size_t)TOKENS * INNER];
__device__ __nv_bfloat16 g_vh[(size_t)TOKENS * INNER];
__device__ __nv_bfloat16 g_vl[(size_t)TOKENS * INNER];
__device__ __nv_bfloat16 g_ph[(size_t)BATCH * HEADS * SEQ * SEQ];
__device__ __nv_bfloat16 g_pl[(size_t)BATCH * HEADS * SEQ * SEQ];

__device__ __forceinline__ uint32_t smem_u32(const void* p) {
    uint32_t a;
    asm("{ .reg .u64 t; cvta.to.shared.u64 t, %1; cvt.u32.u64 %0, t; }" : "=r"(a) : "l"(p));
    return a;
}

#define CP16(dst, src) \
    asm volatile("cp.async.cg.shared.global [%0], [%1], 16;" \
        :: "r"(dst), "l"(__cvta_generic_to_global(src)) : "memory")
#define CP_COMMIT() asm volatile("cp.async.commit_group;" ::: "memory")
#define CP_WAIT(n)  asm volatile("cp.async.wait_group %0;" :: "n"(n) : "memory")

#define LDSM4(r, a) \
    asm volatile("ldmatrix.sync.aligned.m8n8.x4.shared.b16 {%0,%1,%2,%3}, [%4];" \
        : "=r"((r)[0]), "=r"((r)[1]), "=r"((r)[2]), "=r"((r)[3]) : "r"(a))
#define LDSM4T(r, a) \
    asm volatile("ldmatrix.sync.aligned.m8n8.x4.trans.shared.b16 {%0,%1,%2,%3}, [%4];" \
        : "=r"((r)[0]), "=r"((r)[1]), "=r"((r)[2]), "=r"((r)[3]) : "r"(a))

#define MMA16816(d, a, b0, b1) \
    asm volatile("mma.sync.aligned.m16n8k16.row.col.f32.bf16.bf16.f32 " \
        "{%0,%1,%2,%3}, {%4,%5,%6,%7}, {%8,%9}, {%0,%1,%2,%3};" \
        : "+f"((d)[0]), "+f"((d)[1]), "+f"((d)[2]), "+f"((d)[3]) \
        : "r"((a)[0]), "r"((a)[1]), "r"((a)[2]), "r"((a)[3]), "r"(b0), "r"(b1))

__device__ __forceinline__ uint32_t packbf(float a, float b) {
    __nv_bfloat162 t = __floats2bfloat162_rn(a, b);
    return *reinterpret_cast<uint32_t*>(&t);
}
__device__ __forceinline__ void splitf(float v, __nv_bfloat16& h, __nv_bfloat16& l) {
    h = __float2bfloat16_rn(v);
    l = __float2bfloat16_rn(v - __bfloat162float(h));
}

// ---------------------------------------------------------------------------
// fp32 -> bf16 hi/lo conversion (vectorized, n multiple of 1024)
// ---------------------------------------------------------------------------
__global__ void __launch_bounds__(256)
convert_kernel(const float* __restrict__ x,
               __nv_bfloat16* __restrict__ h, __nv_bfloat16* __restrict__ l)
{
    int i = (blockIdx.x * 256 + threadIdx.x) * 4;
    float4 v = *reinterpret_cast<const float4*>(x + i);
    float h0 = __bfloat162float(__float2bfloat16_rn(v.x));
    float h1 = __bfloat162float(__float2bfloat16_rn(v.y));
    float h2 = __bfloat162float(__float2bfloat16_rn(v.z));
    float h3 = __bfloat162float(__float2bfloat16_rn(v.w));
    *reinterpret_cast<uint2*>(h + i) = make_uint2(packbf(h0, h1), packbf(h2, h3));
    *reinterpret_cast<uint2*>(l + i) =
        make_uint2(packbf(v.x - h0, v.y - h1), packbf(v.z - h2, v.w - h3));
}

// ---------------------------------------------------------------------------
// cp.async tile fill (one stage). A: [BM][BK] from [m][k]; B: BT -> [BN][BK]
// from [n][k]; NN -> [BK][BN] from [k][n]. Row pads: A/B-BT 80B, B-NN 272B.
// ---------------------------------------------------------------------------
template<bool BT>
__device__ __forceinline__ void fill_stage(uint32_t st,
    const __nv_bfloat16* __restrict__ Ah, const __nv_bfloat16* __restrict__ Al,
    const __nv_bfloat16* __restrict__ Bh, const __nv_bfloat16* __restrict__ Bl,
    int row0, int col0, int k0, int lda, int ldb, int tid)
{
    #pragma unroll
    for (int l = 0; l < 4; l++) {
        int c = (tid + l * 256) & 511;
        int r = c >> 2;
        int kc = (c & 3) * 8;
        const __nv_bfloat16* src = (l < 2) ? Ah : Al;
        uint32_t dst = st + ((l < 2) ? OFFAH : OFFAL) + r * 80 + kc * 2;
        CP16(dst, &src[(long long)(row0 + r) * lda + k0 + kc]);
    }
    if (BT) {
        #pragma unroll
        for (int l = 0; l < 4; l++) {
            int c = (tid + l * 256) & 511;
            int r = c >> 2;
            int kc = (c & 3) * 8;
            const __nv_bfloat16* src = (l < 2) ? Bh : Bl;
            uint32_t dst = st + ((l < 2) ? OFFBH : OFFBL_BT) + r * 80 + kc * 2;
            CP16(dst, &src[(long long)(col0 + r) * ldb + k0 + kc]);
        }
    } else {
        #pragma unroll
        for (int l = 0; l < 4; l++) {
            int c = (tid + l * 256) & 511;
            int r = c >> 4;
            int nc = (c & 15) * 8;
            const __nv_bfloat16* src = (l < 2) ? Bh : Bl;
            uint32_t dst = st + ((l < 2) ? OFFBH : OFFBL_NN) + r * 272 + nc * 2;
            CP16(dst, &src[(long long)(k0 + r) * ldb + col0 + nc]);
        }
    }
}

// ---------------------------------------------------------------------------
// HMMA bf16 hi/lo-split GEMM, pre-converted operands, cp.async double buffer.
//   BT=true : B [n][k]; BT=false: B [k][n] (ldmatrix.trans)
//   SPLIT=false: C fp32 (+bias); SPLIT=true: C -> bf16 hi/lo pair (+bias)
// ---------------------------------------------------------------------------
template<bool BT, bool SPLIT>
__global__ void __launch_bounds__(NTHREADS)
mma_gemm(const __nv_bfloat16* __restrict__ Ah, const __nv_bfloat16* __restrict__ Al,
         const __nv_bfloat16* __restrict__ Bh, const __nv_bfloat16* __restrict__ Bl,
         const float* __restrict__ bias,
         float* __restrict__ C, __nv_bfloat16* __restrict__ Ch,
         __nv_bfloat16* __restrict__ Cl,
         int K, int lda, int ldb, int ldc,
         long long sA1, long long sA2,
         long long sB1, long long sB2,
         long long sC1, long long sC2)
{
    extern __shared__ __align__(16) char dynsm[];
    const int z = blockIdx.z;
    const long long zb = z / HEADS, zh = z % HEADS;
    Ah += zb * sA1 + zh * sA2;  Al += zb * sA1 + zh * sA2;
    Bh += zb * sB1 + zh * sB2;  Bl += zb * sB1 + zh * sB2;
    const long long coff = zb * sC1 + zh * sC2;

    const int tid  = threadIdx.x;
    const int wid  = tid >> 5;
    const int lane = tid & 31;
    const int row0 = blockIdx.y * BM;
    const int col0 = blockIdx.x * BN;
    const int wm   = (wid & 3) * 32;
    const int wn   = (wid >> 2) * 64;

    const uint32_t smBase = smem_u32(dynsm);

    float acc[2][8][4];
    #pragma unroll
    for (int i = 0; i < 2; i++)
        #pragma unroll
        for (int j = 0; j < 8; j++)
            #pragma unroll
            for (int t = 0; t < 4; t++) acc[i][j][t] = 0.f;

    // ldmatrix lane addressing
    const int aRow = wm + (lane & 15);
    const int aColOff = (lane >> 4) << 3;
    const int bRowBT = wn + (lane & 7) + ((lane >> 4) << 3);
    const int bColBT = ((lane >> 3) & 1) << 3;
    const int bRowNN = (lane & 7) + (((lane >> 3) & 1) << 3);
    const int bColNN = wn + ((lane >> 4) << 3);

    const int nch = K / BK;
    fill_stage<BT>(smBase, Ah, Al, Bh, Bl, row0, col0, 0, lda, ldb, tid);
    CP_COMMIT();

    for (int ch = 0; ch < nch; ch++) {
        const uint32_t st = smBase + (ch & 1) * STAGE_SZ;
        if (ch + 1 < nch) {
            fill_stage<BT>(smBase + ((ch + 1) & 1) * STAGE_SZ,
                           Ah, Al, Bh, Bl, row0, col0, (ch + 1) * BK, lda, ldb, tid);
            CP_COMMIT();
            CP_WAIT(1);
        } else {
            CP_WAIT(0);
        }
        __syncthreads();

        #pragma unroll
        for (int kk = 0; kk < BK; kk += 16) {
            uint32_t ah[2][4], al[2][4];
            #pragma unroll
            for (int mi = 0; mi < 2; mi++) {
                uint32_t off = (aRow + mi * 16) * 80 + (kk + aColOff) * 2;
                LDSM4(ah[mi], st + OFFAH + off);
                LDSM4(al[mi], st + OFFAL + off);
            }
            #pragma unroll
            for (int ng = 0; ng < 4; ng++) {
                uint32_t bh[4], bl[4];
                if (BT) {
                    uint32_t off = (bRowBT + ng * 16) * 80 + (kk + bColBT) * 2;
                    LDSM4(bh, st + OFFBH + off);
                    LDSM4(bl, st + OFFBL_BT + off);
                } else {
                    uint32_t off = (kk + bRowNN) * 272 + (bColNN + ng * 16) * 2;
                    LDSM4T(bh, st + OFFBH + off);
                    LDSM4T(bl, st + OFFBL_NN + off);
                }
                #pragma unroll
                for (int mi = 0; mi < 2; mi++) {
                    #pragma unroll
                    for (int s = 0; s < 2; s++) {
                        float* d = acc[mi][ng * 2 + s];
                        MMA16816(d, ah[mi], bh[s * 2], bh[s * 2 + 1]);
                        MMA16816(d, ah[mi], bl[s * 2], bl[s * 2 + 1]);
                        MMA16816(d, al[mi], bh[s * 2], bh[s * 2 + 1]);
                    }
                }
            }
        }
        __syncthreads();
    }

    // ---- epilogue ----
    #pragma unroll
    for (int mi = 0; mi < 2; mi++) {
        int r = row0 + wm + mi * 16 + (lane >> 2);
        #pragma unroll
        for (int nf = 0; nf < 8; nf++) {
            int c = col0 + wn + nf * 8 + (lane & 3) * 2;
            float b0 = 0.f, b1 = 0.f;
            if (bias) { b0 = bias[c]; b1 = bias[c + 1]; }
            float v00 = acc[mi][nf][0] + b0, v01 = acc[mi][nf][1] + b1;
            float v10 = acc[mi][nf][2] + b0, v11 = acc[mi][nf][3] + b1;
            long long i0 = coff + (long long)r * ldc + c;
            long long i1 = coff + (long long)(r + 8) * ldc + c;
            if (SPLIT) {
                float h00 = __bfloat162float(__float2bfloat16_rn(v00));
                float h01 = __bfloat162float(__float2bfloat16_rn(v01));
                float h10 = __bfloat162float(__float2bfloat16_rn(v10));
                float h11 = __bfloat162float(__float2bfloat16_rn(v11));
                *reinterpret_cast<uint32_t*>(Ch + i0) = packbf(h00, h01);
                *reinterpret_cast<uint32_t*>(Cl + i0) = packbf(v00 - h00, v01 - h01);
                *reinterpret_cast<uint32_t*>(Ch + i1) = packbf(h10, h11);
                *reinterpret_cast<uint32_t*>(Cl + i1) = packbf(v10 - h10, v11 - h11);
            } else {
                *reinterpret_cast<float2*>(C + i0) = make_float2(v00, v01);
                *reinterpret_cast<float2*>(C + i1) = make_float2(v10, v11);
            }
        }
    }
}

// ---------------------------------------------------------------------------
// Fused RMSNorm + RoPE + scales; reads fp32 q/k, writes bf16 hi/lo splits.
// ---------------------------------------------------------------------------
__global__ void __launch_bounds__(256)
normrope_kernel(const float* __restrict__ q, const float* __restrict__ k,
                const float* __restrict__ rope,
                const float* __restrict__ wq, const float* __restrict__ wk,
                const float* __restrict__ hks,
                __nv_bfloat16* __restrict__ qh, __nv_bfloat16* __restrict__ ql,
                __nv_bfloat16* __restrict__ kh, __nv_bfloat16* __restrict__ kl)
{
    const int tok = blockIdx.x;
    const int s   = tok & (SEQ - 1);
    const bool isK = (blockIdx.y == 1);
    const float* x = (isK ? k : q) + (long long)tok * INNER;
    __nv_bfloat16* oh = (isK ? kh : qh) + (long long)tok * INNER;
    __nv_bfloat16* ol = (isK ? kl : ql) + (long long)tok * INNER;
    const float* w = isK ? wk : wq;
    const int tid = threadIdx.x;

    float2 vals[4];
    float ss = 0.f;
    #pragma unroll
    for (int l = 0; l < 4; l++) {
        int p = tid + 256 * l;
        float2 vv = *reinterpret_cast<const float2*>(&x[2 * p]);
        ss += vv.x * vv.x + vv.y * vv.y;
        vals[l] = vv;
    }
    #pragma unroll
    for (int off = 16; off; off >>= 1) ss += __shfl_xor_sync(0xFFFFFFFFu, ss, off);
    __shared__ float sred[8];
    if ((tid & 31) == 0) sred[tid >> 5] = ss;
    __syncthreads();
    float tot = 0.f;
    #pragma unroll
    for (int i = 0; i < 8; i++) tot += sred[i];
    const float inv = rsqrtf(tot * (1.f / (float)INNER) + 1e-5f);

    #pragma unroll
    for (int l = 0; l < 4; l++) {
        int p = tid + 256 * l;
        int h = p >> 6;
        int i = p & 63;
        float c  = rope[(long long)s * 256 + 2 * i];
        float sn = rope[(long long)s * 256 + 128 + 2 * i + 1];
        float x1 = vals[l].x * inv * w[2 * p];
        float x2 = vals[l].y * inv * w[2 * p + 1];
        float e = x1 * c - x2 * sn;
        float o = x1 * sn + x2 * c;
        float mult;
        if (isK) {
            mult = (s < HIST) ? (1.f + 9.f / (1.f + __expf(-hks[h]))) : 1.f;
        } else {
            mult = QSCALE;
        }
        e *= mult; o *= mult;
        float eh = __bfloat162float(__float2bfloat16_rn(e));
        float oh2 = __bfloat162float(__float2bfloat16_rn(o));
        *reinterpret_cast<uint32_t*>(&oh[2 * p]) = packbf(eh, oh2);
        *reinterpret_cast<uint32_t*>(&ol[2 * p]) = packbf(e - eh, o - oh2);
    }
}

// ---------------------------------------------------------------------------
// Row softmax over 2048; reads fp32 scores, writes bf16 hi/lo probs.
// ---------------------------------------------------------------------------
__global__ void __launch_bounds__(256)
softmax_kernel(const float* __restrict__ attn,
               __nv_bfloat16* __restrict__ ph, __nv_bfloat16* __restrict__ pl)
{
    const long long rb = (long long)blockIdx.x * SEQ;
    const float* p = attn + rb;
    const int tid = threadIdx.x;
    float2 vals[4];
    float m = -1e30f;
    #pragma unroll
    for (int l = 0; l < 4; l++) {
        vals[l] = *reinterpret_cast<const float2*>(&p[2 * (tid + 256 * l)]);
        m = fmaxf(m, fmaxf(vals[l].x, vals[l].y));
    }
    #pragma unroll
    for (int off = 16; off; off >>= 1) m = fmaxf(m, __shfl_xor_sync(0xFFFFFFFFu, m, off));
    __shared__ float sm[8], ssum[8];
    if ((tid & 31) == 0) sm[tid >> 5] = m;
    __syncthreads();
    float mm = sm[0];
    #pragma unroll
    for (int i = 1; i < 8; i++) mm = fmaxf(mm, sm[i]);

    float s = 0.f;
    #pragma unroll
    for (int l = 0; l < 4; l++) {
        vals[l].x = __expf(vals[l].x - mm);
        vals[l].y = __expf(vals[l].y - mm);
        s += vals[l].x + vals[l].y;
    }
    #pragma unroll
    for (int off = 16; off; off >>= 1) s += __shfl_xor_sync(0xFFFFFFFFu, s, off);
    if ((tid & 31) == 0) ssum[tid >> 5] = s;
    __syncthreads();
    float tot = 0.f;
    #pragma unroll
    for (int i = 0; i < 8; i++) tot += ssum[i];
    const float inv = 1.f / tot;
    #pragma unroll
    for (int l = 0; l < 4; l++) {
        float a = vals[l].x * inv, b = vals[l].y * inv;
        float ha = __bfloat162float(__float2bfloat16_rn(a));
        float hb = __bfloat162float(__float2bfloat16_rn(b));
        long long idx = rb + 2 * (tid + 256 * l);
        *reinterpret_cast<uint32_t*>(&ph[idx]) = packbf(ha, hb);
        *reinterpret_cast<uint32_t*>(&pl[idx]) = packbf(a - ha, b - hb);
    }
}

// ---------------------------------------------------------------------------
extern "C" void kernel_launch(void* const* d_in, const int* in_sizes, int n_in,
                              void* d_out, int out_size)
{
    const float* hs   = (const float*)d_in[0];
    const float* rope = (const float*)d_in[1];
    const float* Wq   = (const float*)d_in[2];
    const float* bq   = (const float*)d_in[3];
    const float* Wk   = (const float*)d_in[4];
    const float* bk   = (const float*)d_in[5];
    const float* Wv   = (const float*)d_in[6];
    const float* bv   = (const float*)d_in[7];
    const float* nqw  = (const float*)d_in[8];
    const float* nkw  = (const float*)d_in[9];
    const float* hks  = (const float*)d_in[10];
    const float* Wo   = (const float*)d_in[11];
    const float* bo   = (const float*)d_in[12];
    float* out = (float*)d_out;

    float *q, *k, *attn;
    __nv_bfloat16 *ah, *al, *wh, *wl, *qh, *ql, *kh, *kl, *vh, *vl, *ph, *pl;
    cudaGetSymbolAddress((void**)&q,    g_q);
    cudaGetSymbolAddress((void**)&k,    g_k);
    cudaGetSymbolAddress((void**)&attn, g_attn);
    cudaGetSymbolAddress((void**)&ah,   g_ah);
    cudaGetSymbolAddress((void**)&al,   g_al);
    cudaGetSymbolAddress((void**)&wh,   g_wh);
    cudaGetSymbolAddress((void**)&wl,   g_wl);
    cudaGetSymbolAddress((void**)&qh,   g_qh);
    cudaGetSymbolAddress((void**)&ql,   g_ql);
    cudaGetSymbolAddress((void**)&kh,   g_kh);
    cudaGetSymbolAddress((void**)&kl,   g_kl);
    cudaGetSymbolAddress((void**)&vh,   g_vh);
    cudaGetSymbolAddress((void**)&vl,   g_vl);
    cudaGetSymbolAddress((void**)&ph,   g_ph);
    cudaGetSymbolAddress((void**)&pl,   g_pl);

    cudaFuncSetAttribute(mma_gemm<true, false>,
        cudaFuncAttributeMaxDynamicSharedMemorySize, SMEM_TOTAL);
    cudaFuncSetAttribute(mma_gemm<true, true>,
        cudaFuncAttributeMaxDynamicSharedMemorySize, SMEM_TOTAL);
    cudaFuncSetAttribute(mma_gemm<false, true>,
        cudaFuncAttributeMaxDynamicSharedMemorySize, SMEM_TOTAL);

    dim3 blk(NTHREADS);

    // 0) convert hidden states
    convert_kernel<<<TOKENS * DIMM / 1024, 256>>>(hs, ah, al);

    // 1) QKV projections (weights converted into shared buffer sequentially)
    dim3 g1(INNER / BN, TOKENS / BM, 1);
    convert_kernel<<<INNER * DIMM / 1024, 256>>>(Wq, wh, wl);
    mma_gemm<true, false><<<g1, blk, SMEM_TOTAL>>>(ah, al, wh, wl, bq, q, nullptr, nullptr,
        DIMM, DIMM, DIMM, INNER, 0, 0, 0, 0, 0, 0);
    convert_kernel<<<INNER * DIMM / 1024, 256>>>(Wk, wh, wl);
    mma_gemm<true, false><<<g1, blk, SMEM_TOTAL>>>(ah, al, wh, wl, bk, k, nullptr, nullptr,
        DIMM, DIMM, DIMM, INNER, 0, 0, 0, 0, 0, 0);
    convert_kernel<<<INNER * DIMM / 1024, 256>>>(Wv, wh, wl);
    mma_gemm<true, true><<<g1, blk, SMEM_TOTAL>>>(ah, al, wh, wl, bv, nullptr, vh, vl,
        DIMM, DIMM, DIMM, INNER, 0, 0, 0, 0, 0, 0);

    // 2) RMSNorm + RoPE + scales -> bf16 splits
    normrope_kernel<<<dim3(TOKENS, 2), blk>>>(q, k, rope, nqw, nkw, hks,
                                              qh, ql, kh, kl);

    // 3) Scores S = Qh @ Kh^T (fp32)
    dim3 g2(SEQ / BN, SEQ / BM, BATCH * HEADS);
    mma_gemm<true, false><<<g2, blk, SMEM_TOTAL>>>(qh, ql, kh, kl, nullptr, attn,
        nullptr, nullptr, DHEAD, INNER, INNER, SEQ,
        (long long)SEQ * INNER, DHEAD,
        (long long)SEQ * INNER, DHEAD,
        (long long)HEADS * SEQ * SEQ, (long long)SEQ * SEQ);

    // 4) Softmax -> bf16 splits
    softmax_kernel<<<BATCH * HEADS * SEQ, blk>>>(attn, ph, pl);

    // 5) O = P @ V (NN) -> bf16 splits into g_ah/g_al (hs dead)
    dim3 g3(DHEAD / BN, SEQ / BM, BATCH * HEADS);
    mma_gemm<false, true><<<g3, blk, SMEM_TOTAL>>>(ph, pl, vh, vl, nullptr, nullptr,
        ah, al, SEQ, SEQ, INNER, INNER,
        (long long)HEADS * SEQ * SEQ, (long long)SEQ * SEQ,
        (long long)SEQ * INNER, DHEAD,
        (long long)SEQ * INNER, DHEAD);

    // 6) Output projection (fp32 out + bias)
    dim3 g4(DIMM / BN, TOKENS / BM, 1);
    convert_kernel<<<INNER * DIMM / 1024, 256>>>(Wo, wh, wl);
    mma_gemm<true, false><<<g4, blk, SMEM_TOTAL>>>(ah, al, wh, wl, bo, out,
        nullptr, nullptr, INNER, INNER, INNER, DIMM, 0, 0, 0, 0, 0, 0);
}

// round 8
// speedup vs baseline: 2.4390x; 1.1294x over previous
#include <cuda_runtime.h>
#include <cuda_bf16.h>
#include <stdint.h>
#include <math.h>

// Problem constants
#define BATCH   2
#define SEQ     2048
#define DIMM    2048
#define HEADS   16
#define DHEAD   128
#define INNER   2048
#define TOKENS  (BATCH*SEQ)
#define HIST    512
#define QSCALE  0.08838834764831845f

// GEMM tiling
#define BM 128
#define BN 128
#define BK 32
#define NTHREADS 256

// Dynamic smem layout (two stages)
#define OFFAH   0
#define OFFAL   10240
#define OFFBH   20480
#define OFFBL_BT 30720
#define OFFBL_NN 29184
#define STAGE_SZ 40960
#define SMEM_TOTAL 81920

// fp32 scratch
__device__ float g_q[(size_t)TOKENS * INNER];
__device__ float g_k[(size_t)TOKENS * INNER];
__device__ float g_attn[(size_t)BATCH * HEADS * SEQ * SEQ];
// bf16 hi/lo scratch
__device__ __nv_bfloat16 g_ah[(size_t)TOKENS * INNER];   // hs, later attn-out
__device__ __nv_bfloat16 g_al[(size_t)TOKENS * INNER];
__device__ __nv_bfloat16 g_wqh[(size_t)INNER * DIMM];
__device__ __nv_bfloat16 g_wql[(size_t)INNER * DIMM];
__device__ __nv_bfloat16 g_wkh[(size_t)INNER * DIMM];
__device__ __nv_bfloat16 g_wkl[(size_t)INNER * DIMM];
__device__ __nv_bfloat16 g_wvh[(size_t)INNER * DIMM];
__device__ __nv_bfloat16 g_wvl[(size_t)INNER * DIMM];
__device__ __nv_bfloat16 g_woh[(size_t)INNER * DIMM];
__device__ __nv_bfloat16 g_wol[(size_t)INNER * DIMM];
__device__ __nv_bfloat16 g_qh[(size_t)TOKENS * INNER];
__device__ __nv_bfloat16 g_ql[(size_t)TOKENS * INNER];
__device__ __nv_bfloat16 g_kh[(size_t)TOKENS * INNER];
__device__ __nv_bfloat16 g_kl[(size_t)TOKENS * INNER];
__device__ __nv_bfloat16 g_vh[(size_t)TOKENS * INNER];
__device__ __nv_bfloat16 g_vl[(size_t)TOKENS * INNER];
__device__ __nv_bfloat16 g_ph[(size_t)BATCH * HEADS * SEQ * SEQ];
__device__ __nv_bfloat16 g_pl[(size_t)BATCH * HEADS * SEQ * SEQ];

__device__ __forceinline__ uint32_t smem_u32(const void* p) {
    uint32_t a;
    asm("{ .reg .u64 t; cvta.to.shared.u64 t, %1; cvt.u32.u64 %0, t; }" : "=r"(a) : "l"(p));
    return a;
}

#define CP16(dst, src) \
    asm volatile("cp.async.cg.shared.global [%0], [%1], 16;" \
        :: "r"(dst), "l"(__cvta_generic_to_global(src)) : "memory")
#define CP_COMMIT() asm volatile("cp.async.commit_group;" ::: "memory")
#define CP_WAIT(n)  asm volatile("cp.async.wait_group %0;" :: "n"(n) : "memory")

#define LDSM4(r, a) \
    asm volatile("ldmatrix.sync.aligned.m8n8.x4.shared.b16 {%0,%1,%2,%3}, [%4];" \
        : "=r"((r)[0]), "=r"((r)[1]), "=r"((r)[2]), "=r"((r)[3]) : "r"(a))
#define LDSM4T(r, a) \
    asm volatile("ldmatrix.sync.aligned.m8n8.x4.trans.shared.b16 {%0,%1,%2,%3}, [%4];" \
        : "=r"((r)[0]), "=r"((r)[1]), "=r"((r)[2]), "=r"((r)[3]) : "r"(a))

#define MMA16816(d, a, b0, b1) \
    asm volatile("mma.sync.aligned.m16n8k16.row.col.f32.bf16.bf16.f32 " \
        "{%0,%1,%2,%3}, {%4,%5,%6,%7}, {%8,%9}, {%0,%1,%2,%3};" \
        : "+f"((d)[0]), "+f"((d)[1]), "+f"((d)[2]), "+f"((d)[3]) \
        : "r"((a)[0]), "r"((a)[1]), "r"((a)[2]), "r"((a)[3]), "r"(b0), "r"(b1))

__device__ __forceinline__ uint32_t packbf(float a, float b) {
    __nv_bfloat162 t = __floats2bfloat162_rn(a, b);
    return *reinterpret_cast<uint32_t*>(&t);
}

// ---------------------------------------------------------------------------
// fp32 -> bf16 hi/lo conversion (vectorized, n multiple of 1024)
// ---------------------------------------------------------------------------
__global__ void __launch_bounds__(256)
convert_kernel(const float* __restrict__ x,
               __nv_bfloat16* __restrict__ h, __nv_bfloat16* __restrict__ l)
{
    int i = (blockIdx.x * 256 + threadIdx.x) * 4;
    float4 v = *reinterpret_cast<const float4*>(x + i);
    float h0 = __bfloat162float(__float2bfloat16_rn(v.x));
    float h1 = __bfloat162float(__float2bfloat16_rn(v.y));
    float h2 = __bfloat162float(__float2bfloat16_rn(v.z));
    float h3 = __bfloat162float(__float2bfloat16_rn(v.w));
    *reinterpret_cast<uint2*>(h + i) = make_uint2(packbf(h0, h1), packbf(h2, h3));
    *reinterpret_cast<uint2*>(l + i) =
        make_uint2(packbf(v.x - h0, v.y - h1), packbf(v.z - h2, v.w - h3));
}

// ---------------------------------------------------------------------------
// cp.async tile fill (one stage). A: [BM][BK] from [m][k]; B: BT -> [BN][BK]
// from [n][k]; NN -> [BK][BN] from [k][n]. Row pads: A/B-BT 80B, B-NN 272B.
// ---------------------------------------------------------------------------
template<bool BT>
__device__ __forceinline__ void fill_stage(uint32_t st,
    const __nv_bfloat16* __restrict__ Ah, const __nv_bfloat16* __restrict__ Al,
    const __nv_bfloat16* __restrict__ Bh, const __nv_bfloat16* __restrict__ Bl,
    int row0, int col0, int k0, int lda, int ldb, int tid)
{
    #pragma unroll
    for (int l = 0; l < 4; l++) {
        int c = (tid + l * 256) & 511;
        int r = c >> 2;
        int kc = (c & 3) * 8;
        const __nv_bfloat16* src = (l < 2) ? Ah : Al;
        uint32_t dst = st + ((l < 2) ? OFFAH : OFFAL) + r * 80 + kc * 2;
        CP16(dst, &src[(long long)(row0 + r) * lda + k0 + kc]);
    }
    if (BT) {
        #pragma unroll
        for (int l = 0; l < 4; l++) {
            int c = (tid + l * 256) & 511;
            int r = c >> 2;
            int kc = (c & 3) * 8;
            const __nv_bfloat16* src = (l < 2) ? Bh : Bl;
            uint32_t dst = st + ((l < 2) ? OFFBH : OFFBL_BT) + r * 80 + kc * 2;
            CP16(dst, &src[(long long)(col0 + r) * ldb + k0 + kc]);
        }
    } else {
        #pragma unroll
        for (int l = 0; l < 4; l++) {
            int c = (tid + l * 256) & 511;
            int r = c >> 4;
            int nc = (c & 15) * 8;
            const __nv_bfloat16* src = (l < 2) ? Bh : Bl;
            uint32_t dst = st + ((l < 2) ? OFFBH : OFFBL_NN) + r * 272 + nc * 2;
            CP16(dst, &src[(long long)(k0 + r) * ldb + col0 + nc]);
        }
    }
}

// ---------------------------------------------------------------------------
// HMMA bf16 hi/lo-split GEMM, pre-converted operands, cp.async double buffer.
//   BT=true : B [n][k]; BT=false: B [k][n] (ldmatrix.trans)
//   SPLIT=false: C fp32 (+bias); SPLIT=true: C -> bf16 hi/lo pair (+bias)
// 2 CTAs/SM so one CTA's MMAs cover the other's barriers/fills/tails.
// ---------------------------------------------------------------------------
template<bool BT, bool SPLIT>
__global__ void __launch_bounds__(NTHREADS, 2)
mma_gemm(const __nv_bfloat16* __restrict__ Ah, const __nv_bfloat16* __restrict__ Al,
         const __nv_bfloat16* __restrict__ Bh, const __nv_bfloat16* __restrict__ Bl,
         const float* __restrict__ bias,
         float* __restrict__ C, __nv_bfloat16* __restrict__ Ch,
         __nv_bfloat16* __restrict__ Cl,
         int K, int lda, int ldb, int ldc,
         long long sA1, long long sA2,
         long long sB1, long long sB2,
         long long sC1, long long sC2)
{
    extern __shared__ __align__(16) char dynsm[];
    const int z = blockIdx.z;
    const long long zb = z / HEADS, zh = z % HEADS;
    Ah += zb * sA1 + zh * sA2;  Al += zb * sA1 + zh * sA2;
    Bh += zb * sB1 + zh * sB2;  Bl += zb * sB1 + zh * sB2;
    const long long coff = zb * sC1 + zh * sC2;

    const int tid  = threadIdx.x;
    const int wid  = tid >> 5;
    const int lane = tid & 31;
    const int row0 = blockIdx.y * BM;
    const int col0 = blockIdx.x * BN;
    const int wm   = (wid & 3) * 32;
    const int wn   = (wid >> 2) * 64;

    const uint32_t smBase = smem_u32(dynsm);

    float acc[2][8][4];
    #pragma unroll
    for (int i = 0; i < 2; i++)
        #pragma unroll
        for (int j = 0; j < 8; j++)
            #pragma unroll
            for (int t = 0; t < 4; t++) acc[i][j][t] = 0.f;

    // ldmatrix lane addressing
    const int aRow = wm + (lane & 15);
    const int aColOff = (lane >> 4) << 3;
    const int bRowBT = wn + (lane & 7) + ((lane >> 4) << 3);
    const int bColBT = ((lane >> 3) & 1) << 3;
    const int bRowNN = (lane & 7) + (((lane >> 3) & 1) << 3);
    const int bColNN = wn + ((lane >> 4) << 3);

    const int nch = K / BK;
    fill_stage<BT>(smBase, Ah, Al, Bh, Bl, row0, col0, 0, lda, ldb, tid);
    CP_COMMIT();

    for (int ch = 0; ch < nch; ch++) {
        const uint32_t st = smBase + (ch & 1) * STAGE_SZ;
        if (ch + 1 < nch) {
            fill_stage<BT>(smBase + ((ch + 1) & 1) * STAGE_SZ,
                           Ah, Al, Bh, Bl, row0, col0, (ch + 1) * BK, lda, ldb, tid);
            CP_COMMIT();
            CP_WAIT(1);
        } else {
            CP_WAIT(0);
        }
        __syncthreads();

        #pragma unroll
        for (int kk = 0; kk < BK; kk += 16) {
            uint32_t ah[2][4], al[2][4];
            #pragma unroll
            for (int mi = 0; mi < 2; mi++) {
                uint32_t off = (aRow + mi * 16) * 80 + (kk + aColOff) * 2;
                LDSM4(ah[mi], st + OFFAH + off);
                LDSM4(al[mi], st + OFFAL + off);
            }
            #pragma unroll
            for (int ng = 0; ng < 4; ng++) {
                uint32_t bh[4], bl[4];
                if (BT) {
                    uint32_t off = (bRowBT + ng * 16) * 80 + (kk + bColBT) * 2;
                    LDSM4(bh, st + OFFBH + off);
                    LDSM4(bl, st + OFFBL_BT + off);
                } else {
                    uint32_t off = (kk + bRowNN) * 272 + (bColNN + ng * 16) * 2;
                    LDSM4T(bh, st + OFFBH + off);
                    LDSM4T(bl, st + OFFBL_NN + off);
                }
                #pragma unroll
                for (int mi = 0; mi < 2; mi++) {
                    #pragma unroll
                    for (int s = 0; s < 2; s++) {
                        float* d = acc[mi][ng * 2 + s];
                        MMA16816(d, ah[mi], bh[s * 2], bh[s * 2 + 1]);
                        MMA16816(d, ah[mi], bl[s * 2], bl[s * 2 + 1]);
                        MMA16816(d, al[mi], bh[s * 2], bh[s * 2 + 1]);
                    }
                }
            }
        }
        __syncthreads();
    }

    // ---- epilogue ----
    #pragma unroll
    for (int mi = 0; mi < 2; mi++) {
        int r = row0 + wm + mi * 16 + (lane >> 2);
        #pragma unroll
        for (int nf = 0; nf < 8; nf++) {
            int c = col0 + wn + nf * 8 + (lane & 3) * 2;
            float b0 = 0.f, b1 = 0.f;
            if (bias) { b0 = bias[c]; b1 = bias[c + 1]; }
            float v00 = acc[mi][nf][0] + b0, v01 = acc[mi][nf][1] + b1;
            float v10 = acc[mi][nf][2] + b0, v11 = acc[mi][nf][3] + b1;
            long long i0 = coff + (long long)r * ldc + c;
            long long i1 = coff + (long long)(r + 8) * ldc + c;
            if (SPLIT) {
                float h00 = __bfloat162float(__float2bfloat16_rn(v00));
                float h01 = __bfloat162float(__float2bfloat16_rn(v01));
                float h10 = __bfloat162float(__float2bfloat16_rn(v10));
                float h11 = __bfloat162float(__float2bfloat16_rn(v11));
                *reinterpret_cast<uint32_t*>(Ch + i0) = packbf(h00, h01);
                *reinterpret_cast<uint32_t*>(Cl + i0) = packbf(v00 - h00, v01 - h01);
                *reinterpret_cast<uint32_t*>(Ch + i1) = packbf(h10, h11);
                *reinterpret_cast<uint32_t*>(Cl + i1) = packbf(v10 - h10, v11 - h11);
            } else {
                *reinterpret_cast<float2*>(C + i0) = make_float2(v00, v01);
                *reinterpret_cast<float2*>(C + i1) = make_float2(v10, v11);
            }
        }
    }
}

// ---------------------------------------------------------------------------
// Fused RMSNorm + RoPE + scales; reads fp32 q/k, writes bf16 hi/lo splits.
// ---------------------------------------------------------------------------
__global__ void __launch_bounds__(256)
normrope_kernel(const float* __restrict__ q, const float* __restrict__ k,
                const float* __restrict__ rope,
                const float* __restrict__ wq, const float* __restrict__ wk,
                const float* __restrict__ hks,
                __nv_bfloat16* __restrict__ qh, __nv_bfloat16* __restrict__ ql,
                __nv_bfloat16* __restrict__ kh, __nv_bfloat16* __restrict__ kl)
{
    const int tok = blockIdx.x;
    const int s   = tok & (SEQ - 1);
    const bool isK = (blockIdx.y == 1);
    const float* x = (isK ? k : q) + (long long)tok * INNER;
    __nv_bfloat16* oh = (isK ? kh : qh) + (long long)tok * INNER;
    __nv_bfloat16* ol = (isK ? kl : ql) + (long long)tok * INNER;
    const float* w = isK ? wk : wq;
    const int tid = threadIdx.x;

    float2 vals[4];
    float ss = 0.f;
    #pragma unroll
    for (int l = 0; l < 4; l++) {
        int p = tid + 256 * l;
        float2 vv = *reinterpret_cast<const float2*>(&x[2 * p]);
        ss += vv.x * vv.x + vv.y * vv.y;
        vals[l] = vv;
    }
    #pragma unroll
    for (int off = 16; off; off >>= 1) ss += __shfl_xor_sync(0xFFFFFFFFu, ss, off);
    __shared__ float sred[8];
    if ((tid & 31) == 0) sred[tid >> 5] = ss;
    __syncthreads();
    float tot = 0.f;
    #pragma unroll
    for (int i = 0; i < 8; i++) tot += sred[i];
    const float inv = rsqrtf(tot * (1.f / (float)INNER) + 1e-5f);

    #pragma unroll
    for (int l = 0; l < 4; l++) {
        int p = tid + 256 * l;
        int h = p >> 6;
        int i = p & 63;
        float c  = rope[(long long)s * 256 + 2 * i];
        float sn = rope[(long long)s * 256 + 128 + 2 * i + 1];
        float x1 = vals[l].x * inv * w[2 * p];
        float x2 = vals[l].y * inv * w[2 * p + 1];
        float e = x1 * c - x2 * sn;
        float o = x1 * sn + x2 * c;
        float mult;
        if (isK) {
            mult = (s < HIST) ? (1.f + 9.f / (1.f + __expf(-hks[h]))) : 1.f;
        } else {
            mult = QSCALE;
        }
        e *= mult; o *= mult;
        float eh = __bfloat162float(__float2bfloat16_rn(e));
        float oh2 = __bfloat162float(__float2bfloat16_rn(o));
        *reinterpret_cast<uint32_t*>(&oh[2 * p]) = packbf(eh, oh2);
        *reinterpret_cast<uint32_t*>(&ol[2 * p]) = packbf(e - eh, o - oh2);
    }
}

// ---------------------------------------------------------------------------
// Row softmax over 2048; reads fp32 scores, writes bf16 hi/lo probs.
// ---------------------------------------------------------------------------
__global__ void __launch_bounds__(256)
softmax_kernel(const float* __restrict__ attn,
               __nv_bfloat16* __restrict__ ph, __nv_bfloat16* __restrict__ pl)
{
    const long long rb = (long long)blockIdx.x * SEQ;
    const float* p = attn + rb;
    const int tid = threadIdx.x;
    float2 vals[4];
    float m = -1e30f;
    #pragma unroll
    for (int l = 0; l < 4; l++) {
        vals[l] = *reinterpret_cast<const float2*>(&p[2 * (tid + 256 * l)]);
        m = fmaxf(m, fmaxf(vals[l].x, vals[l].y));
    }
    #pragma unroll
    for (int off = 16; off; off >>= 1) m = fmaxf(m, __shfl_xor_sync(0xFFFFFFFFu, m, off));
    __shared__ float sm[8], ssum[8];
    if ((tid & 31) == 0) sm[tid >> 5] = m;
    __syncthreads();
    float mm = sm[0];
    #pragma unroll
    for (int i = 1; i < 8; i++) mm = fmaxf(mm, sm[i]);

    float s = 0.f;
    #pragma unroll
    for (int l = 0; l < 4; l++) {
        vals[l].x = __expf(vals[l].x - mm);
        vals[l].y = __expf(vals[l].y - mm);
        s += vals[l].x + vals[l].y;
    }
    #pragma unroll
    for (int off = 16; off; off >>= 1) s += __shfl_xor_sync(0xFFFFFFFFu, s, off);
    if ((tid & 31) == 0) ssum[tid >> 5] = s;
    __syncthreads();
    float tot = 0.f;
    #pragma unroll
    for (int i = 0; i < 8; i++) tot += ssum[i];
    const float inv = 1.f / tot;
    #pragma unroll
    for (int l = 0; l < 4; l++) {
        float a = vals[l].x * inv, b = vals[l].y * inv;
        float ha = __bfloat162float(__float2bfloat16_rn(a));
        float hb = __bfloat162float(__float2bfloat16_rn(b));
        long long idx = rb + 2 * (tid + 256 * l);
        *reinterpret_cast<uint32_t*>(&ph[idx]) = packbf(ha, hb);
        *reinterpret_cast<uint32_t*>(&pl[idx]) = packbf(a - ha, b - hb);
    }
}

// ---------------------------------------------------------------------------
extern "C" void kernel_launch(void* const* d_in, const int* in_sizes, int n_in,
                              void* d_out, int out_size)
{
    const float* hs   = (const float*)d_in[0];
    const float* rope = (const float*)d_in[1];
    const float* Wq   = (const float*)d_in[2];
    const float* bq   = (const float*)d_in[3];
    const float* Wk   = (const float*)d_in[4];
    const float* bk   = (const float*)d_in[5];
    const float* Wv   = (const float*)d_in[6];
    const float* bv   = (const float*)d_in[7];
    const float* nqw  = (const float*)d_in[8];
    const float* nkw  = (const float*)d_in[9];
    const float* hks  = (const float*)d_in[10];
    const float* Wo   = (const float*)d_in[11];
    const float* bo   = (const float*)d_in[12];
    float* out = (float*)d_out;

    float *q, *k, *attn;
    __nv_bfloat16 *ah, *al, *qh, *ql, *kh, *kl, *vh, *vl, *ph, *pl;
    __nv_bfloat16 *wqh, *wql, *wkh, *wkl, *wvh, *wvl, *woh, *wol;
    cudaGetSymbolAddress((void**)&q,    g_q);
    cudaGetSymbolAddress((void**)&k,    g_k);
    cudaGetSymbolAddress((void**)&attn, g_attn);
    cudaGetSymbolAddress((void**)&ah,   g_ah);
    cudaGetSymbolAddress((void**)&al,   g_al);
    cudaGetSymbolAddress((void**)&wqh,  g_wqh);
    cudaGetSymbolAddress((void**)&wql,  g_wql);
    cudaGetSymbolAddress((void**)&wkh,  g_wkh);
    cudaGetSymbolAddress((void**)&wkl,  g_wkl);
    cudaGetSymbolAddress((void**)&wvh,  g_wvh);
    cudaGetSymbolAddress((void**)&wvl,  g_wvl);
    cudaGetSymbolAddress((void**)&woh,  g_woh);
    cudaGetSymbolAddress((void**)&wol,  g_wol);
    cudaGetSymbolAddress((void**)&qh,   g_qh);
    cudaGetSymbolAddress((void**)&ql,   g_ql);
    cudaGetSymbolAddress((void**)&kh,   g_kh);
    cudaGetSymbolAddress((void**)&kl,   g_kl);
    cudaGetSymbolAddress((void**)&vh,   g_vh);
    cudaGetSymbolAddress((void**)&vl,   g_vl);
    cudaGetSymbolAddress((void**)&ph,   g_ph);
    cudaGetSymbolAddress((void**)&pl,   g_pl);

    cudaFuncSetAttribute(mma_gemm<true, false>,
        cudaFuncAttributeMaxDynamicSharedMemorySize, SMEM_TOTAL);
    cudaFuncSetAttribute(mma_gemm<true, true>,
        cudaFuncAttributeMaxDynamicSharedMemorySize, SMEM_TOTAL);
    cudaFuncSetAttribute(mma_gemm<false, true>,
        cudaFuncAttributeMaxDynamicSharedMemorySize, SMEM_TOTAL);

    dim3 blk(NTHREADS);

    // 0) convert activations + all weights upfront (GEMMs then run back-to-back)
    convert_kernel<<<TOKENS * DIMM / 1024, 256>>>(hs, ah, al);
    convert_kernel<<<INNER * DIMM / 1024, 256>>>(Wq, wqh, wql);
    convert_kernel<<<INNER * DIMM / 1024, 256>>>(Wk, wkh, wkl);
    convert_kernel<<<INNER * DIMM / 1024, 256>>>(Wv, wvh, wvl);
    convert_kernel<<<INNER * DIMM / 1024, 256>>>(Wo, woh, wol);

    // 1) QKV projections
    dim3 g1(INNER / BN, TOKENS / BM, 1);
    mma_gemm<true, false><<<g1, blk, SMEM_TOTAL>>>(ah, al, wqh, wql, bq, q, nullptr, nullptr,
        DIMM, DIMM, DIMM, INNER, 0, 0, 0, 0, 0, 0);
    mma_gemm<true, false><<<g1, blk, SMEM_TOTAL>>>(ah, al, wkh, wkl, bk, k, nullptr, nullptr,
        DIMM, DIMM, DIMM, INNER, 0, 0, 0, 0, 0, 0);
    mma_gemm<true, true><<<g1, blk, SMEM_TOTAL>>>(ah, al, wvh, wvl, bv, nullptr, vh, vl,
        DIMM, DIMM, DIMM, INNER, 0, 0, 0, 0, 0, 0);

    // 2) RMSNorm + RoPE + scales -> bf16 splits
    normrope_kernel<<<dim3(TOKENS, 2), blk>>>(q, k, rope, nqw, nkw, hks,
                                              qh, ql, kh, kl);

    // 3) Scores S = Qh @ Kh^T (fp32)
    dim3 g2(SEQ / BN, SEQ / BM, BATCH * HEADS);
    mma_gemm<true, false><<<g2, blk, SMEM_TOTAL>>>(qh, ql, kh, kl, nullptr, attn,
        nullptr, nullptr, DHEAD, INNER, INNER, SEQ,
        (long long)SEQ * INNER, DHEAD,
        (long long)SEQ * INNER, DHEAD,
        (long long)HEADS * SEQ * SEQ, (long long)SEQ * SEQ);

    // 4) Softmax -> bf16 splits
    softmax_kernel<<<BATCH * HEADS * SEQ, blk>>>(attn, ph, pl);

    // 5) O = P @ V (NN) -> bf16 splits into g_ah/g_al (hs dead)
    dim3 g3(DHEAD / BN, SEQ / BM, BATCH * HEADS);
    mma_gemm<false, true><<<g3, blk, SMEM_TOTAL>>>(ph, pl, vh, vl, nullptr, nullptr,
        ah, al, SEQ, SEQ, INNER, INNER,
        (long long)HEADS * SEQ * SEQ, (long long)SEQ * SEQ,
        (long long)SEQ * INNER, DHEAD,
        (long long)SEQ * INNER, DHEAD);

    // 6) Output projection (fp32 out + bias)
    dim3 g4(DIMM / BN, TOKENS / BM, 1);
    mma_gemm<true, false><<<g4, blk, SMEM_TOTAL>>>(ah, al, woh, wol, bo, out,
        nullptr, nullptr, INNER, INNER, INNER, DIMM, 0, 0, 0, 0, 0, 0);
}

// round 9
// speedup vs baseline: 2.6474x; 1.0855x over previous
#include <cuda_runtime.h>
#include <cuda_bf16.h>
#include <stdint.h>
#include <math.h>

// Problem constants
#define BATCH   2
#define SEQ     2048
#define DIMM    2048
#define HEADS   16
#define DHEAD   128
#define INNER   2048
#define TOKENS  (BATCH*SEQ)
#define HIST    512
#define QSCALE  0.08838834764831845f

// Dense GEMM tiling
#define BM 128
#define BN 128
#define BK 32
#define NTHREADS 256

// Dense GEMM dynamic smem (two stages)
#define OFFAH   0
#define OFFAL   10240
#define OFFBH   20480
#define OFFBL_BT 30720
#define STAGE_SZ 40960
#define SMEM_TOTAL 81920

// Flash kernel smem: 6 tiles of 128 rows x 272B
#define FROWB  272
#define FT_SZ  (128 * FROWB)          // 34816
#define OFF_QH 0
#define OFF_QL (1 * FT_SZ)
#define OFF_KH (2 * FT_SZ)
#define OFF_KL (3 * FT_SZ)
#define OFF_VH (4 * FT_SZ)
#define OFF_VL (5 * FT_SZ)
#define FSMEM  (6 * FT_SZ)            // 208896

// fp32 scratch
__device__ float g_q[(size_t)TOKENS * INNER];
__device__ float g_k[(size_t)TOKENS * INNER];
// bf16 hi/lo scratch
__device__ __nv_bfloat16 g_ah[(size_t)TOKENS * INNER];   // hs, later attn-out
__device__ __nv_bfloat16 g_al[(size_t)TOKENS * INNER];
__device__ __nv_bfloat16 g_wqh[(size_t)INNER * DIMM];
__device__ __nv_bfloat16 g_wql[(size_t)INNER * DIMM];
__device__ __nv_bfloat16 g_wkh[(size_t)INNER * DIMM];
__device__ __nv_bfloat16 g_wkl[(size_t)INNER * DIMM];
__device__ __nv_bfloat16 g_wvh[(size_t)INNER * DIMM];
__device__ __nv_bfloat16 g_wvl[(size_t)INNER * DIMM];
__device__ __nv_bfloat16 g_woh[(size_t)INNER * DIMM];
__device__ __nv_bfloat16 g_wol[(size_t)INNER * DIMM];
__device__ __nv_bfloat16 g_qh[(size_t)TOKENS * INNER];
__device__ __nv_bfloat16 g_ql[(size_t)TOKENS * INNER];
__device__ __nv_bfloat16 g_kh[(size_t)TOKENS * INNER];
__device__ __nv_bfloat16 g_kl[(size_t)TOKENS * INNER];
__device__ __nv_bfloat16 g_vh[(size_t)TOKENS * INNER];
__device__ __nv_bfloat16 g_vl[(size_t)TOKENS * INNER];

__device__ __forceinline__ uint32_t smem_u32(const void* p) {
    uint32_t a;
    asm("{ .reg .u64 t; cvta.to.shared.u64 t, %1; cvt.u32.u64 %0, t; }" : "=r"(a) : "l"(p));
    return a;
}

#define CP16(dst, src) \
    asm volatile("cp.async.cg.shared.global [%0], [%1], 16;" \
        :: "r"(dst), "l"(__cvta_generic_to_global(src)) : "memory")
#define CP_COMMIT() asm volatile("cp.async.commit_group;" ::: "memory")
#define CP_WAIT(n)  asm volatile("cp.async.wait_group %0;" :: "n"(n) : "memory")

#define LDSM4(r, a) \
    asm volatile("ldmatrix.sync.aligned.m8n8.x4.shared.b16 {%0,%1,%2,%3}, [%4];" \
        : "=r"((r)[0]), "=r"((r)[1]), "=r"((r)[2]), "=r"((r)[3]) : "r"(a))
#define LDSM4T(r, a) \
    asm volatile("ldmatrix.sync.aligned.m8n8.x4.trans.shared.b16 {%0,%1,%2,%3}, [%4];" \
        : "=r"((r)[0]), "=r"((r)[1]), "=r"((r)[2]), "=r"((r)[3]) : "r"(a))

#define MMA16816(d, a, b0, b1) \
    asm volatile("mma.sync.aligned.m16n8k16.row.col.f32.bf16.bf16.f32 " \
        "{%0,%1,%2,%3}, {%4,%5,%6,%7}, {%8,%9}, {%0,%1,%2,%3};" \
        : "+f"((d)[0]), "+f"((d)[1]), "+f"((d)[2]), "+f"((d)[3]) \
        : "r"((a)[0]), "r"((a)[1]), "r"((a)[2]), "r"((a)[3]), "r"(b0), "r"(b1))

__device__ __forceinline__ uint32_t packbf(float a, float b) {
    __nv_bfloat162 t = __floats2bfloat162_rn(a, b);
    return *reinterpret_cast<uint32_t*>(&t);
}
__device__ __forceinline__ float bhi(float x) {
    return __bfloat162float(__float2bfloat16_rn(x));
}

// ---------------------------------------------------------------------------
// fp32 -> bf16 hi/lo conversion
// ---------------------------------------------------------------------------
__global__ void __launch_bounds__(256)
convert_kernel(const float* __restrict__ x,
               __nv_bfloat16* __restrict__ h, __nv_bfloat16* __restrict__ l)
{
    int i = (blockIdx.x * 256 + threadIdx.x) * 4;
    float4 v = *reinterpret_cast<const float4*>(x + i);
    float h0 = bhi(v.x), h1 = bhi(v.y), h2 = bhi(v.z), h3 = bhi(v.w);
    *reinterpret_cast<uint2*>(h + i) = make_uint2(packbf(h0, h1), packbf(h2, h3));
    *reinterpret_cast<uint2*>(l + i) =
        make_uint2(packbf(v.x - h0, v.y - h1), packbf(v.z - h2, v.w - h3));
}

// ---------------------------------------------------------------------------
// Dense GEMM (BT only): C = A @ B^T + bias; cp.async double buffer; 2 CTAs/SM.
// SPLIT=false: fp32 out; SPLIT=true: bf16 hi/lo out.
// ---------------------------------------------------------------------------
__device__ __forceinline__ void fill_stage_bt(uint32_t st,
    const __nv_bfloat16* __restrict__ Ah, const __nv_bfloat16* __restrict__ Al,
    const __nv_bfloat16* __restrict__ Bh, const __nv_bfloat16* __restrict__ Bl,
    int row0, int col0, int k0, int lda, int ldb, int tid)
{
    #pragma unroll
    for (int l = 0; l < 4; l++) {
        int c = (tid + l * 256) & 511;
        int r = c >> 2;
        int kc = (c & 3) * 8;
        const __nv_bfloat16* src = (l < 2) ? Ah : Al;
        uint32_t dst = st + ((l < 2) ? OFFAH : OFFAL) + r * 80 + kc * 2;
        CP16(dst, &src[(long long)(row0 + r) * lda + k0 + kc]);
    }
    #pragma unroll
    for (int l = 0; l < 4; l++) {
        int c = (tid + l * 256) & 511;
        int r = c >> 2;
        int kc = (c & 3) * 8;
        const __nv_bfloat16* src = (l < 2) ? Bh : Bl;
        uint32_t dst = st + ((l < 2) ? OFFBH : OFFBL_BT) + r * 80 + kc * 2;
        CP16(dst, &src[(long long)(col0 + r) * ldb + k0 + kc]);
    }
}

template<bool SPLIT>
__global__ void __launch_bounds__(NTHREADS, 2)
mma_gemm(const __nv_bfloat16* __restrict__ Ah, const __nv_bfloat16* __restrict__ Al,
         const __nv_bfloat16* __restrict__ Bh, const __nv_bfloat16* __restrict__ Bl,
         const float* __restrict__ bias,
         float* __restrict__ C, __nv_bfloat16* __restrict__ Ch,
         __nv_bfloat16* __restrict__ Cl,
         int K, int lda, int ldb, int ldc)
{
    extern __shared__ __align__(16) char dynsm[];
    const int tid  = threadIdx.x;
    const int wid  = tid >> 5;
    const int lane = tid & 31;
    const int row0 = blockIdx.y * BM;
    const int col0 = blockIdx.x * BN;
    const int wm   = (wid & 3) * 32;
    const int wn   = (wid >> 2) * 64;
    const uint32_t smBase = smem_u32(dynsm);

    float acc[2][8][4];
    #pragma unroll
    for (int i = 0; i < 2; i++)
        #pragma unroll
        for (int j = 0; j < 8; j++)
            #pragma unroll
            for (int t = 0; t < 4; t++) acc[i][j][t] = 0.f;

    const int aRow = wm + (lane & 15);
    const int aColOff = (lane >> 4) << 3;
    const int bRow = wn + (lane & 7) + ((lane >> 4) << 3);
    const int bCol = ((lane >> 3) & 1) << 3;

    const int nch = K / BK;
    fill_stage_bt(smBase, Ah, Al, Bh, Bl, row0, col0, 0, lda, ldb, tid);
    CP_COMMIT();

    for (int ch = 0; ch < nch; ch++) {
        const uint32_t st = smBase + (ch & 1) * STAGE_SZ;
        if (ch + 1 < nch) {
            fill_stage_bt(smBase + ((ch + 1) & 1) * STAGE_SZ,
                          Ah, Al, Bh, Bl, row0, col0, (ch + 1) * BK, lda, ldb, tid);
            CP_COMMIT();
            CP_WAIT(1);
        } else {
            CP_WAIT(0);
        }
        __syncthreads();

        #pragma unroll
        for (int kk = 0; kk < BK; kk += 16) {
            uint32_t ah[2][4], al[2][4];
            #pragma unroll
            for (int mi = 0; mi < 2; mi++) {
                uint32_t off = (aRow + mi * 16) * 80 + (kk + aColOff) * 2;
                LDSM4(ah[mi], st + OFFAH + off);
                LDSM4(al[mi], st + OFFAL + off);
            }
            #pragma unroll
            for (int ng = 0; ng < 4; ng++) {
                uint32_t bh[4], bl[4];
                uint32_t off = (bRow + ng * 16) * 80 + (kk + bCol) * 2;
                LDSM4(bh, st + OFFBH + off);
                LDSM4(bl, st + OFFBL_BT + off);
                #pragma unroll
                for (int mi = 0; mi < 2; mi++) {
                    #pragma unroll
                    for (int s = 0; s < 2; s++) {
                        float* d = acc[mi][ng * 2 + s];
                        MMA16816(d, ah[mi], bh[s * 2], bh[s * 2 + 1]);
                        MMA16816(d, ah[mi], bl[s * 2], bl[s * 2 + 1]);
                        MMA16816(d, al[mi], bh[s * 2], bh[s * 2 + 1]);
                    }
                }
            }
        }
        __syncthreads();
    }

    #pragma unroll
    for (int mi = 0; mi < 2; mi++) {
        int r = row0 + wm + mi * 16 + (lane >> 2);
        #pragma unroll
        for (int nf = 0; nf < 8; nf++) {
            int c = col0 + wn + nf * 8 + (lane & 3) * 2;
            float b0 = 0.f, b1 = 0.f;
            if (bias) { b0 = bias[c]; b1 = bias[c + 1]; }
            float v00 = acc[mi][nf][0] + b0, v01 = acc[mi][nf][1] + b1;
            float v10 = acc[mi][nf][2] + b0, v11 = acc[mi][nf][3] + b1;
            long long i0 = (long long)r * ldc + c;
            long long i1 = (long long)(r + 8) * ldc + c;
            if (SPLIT) {
                float h00 = bhi(v00), h01 = bhi(v01), h10 = bhi(v10), h11 = bhi(v11);
                *reinterpret_cast<uint32_t*>(Ch + i0) = packbf(h00, h01);
                *reinterpret_cast<uint32_t*>(Cl + i0) = packbf(v00 - h00, v01 - h01);
                *reinterpret_cast<uint32_t*>(Ch + i1) = packbf(h10, h11);
                *reinterpret_cast<uint32_t*>(Cl + i1) = packbf(v10 - h10, v11 - h11);
            } else {
                *reinterpret_cast<float2*>(C + i0) = make_float2(v00, v01);
                *reinterpret_cast<float2*>(C + i1) = make_float2(v10, v11);
            }
        }
    }
}

// ---------------------------------------------------------------------------
// Flash attention: fused S = Q@K^T, online softmax, O = P@V.
// Grid (16 q-tiles, 32 batch-heads), 8 warps; warp = 16 q-rows x full width.
// 3-term hi/lo split on both MMAs; fp32 accumulation + softmax.
// ---------------------------------------------------------------------------
__global__ void __launch_bounds__(256, 1)
flash_kernel(const __nv_bfloat16* __restrict__ qh, const __nv_bfloat16* __restrict__ ql,
             const __nv_bfloat16* __restrict__ kh, const __nv_bfloat16* __restrict__ kl,
             const __nv_bfloat16* __restrict__ vh, const __nv_bfloat16* __restrict__ vl,
             __nv_bfloat16* __restrict__ oh, __nv_bfloat16* __restrict__ ol)
{
    extern __shared__ __align__(16) char fsm[];
    const uint32_t smb = smem_u32(fsm);
    const int tid  = threadIdx.x;
    const int wid  = tid >> 5;
    const int lane = tid & 31;
    const int q0   = blockIdx.x * 128;
    const int bh   = blockIdx.y;
    const long long tokb = (long long)(bh / HEADS) * SEQ;
    const int hcol = (bh % HEADS) * DHEAD;
    const int wm   = wid * 16;

    // cp.async fill of one 128x128 bf16 tile (rows = tokens, cols = head dims)
    auto fill = [&](uint32_t off, const __nv_bfloat16* __restrict__ src, int rowStart) {
        #pragma unroll
        for (int l = 0; l < 8; l++) {
            int idx = tid + l * 256;
            int r = idx >> 4, c = idx & 15;
            CP16(smb + off + r * FROWB + c * 16,
                 &src[(tokb + rowStart + r) * INNER + hcol + c * 8]);
        }
    };

    fill(OFF_QH, qh, q0); fill(OFF_QL, ql, q0);
    fill(OFF_KH, kh, 0);  fill(OFF_KL, kl, 0);
    CP_COMMIT();
    fill(OFF_VH, vh, 0);  fill(OFF_VL, vl, 0);
    CP_COMMIT();

    float oacc[16][4];
    #pragma unroll
    for (int g = 0; g < 16; g++)
        #pragma unroll
        for (int t = 0; t < 4; t++) oacc[g][t] = 0.f;
    float m0 = -1e30f, m1 = -1e30f, l0 = 0.f, l1 = 0.f;

    for (int it = 0; it < 16; it++) {
        CP_WAIT(1);                 // K(it) (and Q on it=0) ready
        __syncthreads();

        // ---- S = Q @ K^T (this key tile) ----
        float sn[16][4];
        #pragma unroll
        for (int j = 0; j < 16; j++)
            #pragma unroll
            for (int t = 0; t < 4; t++) sn[j][t] = 0.f;

        #pragma unroll
        for (int k8 = 0; k8 < 8; k8++) {
            const int kk = k8 * 16;
            uint32_t qfh[4], qfl[4];
            uint32_t qoff = (uint32_t)(wm + (lane & 15)) * FROWB
                          + (uint32_t)(kk + ((lane >> 4) << 3)) * 2;
            LDSM4(qfh, smb + OFF_QH + qoff);
            LDSM4(qfl, smb + OFF_QL + qoff);
            #pragma unroll
            for (int g = 0; g < 8; g++) {
                uint32_t kbh[4], kbl[4];
                uint32_t koff = (uint32_t)(g * 16 + (lane & 7) + ((lane >> 4) << 3)) * FROWB
                              + (uint32_t)(kk + (((lane >> 3) & 1) << 3)) * 2;
                LDSM4(kbh, smb + OFF_KH + koff);
                LDSM4(kbl, smb + OFF_KL + koff);
                #pragma unroll
                for (int s2 = 0; s2 < 2; s2++) {
                    float* d = sn[g * 2 + s2];
                    MMA16816(d, qfh, kbh[s2 * 2], kbh[s2 * 2 + 1]);
                    MMA16816(d, qfh, kbl[s2 * 2], kbl[s2 * 2 + 1]);
                    MMA16816(d, qfl, kbh[s2 * 2], kbh[s2 * 2 + 1]);
                }
            }
        }
        __syncthreads();            // everyone done reading K
        if (it < 15) {
            fill(OFF_KH, kh, (it + 1) * 128);
            fill(OFF_KL, kl, (it + 1) * 128);
            CP_COMMIT();
        }

        // ---- online softmax (rows owned in-warp; quad reductions) ----
        float rm0 = -1e30f, rm1 = -1e30f;
        #pragma unroll
        for (int j = 0; j < 16; j++) {
            rm0 = fmaxf(rm0, fmaxf(sn[j][0], sn[j][1]));
            rm1 = fmaxf(rm1, fmaxf(sn[j][2], sn[j][3]));
        }
        rm0 = fmaxf(rm0, __shfl_xor_sync(0xFFFFFFFFu, rm0, 1));
        rm0 = fmaxf(rm0, __shfl_xor_sync(0xFFFFFFFFu, rm0, 2));
        rm1 = fmaxf(rm1, __shfl_xor_sync(0xFFFFFFFFu, rm1, 1));
        rm1 = fmaxf(rm1, __shfl_xor_sync(0xFFFFFFFFu, rm1, 2));
        const float mn0 = fmaxf(m0, rm0), mn1 = fmaxf(m1, rm1);
        const float sc0 = __expf(m0 - mn0), sc1 = __expf(m1 - mn1);
        float rs0 = 0.f, rs1 = 0.f;
        #pragma unroll
        for (int j = 0; j < 16; j++) {
            sn[j][0] = __expf(sn[j][0] - mn0);
            sn[j][1] = __expf(sn[j][1] - mn0);
            sn[j][2] = __expf(sn[j][2] - mn1);
            sn[j][3] = __expf(sn[j][3] - mn1);
            rs0 += sn[j][0] + sn[j][1];
            rs1 += sn[j][2] + sn[j][3];
        }
        rs0 += __shfl_xor_sync(0xFFFFFFFFu, rs0, 1);
        rs0 += __shfl_xor_sync(0xFFFFFFFFu, rs0, 2);
        rs1 += __shfl_xor_sync(0xFFFFFFFFu, rs1, 1);
        rs1 += __shfl_xor_sync(0xFFFFFFFFu, rs1, 2);
        l0 = l0 * sc0 + rs0;  l1 = l1 * sc1 + rs1;
        m0 = mn0;  m1 = mn1;
        #pragma unroll
        for (int g = 0; g < 16; g++) {
            oacc[g][0] *= sc0;  oacc[g][1] *= sc0;
            oacc[g][2] *= sc1;  oacc[g][3] *= sc1;
        }

        if (it < 15) CP_WAIT(1); else CP_WAIT(0);   // V(it) ready
        __syncthreads();

        // ---- O += P @ V ----
        #pragma unroll
        for (int s = 0; s < 8; s++) {
            const float* f0 = sn[2 * s];
            const float* f1 = sn[2 * s + 1];
            uint32_t pah[4], pal[4];
            {
                float h00 = bhi(f0[0]), h01 = bhi(f0[1]), h02 = bhi(f0[2]), h03 = bhi(f0[3]);
                float h10 = bhi(f1[0]), h11 = bhi(f1[1]), h12 = bhi(f1[2]), h13 = bhi(f1[3]);
                pah[0] = packbf(h00, h01);  pal[0] = packbf(f0[0] - h00, f0[1] - h01);
                pah[1] = packbf(h02, h03);  pal[1] = packbf(f0[2] - h02, f0[3] - h03);
                pah[2] = packbf(h10, h11);  pal[2] = packbf(f1[0] - h10, f1[1] - h11);
                pah[3] = packbf(h12, h13);  pal[3] = packbf(f1[2] - h12, f1[3] - h13);
            }
            #pragma unroll
            for (int g = 0; g < 8; g++) {
                uint32_t vbh[4], vbl[4];
                uint32_t voff = (uint32_t)(s * 16 + (lane & 7) + (((lane >> 3) & 1) << 3)) * FROWB
                              + (uint32_t)(g * 16 + ((lane >> 4) << 3)) * 2;
                LDSM4T(vbh, smb + OFF_VH + voff);
                LDSM4T(vbl, smb + OFF_VL + voff);
                #pragma unroll
                for (int s2 = 0; s2 < 2; s2++) {
                    float* d = oacc[g * 2 + s2];
                    MMA16816(d, pah, vbh[s2 * 2], vbh[s2 * 2 + 1]);
                    MMA16816(d, pah, vbl[s2 * 2], vbl[s2 * 2 + 1]);
                    MMA16816(d, pal, vbh[s2 * 2], vbh[s2 * 2 + 1]);
                }
            }
        }
        __syncthreads();            // everyone done reading V
        if (it < 15) {
            fill(OFF_VH, vh, (it + 1) * 128);
            fill(OFF_VL, vl, (it + 1) * 128);
            CP_COMMIT();
        }
    }

    // ---- normalize + write O as bf16 hi/lo ----
    const float inv0 = 1.f / l0, inv1 = 1.f / l1;
    const int r0 = q0 + wm + (lane >> 2);
    #pragma unroll
    for (int g = 0; g < 16; g++) {
        const int c = hcol + g * 8 + (lane & 3) * 2;
        float v0 = oacc[g][0] * inv0, v1 = oacc[g][1] * inv0;
        float v2 = oacc[g][2] * inv1, v3 = oacc[g][3] * inv1;
        long long i0 = (tokb + r0) * INNER + c;
        long long i1 = (tokb + r0 + 8) * INNER + c;
        float h0 = bhi(v0), h1 = bhi(v1), h2 = bhi(v2), h3 = bhi(v3);
        *reinterpret_cast<uint32_t*>(oh + i0) = packbf(h0, h1);
        *reinterpret_cast<uint32_t*>(ol + i0) = packbf(v0 - h0, v1 - h1);
        *reinterpret_cast<uint32_t*>(oh + i1) = packbf(h2, h3);
        *reinterpret_cast<uint32_t*>(ol + i1) = packbf(v2 - h2, v3 - h3);
    }
}

// ---------------------------------------------------------------------------
// Fused RMSNorm + RoPE + scales; fp32 in, bf16 hi/lo out.
// ---------------------------------------------------------------------------
__global__ void __launch_bounds__(256)
normrope_kernel(const float* __restrict__ q, const float* __restrict__ k,
                const float* __restrict__ rope,
                const float* __restrict__ wq, const float* __restrict__ wk,
                const float* __restrict__ hks,
                __nv_bfloat16* __restrict__ qh, __nv_bfloat16* __restrict__ ql,
                __nv_bfloat16* __restrict__ kh, __nv_bfloat16* __restrict__ kl)
{
    const int tok = blockIdx.x;
    const int s   = tok & (SEQ - 1);
    const bool isK = (blockIdx.y == 1);
    const float* x = (isK ? k : q) + (long long)tok * INNER;
    __nv_bfloat16* outh = (isK ? kh : qh) + (long long)tok * INNER;
    __nv_bfloat16* outl = (isK ? kl : ql) + (long long)tok * INNER;
    const float* w = isK ? wk : wq;
    const int tid = threadIdx.x;

    float2 vals[4];
    float ss = 0.f;
    #pragma unroll
    for (int l = 0; l < 4; l++) {
        int p = tid + 256 * l;
        float2 vv = *reinterpret_cast<const float2*>(&x[2 * p]);
        ss += vv.x * vv.x + vv.y * vv.y;
        vals[l] = vv;
    }
    #pragma unroll
    for (int off = 16; off; off >>= 1) ss += __shfl_xor_sync(0xFFFFFFFFu, ss, off);
    __shared__ float sred[8];
    if ((tid & 31) == 0) sred[tid >> 5] = ss;
    __syncthreads();
    float tot = 0.f;
    #pragma unroll
    for (int i = 0; i < 8; i++) tot += sred[i];
    const float inv = rsqrtf(tot * (1.f / (float)INNER) + 1e-5f);

    #pragma unroll
    for (int l = 0; l < 4; l++) {
        int p = tid + 256 * l;
        int h = p >> 6;
        int i = p & 63;
        float c  = rope[(long long)s * 256 + 2 * i];
        float sn = rope[(long long)s * 256 + 128 + 2 * i + 1];
        float x1 = vals[l].x * inv * w[2 * p];
        float x2 = vals[l].y * inv * w[2 * p + 1];
        float e = x1 * c - x2 * sn;
        float o = x1 * sn + x2 * c;
        float mult;
        if (isK) {
            mult = (s < HIST) ? (1.f + 9.f / (1.f + __expf(-hks[h]))) : 1.f;
        } else {
            mult = QSCALE;
        }
        e *= mult; o *= mult;
        float eh = bhi(e), oh2 = bhi(o);
        *reinterpret_cast<uint32_t*>(&outh[2 * p]) = packbf(eh, oh2);
        *reinterpret_cast<uint32_t*>(&outl[2 * p]) = packbf(e - eh, o - oh2);
    }
}

// ---------------------------------------------------------------------------
extern "C" void kernel_launch(void* const* d_in, const int* in_sizes, int n_in,
                              void* d_out, int out_size)
{
    const float* hs   = (const float*)d_in[0];
    const float* rope = (const float*)d_in[1];
    const float* Wq   = (const float*)d_in[2];
    const float* bq   = (const float*)d_in[3];
    const float* Wk   = (const float*)d_in[4];
    const float* bk   = (const float*)d_in[5];
    const float* Wv   = (const float*)d_in[6];
    const float* bv   = (const float*)d_in[7];
    const float* nqw  = (const float*)d_in[8];
    const float* nkw  = (const float*)d_in[9];
    const float* hks  = (const float*)d_in[10];
    const float* Wo   = (const float*)d_in[11];
    const float* bo   = (const float*)d_in[12];
    float* out = (float*)d_out;

    float *q, *k;
    __nv_bfloat16 *ah, *al, *qh, *ql, *kh, *kl, *vh, *vl;
    __nv_bfloat16 *wqh, *wql, *wkh, *wkl, *wvh, *wvl, *woh, *wol;
    cudaGetSymbolAddress((void**)&q,    g_q);
    cudaGetSymbolAddress((void**)&k,    g_k);
    cudaGetSymbolAddress((void**)&ah,   g_ah);
    cudaGetSymbolAddress((void**)&al,   g_al);
    cudaGetSymbolAddress((void**)&wqh,  g_wqh);
    cudaGetSymbolAddress((void**)&wql,  g_wql);
    cudaGetSymbolAddress((void**)&wkh,  g_wkh);
    cudaGetSymbolAddress((void**)&wkl,  g_wkl);
    cudaGetSymbolAddress((void**)&wvh,  g_wvh);
    cudaGetSymbolAddress((void**)&wvl,  g_wvl);
    cudaGetSymbolAddress((void**)&woh,  g_woh);
    cudaGetSymbolAddress((void**)&wol,  g_wol);
    cudaGetSymbolAddress((void**)&qh,   g_qh);
    cudaGetSymbolAddress((void**)&ql,   g_ql);
    cudaGetSymbolAddress((void**)&kh,   g_kh);
    cudaGetSymbolAddress((void**)&kl,   g_kl);
    cudaGetSymbolAddress((void**)&vh,   g_vh);
    cudaGetSymbolAddress((void**)&vl,   g_vl);

    cudaFuncSetAttribute(mma_gemm<false>,
        cudaFuncAttributeMaxDynamicSharedMemorySize, SMEM_TOTAL);
    cudaFuncSetAttribute(mma_gemm<true>,
        cudaFuncAttributeMaxDynamicSharedMemorySize, SMEM_TOTAL);
    cudaFuncSetAttribute(flash_kernel,
        cudaFuncAttributeMaxDynamicSharedMemorySize, FSMEM);

    dim3 blk(NTHREADS);

    // 0) convert activations + weights upfront
    convert_kernel<<<TOKENS * DIMM / 1024, 256>>>(hs, ah, al);
    convert_kernel<<<INNER * DIMM / 1024, 256>>>(Wq, wqh, wql);
    convert_kernel<<<INNER * DIMM / 1024, 256>>>(Wk, wkh, wkl);
    convert_kernel<<<INNER * DIMM / 1024, 256>>>(Wv, wvh, wvl);
    convert_kernel<<<INNER * DIMM / 1024, 256>>>(Wo, woh, wol);

    // 1) QKV projections
    dim3 g1(INNER / BN, TOKENS / BM, 1);
    mma_gemm<false><<<g1, blk, SMEM_TOTAL>>>(ah, al, wqh, wql, bq, q, nullptr, nullptr,
        DIMM, DIMM, DIMM, INNER);
    mma_gemm<false><<<g1, blk, SMEM_TOTAL>>>(ah, al, wkh, wkl, bk, k, nullptr, nullptr,
        DIMM, DIMM, DIMM, INNER);
    mma_gemm<true><<<g1, blk, SMEM_TOTAL>>>(ah, al, wvh, wvl, bv, nullptr, vh, vl,
        DIMM, DIMM, DIMM, INNER);

    // 2) RMSNorm + RoPE + scales -> bf16 splits
    normrope_kernel<<<dim3(TOKENS, 2), blk>>>(q, k, rope, nqw, nkw, hks,
                                              qh, ql, kh, kl);

    // 3-5) Flash attention -> attn-out bf16 splits into g_ah/g_al (hs dead)
    flash_kernel<<<dim3(SEQ / 128, BATCH * HEADS), blk, FSMEM>>>(
        qh, ql, kh, kl, vh, vl, ah, al);

    // 6) Output projection (fp32 out + bias)
    dim3 g4(DIMM / BN, TOKENS / BM, 1);
    mma_gemm<false><<<g4, blk, SMEM_TOTAL>>>(ah, al, woh, wol, bo, out,
        nullptr, nullptr, INNER, INNER, INNER, DIMM);
}

// round 11
// speedup vs baseline: 2.9739x; 1.1233x over previous
#include <cuda_runtime.h>
#include <cuda_fp16.h>
#include <stdint.h>
#include <math.h>

// Problem constants
#define BATCH   2
#define SEQ     2048
#define DIMM    2048
#define HEADS   16
#define DHEAD   128
#define INNER   2048
#define TOKENS  (BATCH*SEQ)
#define HIST    512
#define QSCALE  0.08838834764831845f

// Dense GEMM tiling
#define BM 128
#define BN 128
#define BK 32
#define NTHREADS 256

// Flash kernel smem: 5 tiles of 128 rows x 272B (QH, QL, KH, KL, V)
#define FROWB  272
#define FT_SZ  (128 * FROWB)
#define OFF_QH 0
#define OFF_QL (1 * FT_SZ)
#define OFF_KH (2 * FT_SZ)
#define OFF_KL (3 * FT_SZ)
#define OFF_V  (4 * FT_SZ)
#define FSMEM  (5 * FT_SZ)            // 174080

// fp32 scratch
__device__ float g_q[(size_t)TOKENS * INNER];
__device__ float g_k[(size_t)TOKENS * INNER];
// fp16 scratch
__device__ __half g_ah[(size_t)TOKENS * INNER];   // hs split hi; later attn-out hi
__device__ __half g_al[(size_t)TOKENS * INNER];
__device__ __half g_wqh[(size_t)INNER * DIMM];    // QKV weights hi/lo split
__device__ __half g_wql[(size_t)INNER * DIMM];
__device__ __half g_wkh[(size_t)INNER * DIMM];
__device__ __half g_wkl[(size_t)INNER * DIMM];
__device__ __half g_wvh[(size_t)INNER * DIMM];
__device__ __half g_wvl[(size_t)INNER * DIMM];
__device__ __half g_wo[(size_t)INNER * DIMM];     // Wo full fp16 (2-term stage)
__device__ __half g_qh[(size_t)TOKENS * INNER];
__device__ __half g_ql[(size_t)TOKENS * INNER];
__device__ __half g_kh[(size_t)TOKENS * INNER];
__device__ __half g_kl[(size_t)TOKENS * INNER];
__device__ __half g_vf[(size_t)TOKENS * INNER];   // V single fp16 (2-term stage)

__device__ __forceinline__ uint32_t smem_u32(const void* p) {
    uint32_t a;
    asm("{ .reg .u64 t; cvta.to.shared.u64 t, %1; cvt.u32.u64 %0, t; }" : "=r"(a) : "l"(p));
    return a;
}

#define CP16(dst, src) \
    asm volatile("cp.async.cg.shared.global [%0], [%1], 16;" \
        :: "r"(dst), "l"(__cvta_generic_to_global(src)) : "memory")
#define CP_COMMIT() asm volatile("cp.async.commit_group;" ::: "memory")
#define CP_WAIT(n)  asm volatile("cp.async.wait_group %0;" :: "n"(n) : "memory")

#define LDSM4(r, a) \
    asm volatile("ldmatrix.sync.aligned.m8n8.x4.shared.b16 {%0,%1,%2,%3}, [%4];" \
        : "=r"((r)[0]), "=r"((r)[1]), "=r"((r)[2]), "=r"((r)[3]) : "r"(a))
#define LDSM4T(r, a) \
    asm volatile("ldmatrix.sync.aligned.m8n8.x4.trans.shared.b16 {%0,%1,%2,%3}, [%4];" \
        : "=r"((r)[0]), "=r"((r)[1]), "=r"((r)[2]), "=r"((r)[3]) : "r"(a))

#define MMA16816(d, a, b0, b1) \
    asm volatile("mma.sync.aligned.m16n8k16.row.col.f32.f16.f16.f32 " \
        "{%0,%1,%2,%3}, {%4,%5,%6,%7}, {%8,%9}, {%0,%1,%2,%3};" \
        : "+f"((d)[0]), "+f"((d)[1]), "+f"((d)[2]), "+f"((d)[3]) \
        : "r"((a)[0]), "r"((a)[1]), "r"((a)[2]), "r"((a)[3]), "r"(b0), "r"(b1))

__device__ __forceinline__ uint32_t packh(float a, float b) {
    __half2 t = __floats2half2_rn(a, b);
    return *reinterpret_cast<uint32_t*>(&t);
}
__device__ __forceinline__ float hhf(float x) {
    return __half2float(__float2half_rn(x));
}

// ---------------------------------------------------------------------------
// fp32 -> fp16 hi/lo split
// ---------------------------------------------------------------------------
__global__ void __launch_bounds__(256)
convert_split(const float* __restrict__ x,
              __half* __restrict__ h, __half* __restrict__ l)
{
    int i = (blockIdx.x * 256 + threadIdx.x) * 4;
    float4 v = *reinterpret_cast<const float4*>(x + i);
    float h0 = hhf(v.x), h1 = hhf(v.y), h2 = hhf(v.z), h3 = hhf(v.w);
    *reinterpret_cast<uint2*>(h + i) = make_uint2(packh(h0, h1), packh(h2, h3));
    *reinterpret_cast<uint2*>(l + i) =
        make_uint2(packh(v.x - h0, v.y - h1), packh(v.z - h2, v.w - h3));
}

// fp32 -> single fp16
__global__ void __launch_bounds__(256)
convert_full(const float* __restrict__ x, __half* __restrict__ h)
{
    int i = (blockIdx.x * 256 + threadIdx.x) * 4;
    float4 v = *reinterpret_cast<const float4*>(x + i);
    *reinterpret_cast<uint2*>(h + i) =
        make_uint2(packh(v.x, v.y), packh(v.z, v.w));
}

// ---------------------------------------------------------------------------
// Dense GEMM: C = A @ B^T + bias. A always fp16 hi/lo split.
//   TERMS=3: B hi/lo split; MMAs = Ah*Bh + Ah*Bl + Al*Bh  (fp32-grade)
//   TERMS=2: B full fp16;   MMAs = Ah*B + Al*B            (~2.5e-4 from B)
//   OUTM=0: fp32 out (+bias); OUTM=2: single fp16 out (+bias)
// cp.async double-buffered, 2 CTAs/SM.
// ---------------------------------------------------------------------------
template<int TERMS>
__device__ __forceinline__ void fill_stage_bt(uint32_t st,
    const __half* __restrict__ Ah, const __half* __restrict__ Al,
    const __half* __restrict__ Bh, const __half* __restrict__ Bl,
    int row0, int col0, int k0, int lda, int ldb, int tid)
{
    #pragma unroll
    for (int l = 0; l < 4; l++) {
        int c = (tid + l * 256) & 511;
        int r = c >> 2;
        int kc = (c & 3) * 8;
        const __half* src = (l < 2) ? Ah : Al;
        uint32_t dst = st + ((l < 2) ? 0 : 10240) + r * 80 + kc * 2;
        CP16(dst, &src[(long long)(row0 + r) * lda + k0 + kc]);
    }
    if (TERMS == 3) {
        #pragma unroll
        for (int l = 0; l < 4; l++) {
            int c = (tid + l * 256) & 511;
            int r = c >> 2;
            int kc = (c & 3) * 8;
            const __half* src = (l < 2) ? Bh : Bl;
            uint32_t dst = st + ((l < 2) ? 20480 : 30720) + r * 80 + kc * 2;
            CP16(dst, &src[(long long)(col0 + r) * ldb + k0 + kc]);
        }
    } else {
        #pragma unroll
        for (int l = 0; l < 2; l++) {
            int c = tid + l * 256;
            int r = c >> 2;
            int kc = (c & 3) * 8;
            uint32_t dst = st + 20480 + r * 80 + kc * 2;
            CP16(dst, &Bh[(long long)(col0 + r) * ldb + k0 + kc]);
        }
    }
}

template<int TERMS, int OUTM>
__global__ void __launch_bounds__(NTHREADS, 2)
mma_gemm(const __half* __restrict__ Ah, const __half* __restrict__ Al,
         const __half* __restrict__ Bh, const __half* __restrict__ Bl,
         const float* __restrict__ bias,
         float* __restrict__ C, __half* __restrict__ Ch,
         int K, int lda, int ldb, int ldc)
{
    constexpr uint32_t STAGE = (TERMS == 3) ? 40960u : 30720u;
    extern __shared__ __align__(16) char dynsm[];
    const int tid  = threadIdx.x;
    const int wid  = tid >> 5;
    const int lane = tid & 31;
    const int row0 = blockIdx.y * BM;
    const int col0 = blockIdx.x * BN;
    const int wm   = (wid & 3) * 32;
    const int wn   = (wid >> 2) * 64;
    const uint32_t smBase = smem_u32(dynsm);

    float acc[2][8][4];
    #pragma unroll
    for (int i = 0; i < 2; i++)
        #pragma unroll
        for (int j = 0; j < 8; j++)
            #pragma unroll
            for (int t = 0; t < 4; t++) acc[i][j][t] = 0.f;

    const int aRow = wm + (lane & 15);
    const int aColOff = (lane >> 4) << 3;
    const int bRow = wn + (lane & 7) + ((lane >> 4) << 3);
    const int bCol = ((lane >> 3) & 1) << 3;

    const int nch = K / BK;
    fill_stage_bt<TERMS>(smBase, Ah, Al, Bh, Bl, row0, col0, 0, lda, ldb, tid);
    CP_COMMIT();

    for (int ch = 0; ch < nch; ch++) {
        const uint32_t st = smBase + (ch & 1) * STAGE;
        if (ch + 1 < nch) {
            fill_stage_bt<TERMS>(smBase + ((ch + 1) & 1) * STAGE,
                                 Ah, Al, Bh, Bl, row0, col0, (ch + 1) * BK, lda, ldb, tid);
            CP_COMMIT();
            CP_WAIT(1);
        } else {
            CP_WAIT(0);
        }
        __syncthreads();

        #pragma unroll
        for (int kk = 0; kk < BK; kk += 16) {
            uint32_t ah[2][4], al[2][4];
            #pragma unroll
            for (int mi = 0; mi < 2; mi++) {
                uint32_t off = (aRow + mi * 16) * 80 + (kk + aColOff) * 2;
                LDSM4(ah[mi], st + off);
                LDSM4(al[mi], st + 10240 + off);
            }
            #pragma unroll
            for (int ng = 0; ng < 4; ng++) {
                uint32_t bh[4], bl[4];
                uint32_t off = (bRow + ng * 16) * 80 + (kk + bCol) * 2;
                LDSM4(bh, st + 20480 + off);
                if (TERMS == 3) LDSM4(bl, st + 30720 + off);
                #pragma unroll
                for (int mi = 0; mi < 2; mi++) {
                    #pragma unroll
                    for (int s = 0; s < 2; s++) {
                        float* d = acc[mi][ng * 2 + s];
                        MMA16816(d, ah[mi], bh[s * 2], bh[s * 2 + 1]);
                        if (TERMS == 3)
                            MMA16816(d, ah[mi], bl[s * 2], bl[s * 2 + 1]);
                        MMA16816(d, al[mi], bh[s * 2], bh[s * 2 + 1]);
                    }
                }
            }
        }
        __syncthreads();
    }

    #pragma unroll
    for (int mi = 0; mi < 2; mi++) {
        int r = row0 + wm + mi * 16 + (lane >> 2);
        #pragma unroll
        for (int nf = 0; nf < 8; nf++) {
            int c = col0 + wn + nf * 8 + (lane & 3) * 2;
            float b0 = 0.f, b1 = 0.f;
            if (bias) { b0 = bias[c]; b1 = bias[c + 1]; }
            float v00 = acc[mi][nf][0] + b0, v01 = acc[mi][nf][1] + b1;
            float v10 = acc[mi][nf][2] + b0, v11 = acc[mi][nf][3] + b1;
            long long i0 = (long long)r * ldc + c;
            long long i1 = (long long)(r + 8) * ldc + c;
            if (OUTM == 0) {
                *reinterpret_cast<float2*>(C + i0) = make_float2(v00, v01);
                *reinterpret_cast<float2*>(C + i1) = make_float2(v10, v11);
            } else {
                *reinterpret_cast<uint32_t*>(Ch + i0) = packh(v00, v01);
                *reinterpret_cast<uint32_t*>(Ch + i1) = packh(v10, v11);
            }
        }
    }
}

// ---------------------------------------------------------------------------
// Flash attention: S = Q@K^T (3-term fp16 split), online softmax,
// O = P@V (2-term: P hi/lo x V full fp16). O written fp16 hi/lo.
// ---------------------------------------------------------------------------
__global__ void __launch_bounds__(256, 1)
flash_kernel(const __half* __restrict__ qh, const __half* __restrict__ ql,
             const __half* __restrict__ kh, const __half* __restrict__ kl,
             const __half* __restrict__ vf,
             __half* __restrict__ oh, __half* __restrict__ ol)
{
    extern __shared__ __align__(16) char fsm[];
    const uint32_t smb = smem_u32(fsm);
    const int tid  = threadIdx.x;
    const int wid  = tid >> 5;
    const int lane = tid & 31;
    const int q0   = blockIdx.x * 128;
    const int bh   = blockIdx.y;
    const long long tokb = (long long)(bh / HEADS) * SEQ;
    const int hcol = (bh % HEADS) * DHEAD;
    const int wm   = wid * 16;

    auto fill = [&](uint32_t off, const __half* __restrict__ src, int rowStart) {
        #pragma unroll
        for (int l = 0; l < 8; l++) {
            int idx = tid + l * 256;
            int r = idx >> 4, c = idx & 15;
            CP16(smb + off + r * FROWB + c * 16,
                 &src[(tokb + rowStart + r) * INNER + hcol + c * 8]);
        }
    };

    fill(OFF_QH, qh, q0); fill(OFF_QL, ql, q0);
    fill(OFF_KH, kh, 0);  fill(OFF_KL, kl, 0);
    CP_COMMIT();
    fill(OFF_V, vf, 0);
    CP_COMMIT();

    float oacc[16][4];
    #pragma unroll
    for (int g = 0; g < 16; g++)
        #pragma unroll
        for (int t = 0; t < 4; t++) oacc[g][t] = 0.f;
    float m0 = -1e30f, m1 = -1e30f, l0 = 0.f, l1 = 0.f;

    for (int it = 0; it < 16; it++) {
        CP_WAIT(1);
        __syncthreads();

        // ---- S = Q @ K^T (3-term) ----
        float sn[16][4];
        #pragma unroll
        for (int j = 0; j < 16; j++)
            #pragma unroll
            for (int t = 0; t < 4; t++) sn[j][t] = 0.f;

        #pragma unroll
        for (int k8 = 0; k8 < 8; k8++) {
            const int kk = k8 * 16;
            uint32_t qfh[4], qfl[4];
            uint32_t qoff = (uint32_t)(wm + (lane & 15)) * FROWB
                          + (uint32_t)(kk + ((lane >> 4) << 3)) * 2;
            LDSM4(qfh, smb + OFF_QH + qoff);
            LDSM4(qfl, smb + OFF_QL + qoff);
            #pragma unroll
            for (int g = 0; g < 8; g++) {
                uint32_t kbh[4], kbl[4];
                uint32_t koff = (uint32_t)(g * 16 + (lane & 7) + ((lane >> 4) << 3)) * FROWB
                              + (uint32_t)(kk + (((lane >> 3) & 1) << 3)) * 2;
                LDSM4(kbh, smb + OFF_KH + koff);
                LDSM4(kbl, smb + OFF_KL + koff);
                #pragma unroll
                for (int s2 = 0; s2 < 2; s2++) {
                    float* d = sn[g * 2 + s2];
                    MMA16816(d, qfh, kbh[s2 * 2], kbh[s2 * 2 + 1]);
                    MMA16816(d, qfh, kbl[s2 * 2], kbl[s2 * 2 + 1]);
                    MMA16816(d, qfl, kbh[s2 * 2], kbh[s2 * 2 + 1]);
                }
            }
        }
        __syncthreads();
        if (it < 15) {
            fill(OFF_KH, kh, (it + 1) * 128);
            fill(OFF_KL, kl, (it + 1) * 128);
            CP_COMMIT();
        }

        // ---- online softmax ----
        float rm0 = -1e30f, rm1 = -1e30f;
        #pragma unroll
        for (int j = 0; j < 16; j++) {
            rm0 = fmaxf(rm0, fmaxf(sn[j][0], sn[j][1]));
            rm1 = fmaxf(rm1, fmaxf(sn[j][2], sn[j][3]));
        }
        rm0 = fmaxf(rm0, __shfl_xor_sync(0xFFFFFFFFu, rm0, 1));
        rm0 = fmaxf(rm0, __shfl_xor_sync(0xFFFFFFFFu, rm0, 2));
        rm1 = fmaxf(rm1, __shfl_xor_sync(0xFFFFFFFFu, rm1, 1));
        rm1 = fmaxf(rm1, __shfl_xor_sync(0xFFFFFFFFu, rm1, 2));
        const float mn0 = fmaxf(m0, rm0), mn1 = fmaxf(m1, rm1);
        const float sc0 = __expf(m0 - mn0), sc1 = __expf(m1 - mn1);
        float rs0 = 0.f, rs1 = 0.f;
        #pragma unroll
        for (int j = 0; j < 16; j++) {
            sn[j][0] = __expf(sn[j][0] - mn0);
            sn[j][1] = __expf(sn[j][1] - mn0);
            sn[j][2] = __expf(sn[j][2] - mn1);
            sn[j][3] = __expf(sn[j][3] - mn1);
            rs0 += sn[j][0] + sn[j][1];
            rs1 += sn[j][2] + sn[j][3];
        }
        rs0 += __shfl_xor_sync(0xFFFFFFFFu, rs0, 1);
        rs0 += __shfl_xor_sync(0xFFFFFFFFu, rs0, 2);
        rs1 += __shfl_xor_sync(0xFFFFFFFFu, rs1, 1);
        rs1 += __shfl_xor_sync(0xFFFFFFFFu, rs1, 2);
        l0 = l0 * sc0 + rs0;  l1 = l1 * sc1 + rs1;
        m0 = mn0;  m1 = mn1;
        #pragma unroll
        for (int g = 0; g < 16; g++) {
            oacc[g][0] *= sc0;  oacc[g][1] *= sc0;
            oacc[g][2] *= sc1;  oacc[g][3] *= sc1;
        }

        if (it < 15) CP_WAIT(1); else CP_WAIT(0);
        __syncthreads();

        // ---- O += P @ V (2-term) ----
        #pragma unroll
        for (int s = 0; s < 8; s++) {
            const float* f0 = sn[2 * s];
            const float* f1 = sn[2 * s + 1];
            uint32_t pah[4], pal[4];
            {
                float h00 = hhf(f0[0]), h01 = hhf(f0[1]), h02 = hhf(f0[2]), h03 = hhf(f0[3]);
                float h10 = hhf(f1[0]), h11 = hhf(f1[1]), h12 = hhf(f1[2]), h13 = hhf(f1[3]);
                pah[0] = packh(h00, h01);  pal[0] = packh(f0[0] - h00, f0[1] - h01);
                pah[1] = packh(h02, h03);  pal[1] = packh(f0[2] - h02, f0[3] - h03);
                pah[2] = packh(h10, h11);  pal[2] = packh(f1[0] - h10, f1[1] - h11);
                pah[3] = packh(h12, h13);  pal[3] = packh(f1[2] - h12, f1[3] - h13);
            }
            #pragma unroll
            for (int g = 0; g < 8; g++) {
                uint32_t vb[4];
                uint32_t voff = (uint32_t)(s * 16 + (lane & 7) + (((lane >> 3) & 1) << 3)) * FROWB
                              + (uint32_t)(g * 16 + ((lane >> 4) << 3)) * 2;
                LDSM4T(vb, smb + OFF_V + voff);
                #pragma unroll
                for (int s2 = 0; s2 < 2; s2++) {
                    float* d = oacc[g * 2 + s2];
                    MMA16816(d, pah, vb[s2 * 2], vb[s2 * 2 + 1]);
                    MMA16816(d, pal, vb[s2 * 2], vb[s2 * 2 + 1]);
                }
            }
        }
        __syncthreads();
        if (it < 15) {
            fill(OFF_V, vf, (it + 1) * 128);
            CP_COMMIT();
        }
    }

    // ---- normalize + write O as fp16 hi/lo ----
    const float inv0 = 1.f / l0, inv1 = 1.f / l1;
    const int r0 = q0 + wm + (lane >> 2);
    #pragma unroll
    for (int g = 0; g < 16; g++) {
        const int c = hcol + g * 8 + (lane & 3) * 2;
        float v0 = oacc[g][0] * inv0, v1 = oacc[g][1] * inv0;
        float v2 = oacc[g][2] * inv1, v3 = oacc[g][3] * inv1;
        long long i0 = (tokb + r0) * INNER + c;
        long long i1 = (tokb + r0 + 8) * INNER + c;
        float h0 = hhf(v0), h1 = hhf(v1), h2 = hhf(v2), h3 = hhf(v3);
        *reinterpret_cast<uint32_t*>(oh + i0) = packh(h0, h1);
        *reinterpret_cast<uint32_t*>(ol + i0) = packh(v0 - h0, v1 - h1);
        *reinterpret_cast<uint32_t*>(oh + i1) = packh(h2, h3);
        *reinterpret_cast<uint32_t*>(ol + i1) = packh(v2 - h2, v3 - h3);
    }
}

// ---------------------------------------------------------------------------
// Fused RMSNorm + RoPE + scales; fp32 in, fp16 hi/lo out.
// ---------------------------------------------------------------------------
__global__ void __launch_bounds__(256)
normrope_kernel(const float* __restrict__ q, const float* __restrict__ k,
                const float* __restrict__ rope,
                const float* __restrict__ wq, const float* __restrict__ wk,
                const float* __restrict__ hks,
                __half* __restrict__ qh, __half* __restrict__ ql,
                __half* __restrict__ kh, __half* __restrict__ kl)
{
    const int tok = blockIdx.x;
    const int s   = tok & (SEQ - 1);
    const bool isK = (blockIdx.y == 1);
    const float* x = (isK ? k : q) + (long long)tok * INNER;
    __half* outh = (isK ? kh : qh) + (long long)tok * INNER;
    __half* outl = (isK ? kl : ql) + (long long)tok * INNER;
    const float* w = isK ? wk : wq;
    const int tid = threadIdx.x;

    float2 vals[4];
    float ss = 0.f;
    #pragma unroll
    for (int l = 0; l < 4; l++) {
        int p = tid + 256 * l;
        float2 vv = *reinterpret_cast<const float2*>(&x[2 * p]);
        ss += vv.x * vv.x + vv.y * vv.y;
        vals[l] = vv;
    }
    #pragma unroll
    for (int off = 16; off; off >>= 1) ss += __shfl_xor_sync(0xFFFFFFFFu, ss, off);
    __shared__ float sred[8];
    if ((tid & 31) == 0) sred[tid >> 5] = ss;
    __syncthreads();
    float tot = 0.f;
    #pragma unroll
    for (int i = 0; i < 8; i++) tot += sred[i];
    const float inv = rsqrtf(tot * (1.f / (float)INNER) + 1e-5f);

    #pragma unroll
    for (int l = 0; l < 4; l++) {
        int p = tid + 256 * l;
        int h = p >> 6;
        int i = p & 63;
        float c  = rope[(long long)s * 256 + 2 * i];
        float sn = rope[(long long)s * 256 + 128 + 2 * i + 1];
        float x1 = vals[l].x * inv * w[2 * p];
        float x2 = vals[l].y * inv * w[2 * p + 1];
        float e = x1 * c - x2 * sn;
        float o = x1 * sn + x2 * c;
        float mult;
        if (isK) {
            mult = (s < HIST) ? (1.f + 9.f / (1.f + __expf(-hks[h]))) : 1.f;
        } else {
            mult = QSCALE;
        }
        e *= mult; o *= mult;
        float eh = hhf(e), oh2 = hhf(o);
        *reinterpret_cast<uint32_t*>(&outh[2 * p]) = packh(eh, oh2);
        *reinterpret_cast<uint32_t*>(&outl[2 * p]) = packh(e - eh, o - oh2);
    }
}

// ---------------------------------------------------------------------------
extern "C" void kernel_launch(void* const* d_in, const int* in_sizes, int n_in,
                              void* d_out, int out_size)
{
    const float* hs   = (const float*)d_in[0];
    const float* rope = (const float*)d_in[1];
    const float* Wq   = (const float*)d_in[2];
    const float* bq   = (const float*)d_in[3];
    const float* Wk   = (const float*)d_in[4];
    const float* bk   = (const float*)d_in[5];
    const float* Wv   = (const float*)d_in[6];
    const float* bv   = (const float*)d_in[7];
    const float* nqw  = (const float*)d_in[8];
    const float* nkw  = (const float*)d_in[9];
    const float* hks  = (const float*)d_in[10];
    const float* Wo   = (const float*)d_in[11];
    const float* bo   = (const float*)d_in[12];
    float* out = (float*)d_out;

    float *q, *k;
    __half *ah, *al, *wqh, *wql, *wkh, *wkl, *wvh, *wvl, *wo;
    __half *qh, *ql, *kh, *kl, *vf;
    cudaGetSymbolAddress((void**)&q,   g_q);
    cudaGetSymbolAddress((void**)&k,   g_k);
    cudaGetSymbolAddress((void**)&ah,  g_ah);
    cudaGetSymbolAddress((void**)&al,  g_al);
    cudaGetSymbolAddress((void**)&wqh, g_wqh);
    cudaGetSymbolAddress((void**)&wql, g_wql);
    cudaGetSymbolAddress((void**)&wkh, g_wkh);
    cudaGetSymbolAddress((void**)&wkl, g_wkl);
    cudaGetSymbolAddress((void**)&wvh, g_wvh);
    cudaGetSymbolAddress((void**)&wvl, g_wvl);
    cudaGetSymbolAddress((void**)&wo,  g_wo);
    cudaGetSymbolAddress((void**)&qh,  g_qh);
    cudaGetSymbolAddress((void**)&ql,  g_ql);
    cudaGetSymbolAddress((void**)&kh,  g_kh);
    cudaGetSymbolAddress((void**)&kl,  g_kl);
    cudaGetSymbolAddress((void**)&vf,  g_vf);

    cudaFuncSetAttribute(mma_gemm<3, 0>,
        cudaFuncAttributeMaxDynamicSharedMemorySize, 81920);
    cudaFuncSetAttribute(mma_gemm<3, 2>,
        cudaFuncAttributeMaxDynamicSharedMemorySize, 81920);
    cudaFuncSetAttribute(mma_gemm<2, 0>,
        cudaFuncAttributeMaxDynamicSharedMemorySize, 61440);
    cudaFuncSetAttribute(flash_kernel,
        cudaFuncAttributeMaxDynamicSharedMemorySize, FSMEM);

    dim3 blk(NTHREADS);

    // 0) converts: activations + QKV weights split, Wo full
    convert_split<<<TOKENS * DIMM / 1024, 256>>>(hs, ah, al);
    convert_split<<<INNER * DIMM / 1024, 256>>>(Wq, wqh, wql);
    convert_split<<<INNER * DIMM / 1024, 256>>>(Wk, wkh, wkl);
    convert_split<<<INNER * DIMM / 1024, 256>>>(Wv, wvh, wvl);
    convert_full<<<INNER * DIMM / 1024, 256>>>(Wo, wo);

    // 1) QKV projections (3-term)
    dim3 g1(INNER / BN, TOKENS / BM, 1);
    mma_gemm<3, 0><<<g1, blk, 81920>>>(ah, al, wqh, wql, bq, q, nullptr,
        DIMM, DIMM, DIMM, INNER);
    mma_gemm<3, 0><<<g1, blk, 81920>>>(ah, al, wkh, wkl, bk, k, nullptr,
        DIMM, DIMM, DIMM, INNER);
    mma_gemm<3, 2><<<g1, blk, 81920>>>(ah, al, wvh, wvl, bv, nullptr, vf,
        DIMM, DIMM, DIMM, INNER);

    // 2) RMSNorm + RoPE + scales -> fp16 splits
    normrope_kernel<<<dim3(TOKENS, 2), blk>>>(q, k, rope, nqw, nkw, hks,
                                              qh, ql, kh, kl);

    // 3-5) Flash attention -> attn-out fp16 splits into g_ah/g_al
    flash_kernel<<<dim3(SEQ / 128, BATCH * HEADS), blk, FSMEM>>>(
        qh, ql, kh, kl, vf, ah, al);

    // 6) Output projection (2-term, fp32 out + bias)
    dim3 g4(DIMM / BN, TOKENS / BM, 1);
    mma_gemm<2, 0><<<g4, blk, 61440>>>(ah, al, wo, nullptr, bo, out, nullptr,
        INNER, INNER, INNER, DIMM);
}

// round 12
// speedup vs baseline: 3.3570x; 1.1288x over previous
#include <cuda_runtime.h>
#include <cuda_fp16.h>
#include <stdint.h>
#include <math.h>

// Problem constants
#define BATCH   2
#define SEQ     2048
#define DIMM    2048
#define HEADS   16
#define DHEAD   128
#define INNER   2048
#define TOKENS  (BATCH*SEQ)
#define HIST    512
#define QSCALE  0.08838834764831845f

// Dense GEMM tiling
#define BM 128
#define BN 128
#define BK 32
#define NTHREADS 256

// Flash kernel smem: 5 tiles of 128 rows x 272B (QH, QL, KH, KL, V)
#define FROWB  272
#define FT_SZ  (128 * FROWB)
#define OFF_QH 0
#define OFF_QL (1 * FT_SZ)
#define OFF_KH (2 * FT_SZ)
#define OFF_KL (3 * FT_SZ)
#define OFF_V  (4 * FT_SZ)
#define FSMEM  (5 * FT_SZ)            // 174080

// fp32 scratch
__device__ float g_q[(size_t)TOKENS * INNER];
__device__ float g_k[(size_t)TOKENS * INNER];
// fp16 scratch
__device__ __half g_ah[(size_t)TOKENS * INNER];   // hs split hi; later attn-out (single)
__device__ __half g_al[(size_t)TOKENS * INNER];   // hs split lo
__device__ __half g_wqh[(size_t)INNER * DIMM];    // Q/K weights hi/lo split
__device__ __half g_wql[(size_t)INNER * DIMM];
__device__ __half g_wkh[(size_t)INNER * DIMM];
__device__ __half g_wkl[(size_t)INNER * DIMM];
__device__ __half g_wv[(size_t)INNER * DIMM];     // Wv full fp16 (2-term stage)
__device__ __half g_wo[(size_t)INNER * DIMM];     // Wo full fp16 (1-term stage)
__device__ __half g_qh[(size_t)TOKENS * INNER];
__device__ __half g_ql[(size_t)TOKENS * INNER];
__device__ __half g_kh[(size_t)TOKENS * INNER];
__device__ __half g_kl[(size_t)TOKENS * INNER];
__device__ __half g_vf[(size_t)TOKENS * INNER];   // V single fp16

__device__ __forceinline__ uint32_t smem_u32(const void* p) {
    uint32_t a;
    asm("{ .reg .u64 t; cvta.to.shared.u64 t, %1; cvt.u32.u64 %0, t; }" : "=r"(a) : "l"(p));
    return a;
}

#define CP16(dst, src) \
    asm volatile("cp.async.cg.shared.global [%0], [%1], 16;" \
        :: "r"(dst), "l"(__cvta_generic_to_global(src)) : "memory")
#define CP_COMMIT() asm volatile("cp.async.commit_group;" ::: "memory")
#define CP_WAIT(n)  asm volatile("cp.async.wait_group %0;" :: "n"(n) : "memory")

#define LDSM4(r, a) \
    asm volatile("ldmatrix.sync.aligned.m8n8.x4.shared.b16 {%0,%1,%2,%3}, [%4];" \
        : "=r"((r)[0]), "=r"((r)[1]), "=r"((r)[2]), "=r"((r)[3]) : "r"(a))
#define LDSM4T(r, a) \
    asm volatile("ldmatrix.sync.aligned.m8n8.x4.trans.shared.b16 {%0,%1,%2,%3}, [%4];" \
        : "=r"((r)[0]), "=r"((r)[1]), "=r"((r)[2]), "=r"((r)[3]) : "r"(a))

#define MMA16816(d, a, b0, b1) \
    asm volatile("mma.sync.aligned.m16n8k16.row.col.f32.f16.f16.f32 " \
        "{%0,%1,%2,%3}, {%4,%5,%6,%7}, {%8,%9}, {%0,%1,%2,%3};" \
        : "+f"((d)[0]), "+f"((d)[1]), "+f"((d)[2]), "+f"((d)[3]) \
        : "r"((a)[0]), "r"((a)[1]), "r"((a)[2]), "r"((a)[3]), "r"(b0), "r"(b1))

__device__ __forceinline__ uint32_t packh(float a, float b) {
    __half2 t = __floats2half2_rn(a, b);
    return *reinterpret_cast<uint32_t*>(&t);
}
__device__ __forceinline__ float hhf(float x) {
    return __half2float(__float2half_rn(x));
}

// ---------------------------------------------------------------------------
// fp32 -> fp16 hi/lo split
// ---------------------------------------------------------------------------
__global__ void __launch_bounds__(256)
convert_split(const float* __restrict__ x,
              __half* __restrict__ h, __half* __restrict__ l)
{
    int i = (blockIdx.x * 256 + threadIdx.x) * 4;
    float4 v = *reinterpret_cast<const float4*>(x + i);
    float h0 = hhf(v.x), h1 = hhf(v.y), h2 = hhf(v.z), h3 = hhf(v.w);
    *reinterpret_cast<uint2*>(h + i) = make_uint2(packh(h0, h1), packh(h2, h3));
    *reinterpret_cast<uint2*>(l + i) =
        make_uint2(packh(v.x - h0, v.y - h1), packh(v.z - h2, v.w - h3));
}

// fp32 -> single fp16
__global__ void __launch_bounds__(256)
convert_full(const float* __restrict__ x, __half* __restrict__ h)
{
    int i = (blockIdx.x * 256 + threadIdx.x) * 4;
    float4 v = *reinterpret_cast<const float4*>(x + i);
    *reinterpret_cast<uint2*>(h + i) =
        make_uint2(packh(v.x, v.y), packh(v.z, v.w));
}

// ---------------------------------------------------------------------------
// Dense GEMM: C = A @ B^T + bias.
//   TERMS=3: A hi/lo, B hi/lo; Ah*Bh + Ah*Bl + Al*Bh  (fp32-grade)
//   TERMS=2: A hi/lo, B full;  Ah*B + Al*B
//   TERMS=1: A full, B full;   A*B
//   OUTM=0: fp32 out (+bias); OUTM=2: single fp16 out (+bias)
// cp.async double-buffered, 2 CTAs/SM.
// ---------------------------------------------------------------------------
template<int TERMS>
__device__ __forceinline__ void fill_stage_bt(uint32_t st,
    const __half* __restrict__ Ah, const __half* __restrict__ Al,
    const __half* __restrict__ Bh, const __half* __restrict__ Bl,
    int row0, int col0, int k0, int lda, int ldb, int tid)
{
    constexpr uint32_t OFFB = (TERMS == 1) ? 10240u : 20480u;
    #pragma unroll
    for (int l = 0; l < ((TERMS >= 2) ? 4 : 2); l++) {
        int c = (tid + l * 256) & 511;
        int r = c >> 2;
        int kc = (c & 3) * 8;
        const __half* src = (l < 2) ? Ah : Al;
        uint32_t dst = st + ((l < 2) ? 0u : 10240u) + r * 80 + kc * 2;
        CP16(dst, &src[(long long)(row0 + r) * lda + k0 + kc]);
    }
    #pragma unroll
    for (int l = 0; l < ((TERMS == 3) ? 4 : 2); l++) {
        int c = (tid + l * 256) & 511;
        int r = c >> 2;
        int kc = (c & 3) * 8;
        const __half* src = (l < 2) ? Bh : Bl;
        uint32_t dst = st + OFFB + ((l < 2) ? 0u : 10240u) + r * 80 + kc * 2;
        CP16(dst, &src[(long long)(col0 + r) * ldb + k0 + kc]);
    }
}

template<int TERMS, int OUTM>
__global__ void __launch_bounds__(NTHREADS, 2)
mma_gemm(const __half* __restrict__ Ah, const __half* __restrict__ Al,
         const __half* __restrict__ Bh, const __half* __restrict__ Bl,
         const float* __restrict__ bias,
         float* __restrict__ C, __half* __restrict__ Ch,
         int K, int lda, int ldb, int ldc)
{
    constexpr uint32_t STAGE = (TERMS == 3) ? 40960u : (TERMS == 2) ? 30720u : 20480u;
    constexpr uint32_t OFFB  = (TERMS == 1) ? 10240u : 20480u;
    extern __shared__ __align__(16) char dynsm[];
    const int tid  = threadIdx.x;
    const int wid  = tid >> 5;
    const int lane = tid & 31;
    const int row0 = blockIdx.y * BM;
    const int col0 = blockIdx.x * BN;
    const int wm   = (wid & 3) * 32;
    const int wn   = (wid >> 2) * 64;
    const uint32_t smBase = smem_u32(dynsm);

    float acc[2][8][4];
    #pragma unroll
    for (int i = 0; i < 2; i++)
        #pragma unroll
        for (int j = 0; j < 8; j++)
            #pragma unroll
            for (int t = 0; t < 4; t++) acc[i][j][t] = 0.f;

    const int aRow = wm + (lane & 15);
    const int aColOff = (lane >> 4) << 3;
    const int bRow = wn + (lane & 7) + ((lane >> 4) << 3);
    const int bCol = ((lane >> 3) & 1) << 3;

    const int nch = K / BK;
    fill_stage_bt<TERMS>(smBase, Ah, Al, Bh, Bl, row0, col0, 0, lda, ldb, tid);
    CP_COMMIT();

    for (int ch = 0; ch < nch; ch++) {
        const uint32_t st = smBase + (ch & 1) * STAGE;
        if (ch + 1 < nch) {
            fill_stage_bt<TERMS>(smBase + ((ch + 1) & 1) * STAGE,
                                 Ah, Al, Bh, Bl, row0, col0, (ch + 1) * BK, lda, ldb, tid);
            CP_COMMIT();
            CP_WAIT(1);
        } else {
            CP_WAIT(0);
        }
        __syncthreads();

        #pragma unroll
        for (int kk = 0; kk < BK; kk += 16) {
            uint32_t ah[2][4], al[2][4];
            #pragma unroll
            for (int mi = 0; mi < 2; mi++) {
                uint32_t off = (aRow + mi * 16) * 80 + (kk + aColOff) * 2;
                LDSM4(ah[mi], st + off);
                if (TERMS >= 2) LDSM4(al[mi], st + 10240 + off);
            }
            #pragma unroll
            for (int ng = 0; ng < 4; ng++) {
                uint32_t bh[4], bl[4];
                uint32_t off = (bRow + ng * 16) * 80 + (kk + bCol) * 2;
                LDSM4(bh, st + OFFB + off);
                if (TERMS == 3) LDSM4(bl, st + OFFB + 10240 + off);
                #pragma unroll
                for (int mi = 0; mi < 2; mi++) {
                    #pragma unroll
                    for (int s = 0; s < 2; s++) {
                        float* d = acc[mi][ng * 2 + s];
                        MMA16816(d, ah[mi], bh[s * 2], bh[s * 2 + 1]);
                        if (TERMS == 3)
                            MMA16816(d, ah[mi], bl[s * 2], bl[s * 2 + 1]);
                        if (TERMS >= 2)
                            MMA16816(d, al[mi], bh[s * 2], bh[s * 2 + 1]);
                    }
                }
            }
        }
        __syncthreads();
    }

    #pragma unroll
    for (int mi = 0; mi < 2; mi++) {
        int r = row0 + wm + mi * 16 + (lane >> 2);
        #pragma unroll
        for (int nf = 0; nf < 8; nf++) {
            int c = col0 + wn + nf * 8 + (lane & 3) * 2;
            float b0 = 0.f, b1 = 0.f;
            if (bias) { b0 = bias[c]; b1 = bias[c + 1]; }
            float v00 = acc[mi][nf][0] + b0, v01 = acc[mi][nf][1] + b1;
            float v10 = acc[mi][nf][2] + b0, v11 = acc[mi][nf][3] + b1;
            long long i0 = (long long)r * ldc + c;
            long long i1 = (long long)(r + 8) * ldc + c;
            if (OUTM == 0) {
                *reinterpret_cast<float2*>(C + i0) = make_float2(v00, v01);
                *reinterpret_cast<float2*>(C + i1) = make_float2(v10, v11);
            } else {
                *reinterpret_cast<uint32_t*>(Ch + i0) = packh(v00, v01);
                *reinterpret_cast<uint32_t*>(Ch + i1) = packh(v10, v11);
            }
        }
    }
}

// ---------------------------------------------------------------------------
// Flash attention: S = Q@K^T (3-term fp16 split), online softmax,
// O = P@V (2-term: P hi/lo x V full fp16). O written single fp16.
// ---------------------------------------------------------------------------
__global__ void __launch_bounds__(256, 1)
flash_kernel(const __half* __restrict__ qh, const __half* __restrict__ ql,
             const __half* __restrict__ kh, const __half* __restrict__ kl,
             const __half* __restrict__ vf,
             __half* __restrict__ oh)
{
    extern __shared__ __align__(16) char fsm[];
    const uint32_t smb = smem_u32(fsm);
    const int tid  = threadIdx.x;
    const int wid  = tid >> 5;
    const int lane = tid & 31;
    const int q0   = blockIdx.x * 128;
    const int bh   = blockIdx.y;
    const long long tokb = (long long)(bh / HEADS) * SEQ;
    const int hcol = (bh % HEADS) * DHEAD;
    const int wm   = wid * 16;

    auto fill = [&](uint32_t off, const __half* __restrict__ src, int rowStart) {
        #pragma unroll
        for (int l = 0; l < 8; l++) {
            int idx = tid + l * 256;
            int r = idx >> 4, c = idx & 15;
            CP16(smb + off + r * FROWB + c * 16,
                 &src[(tokb + rowStart + r) * INNER + hcol + c * 8]);
        }
    };

    fill(OFF_QH, qh, q0); fill(OFF_QL, ql, q0);
    fill(OFF_KH, kh, 0);  fill(OFF_KL, kl, 0);
    CP_COMMIT();
    fill(OFF_V, vf, 0);
    CP_COMMIT();

    float oacc[16][4];
    #pragma unroll
    for (int g = 0; g < 16; g++)
        #pragma unroll
        for (int t = 0; t < 4; t++) oacc[g][t] = 0.f;
    float m0 = -1e30f, m1 = -1e30f, l0 = 0.f, l1 = 0.f;

    for (int it = 0; it < 16; it++) {
        CP_WAIT(1);
        __syncthreads();

        // ---- S = Q @ K^T (3-term) ----
        float sn[16][4];
        #pragma unroll
        for (int j = 0; j < 16; j++)
            #pragma unroll
            for (int t = 0; t < 4; t++) sn[j][t] = 0.f;

        #pragma unroll
        for (int k8 = 0; k8 < 8; k8++) {
            const int kk = k8 * 16;
            uint32_t qfh[4], qfl[4];
            uint32_t qoff = (uint32_t)(wm + (lane & 15)) * FROWB
                          + (uint32_t)(kk + ((lane >> 4) << 3)) * 2;
            LDSM4(qfh, smb + OFF_QH + qoff);
            LDSM4(qfl, smb + OFF_QL + qoff);
            #pragma unroll
            for (int g = 0; g < 8; g++) {
                uint32_t kbh[4], kbl[4];
                uint32_t koff = (uint32_t)(g * 16 + (lane & 7) + ((lane >> 4) << 3)) * FROWB
                              + (uint32_t)(kk + (((lane >> 3) & 1) << 3)) * 2;
                LDSM4(kbh, smb + OFF_KH + koff);
                LDSM4(kbl, smb + OFF_KL + koff);
                #pragma unroll
                for (int s2 = 0; s2 < 2; s2++) {
                    float* d = sn[g * 2 + s2];
                    MMA16816(d, qfh, kbh[s2 * 2], kbh[s2 * 2 + 1]);
                    MMA16816(d, qfh, kbl[s2 * 2], kbl[s2 * 2 + 1]);
                    MMA16816(d, qfl, kbh[s2 * 2], kbh[s2 * 2 + 1]);
                }
            }
        }
        __syncthreads();
        if (it < 15) {
            fill(OFF_KH, kh, (it + 1) * 128);
            fill(OFF_KL, kl, (it + 1) * 128);
            CP_COMMIT();
        }

        // ---- online softmax ----
        float rm0 = -1e30f, rm1 = -1e30f;
        #pragma unroll
        for (int j = 0; j < 16; j++) {
            rm0 = fmaxf(rm0, fmaxf(sn[j][0], sn[j][1]));
            rm1 = fmaxf(rm1, fmaxf(sn[j][2], sn[j][3]));
        }
        rm0 = fmaxf(rm0, __shfl_xor_sync(0xFFFFFFFFu, rm0, 1));
        rm0 = fmaxf(rm0, __shfl_xor_sync(0xFFFFFFFFu, rm0, 2));
        rm1 = fmaxf(rm1, __shfl_xor_sync(0xFFFFFFFFu, rm1, 1));
        rm1 = fmaxf(rm1, __shfl_xor_sync(0xFFFFFFFFu, rm1, 2));
        const float mn0 = fmaxf(m0, rm0), mn1 = fmaxf(m1, rm1);
        const float sc0 = __expf(m0 - mn0), sc1 = __expf(m1 - mn1);
        float rs0 = 0.f, rs1 = 0.f;
        #pragma unroll
        for (int j = 0; j < 16; j++) {
            sn[j][0] = __expf(sn[j][0] - mn0);
            sn[j][1] = __expf(sn[j][1] - mn0);
            sn[j][2] = __expf(sn[j][2] - mn1);
            sn[j][3] = __expf(sn[j][3] - mn1);
            rs0 += sn[j][0] + sn[j][1];
            rs1 += sn[j][2] + sn[j][3];
        }
        rs0 += __shfl_xor_sync(0xFFFFFFFFu, rs0, 1);
        rs0 += __shfl_xor_sync(0xFFFFFFFFu, rs0, 2);
        rs1 += __shfl_xor_sync(0xFFFFFFFFu, rs1, 1);
        rs1 += __shfl_xor_sync(0xFFFFFFFFu, rs1, 2);
        l0 = l0 * sc0 + rs0;  l1 = l1 * sc1 + rs1;
        m0 = mn0;  m1 = mn1;
        #pragma unroll
        for (int g = 0; g < 16; g++) {
            oacc[g][0] *= sc0;  oacc[g][1] *= sc0;
            oacc[g][2] *= sc1;  oacc[g][3] *= sc1;
        }

        if (it < 15) CP_WAIT(1); else CP_WAIT(0);
        __syncthreads();

        // ---- O += P @ V (2-term) ----
        #pragma unroll
        for (int s = 0; s < 8; s++) {
            const float* f0 = sn[2 * s];
            const float* f1 = sn[2 * s + 1];
            uint32_t pah[4], pal[4];
            {
                float h00 = hhf(f0[0]), h01 = hhf(f0[1]), h02 = hhf(f0[2]), h03 = hhf(f0[3]);
                float h10 = hhf(f1[0]), h11 = hhf(f1[1]), h12 = hhf(f1[2]), h13 = hhf(f1[3]);
                pah[0] = packh(h00, h01);  pal[0] = packh(f0[0] - h00, f0[1] - h01);
                pah[1] = packh(h02, h03);  pal[1] = packh(f0[2] - h02, f0[3] - h03);
                pah[2] = packh(h10, h11);  pal[2] = packh(f1[0] - h10, f1[1] - h11);
                pah[3] = packh(h12, h13);  pal[3] = packh(f1[2] - h12, f1[3] - h13);
            }
            #pragma unroll
            for (int g = 0; g < 8; g++) {
                uint32_t vb[4];
                uint32_t voff = (uint32_t)(s * 16 + (lane & 7) + (((lane >> 3) & 1) << 3)) * FROWB
                              + (uint32_t)(g * 16 + ((lane >> 4) << 3)) * 2;
                LDSM4T(vb, smb + OFF_V + voff);
                #pragma unroll
                for (int s2 = 0; s2 < 2; s2++) {
                    float* d = oacc[g * 2 + s2];
                    MMA16816(d, pah, vb[s2 * 2], vb[s2 * 2 + 1]);
                    MMA16816(d, pal, vb[s2 * 2], vb[s2 * 2 + 1]);
                }
            }
        }
        __syncthreads();
        if (it < 15) {
            fill(OFF_V, vf, (it + 1) * 128);
            CP_COMMIT();
        }
    }

    // ---- normalize + write O as single fp16 ----
    const float inv0 = 1.f / l0, inv1 = 1.f / l1;
    const int r0 = q0 + wm + (lane >> 2);
    #pragma unroll
    for (int g = 0; g < 16; g++) {
        const int c = hcol + g * 8 + (lane & 3) * 2;
        long long i0 = (tokb + r0) * INNER + c;
        long long i1 = (tokb + r0 + 8) * INNER + c;
        *reinterpret_cast<uint32_t*>(oh + i0) =
            packh(oacc[g][0] * inv0, oacc[g][1] * inv0);
        *reinterpret_cast<uint32_t*>(oh + i1) =
            packh(oacc[g][2] * inv1, oacc[g][3] * inv1);
    }
}

// ---------------------------------------------------------------------------
// Fused RMSNorm + RoPE + scales; fp32 in, fp16 hi/lo out.
// ---------------------------------------------------------------------------
__global__ void __launch_bounds__(256)
normrope_kernel(const float* __restrict__ q, const float* __restrict__ k,
                const float* __restrict__ rope,
                const float* __restrict__ wq, const float* __restrict__ wk,
                const float* __restrict__ hks,
                __half* __restrict__ qh, __half* __restrict__ ql,
                __half* __restrict__ kh, __half* __restrict__ kl)
{
    const int tok = blockIdx.x;
    const int s   = tok & (SEQ - 1);
    const bool isK = (blockIdx.y == 1);
    const float* x = (isK ? k : q) + (long long)tok * INNER;
    __half* outh = (isK ? kh : qh) + (long long)tok * INNER;
    __half* outl = (isK ? kl : ql) + (long long)tok * INNER;
    const float* w = isK ? wk : wq;
    const int tid = threadIdx.x;

    float2 vals[4];
    float ss = 0.f;
    #pragma unroll
    for (int l = 0; l < 4; l++) {
        int p = tid + 256 * l;
        float2 vv = *reinterpret_cast<const float2*>(&x[2 * p]);
        ss += vv.x * vv.x + vv.y * vv.y;
        vals[l] = vv;
    }
    #pragma unroll
    for (int off = 16; off; off >>= 1) ss += __shfl_xor_sync(0xFFFFFFFFu, ss, off);
    __shared__ float sred[8];
    if ((tid & 31) == 0) sred[tid >> 5] = ss;
    __syncthreads();
    float tot = 0.f;
    #pragma unroll
    for (int i = 0; i < 8; i++) tot += sred[i];
    const float inv = rsqrtf(tot * (1.f / (float)INNER) + 1e-5f);

    #pragma unroll
    for (int l = 0; l < 4; l++) {
        int p = tid + 256 * l;
        int h = p >> 6;
        int i = p & 63;
        float c  = rope[(long long)s * 256 + 2 * i];
        float sn = rope[(long long)s * 256 + 128 + 2 * i + 1];
        float x1 = vals[l].x * inv * w[2 * p];
        float x2 = vals[l].y * inv * w[2 * p + 1];
        float e = x1 * c - x2 * sn;
        float o = x1 * sn + x2 * c;
        float mult;
        if (isK) {
            mult = (s < HIST) ? (1.f + 9.f / (1.f + __expf(-hks[h]))) : 1.f;
        } else {
            mult = QSCALE;
        }
        e *= mult; o *= mult;
        float eh = hhf(e), oh2 = hhf(o);
        *reinterpret_cast<uint32_t*>(&outh[2 * p]) = packh(eh, oh2);
        *reinterpret_cast<uint32_t*>(&outl[2 * p]) = packh(e - eh, o - oh2);
    }
}

// ---------------------------------------------------------------------------
extern "C" void kernel_launch(void* const* d_in, const int* in_sizes, int n_in,
                              void* d_out, int out_size)
{
    const float* hs   = (const float*)d_in[0];
    const float* rope = (const float*)d_in[1];
    const float* Wq   = (const float*)d_in[2];
    const float* bq   = (const float*)d_in[3];
    const float* Wk   = (const float*)d_in[4];
    const float* bk   = (const float*)d_in[5];
    const float* Wv   = (const float*)d_in[6];
    const float* bv   = (const float*)d_in[7];
    const float* nqw  = (const float*)d_in[8];
    const float* nkw  = (const float*)d_in[9];
    const float* hks  = (const float*)d_in[10];
    const float* Wo   = (const float*)d_in[11];
    const float* bo   = (const float*)d_in[12];
    float* out = (float*)d_out;

    float *q, *k;
    __half *ah, *al, *wqh, *wql, *wkh, *wkl, *wv, *wo;
    __half *qh, *ql, *kh, *kl, *vf;
    cudaGetSymbolAddress((void**)&q,   g_q);
    cudaGetSymbolAddress((void**)&k,   g_k);
    cudaGetSymbolAddress((void**)&ah,  g_ah);
    cudaGetSymbolAddress((void**)&al,  g_al);
    cudaGetSymbolAddress((void**)&wqh, g_wqh);
    cudaGetSymbolAddress((void**)&wql, g_wql);
    cudaGetSymbolAddress((void**)&wkh, g_wkh);
    cudaGetSymbolAddress((void**)&wkl, g_wkl);
    cudaGetSymbolAddress((void**)&wv,  g_wv);
    cudaGetSymbolAddress((void**)&wo,  g_wo);
    cudaGetSymbolAddress((void**)&qh,  g_qh);
    cudaGetSymbolAddress((void**)&ql,  g_ql);
    cudaGetSymbolAddress((void**)&kh,  g_kh);
    cudaGetSymbolAddress((void**)&kl,  g_kl);
    cudaGetSymbolAddress((void**)&vf,  g_vf);

    cudaFuncSetAttribute(mma_gemm<3, 0>,
        cudaFuncAttributeMaxDynamicSharedMemorySize, 81920);
    cudaFuncSetAttribute(mma_gemm<2, 2>,
        cudaFuncAttributeMaxDynamicSharedMemorySize, 61440);
    cudaFuncSetAttribute(mma_gemm<1, 0>,
        cudaFuncAttributeMaxDynamicSharedMemorySize, 40960);
    cudaFuncSetAttribute(flash_kernel,
        cudaFuncAttributeMaxDynamicSharedMemorySize, FSMEM);

    dim3 blk(NTHREADS);

    // 0) converts: hs + Wq/Wk split; Wv/Wo full
    convert_split<<<TOKENS * DIMM / 1024, 256>>>(hs, ah, al);
    convert_split<<<INNER * DIMM / 1024, 256>>>(Wq, wqh, wql);
    convert_split<<<INNER * DIMM / 1024, 256>>>(Wk, wkh, wkl);
    convert_full<<<INNER * DIMM / 1024, 256>>>(Wv, wv);
    convert_full<<<INNER * DIMM / 1024, 256>>>(Wo, wo);

    // 1) Q/K projections (3-term), V projection (2-term, fp16 out)
    dim3 g1(INNER / BN, TOKENS / BM, 1);
    mma_gemm<3, 0><<<g1, blk, 81920>>>(ah, al, wqh, wql, bq, q, nullptr,
        DIMM, DIMM, DIMM, INNER);
    mma_gemm<3, 0><<<g1, blk, 81920>>>(ah, al, wkh, wkl, bk, k, nullptr,
        DIMM, DIMM, DIMM, INNER);
    mma_gemm<2, 2><<<g1, blk, 61440>>>(ah, al, wv, nullptr, bv, nullptr, vf,
        DIMM, DIMM, DIMM, INNER);

    // 2) RMSNorm + RoPE + scales -> fp16 splits
    normrope_kernel<<<dim3(TOKENS, 2), blk>>>(q, k, rope, nqw, nkw, hks,
                                              qh, ql, kh, kl);

    // 3-5) Flash attention -> attn-out single fp16 into g_ah
    flash_kernel<<<dim3(SEQ / 128, BATCH * HEADS), blk, FSMEM>>>(
        qh, ql, kh, kl, vf, ah);

    // 6) Output projection (1-term, fp32 out + bias)
    dim3 g4(DIMM / BN, TOKENS / BM, 1);
    mma_gemm<1, 0><<<g4, blk, 40960>>>(ah, nullptr, wo, nullptr, bo, out, nullptr,
        INNER, INNER, INNER, DIMM);
}

// round 14
// speedup vs baseline: 3.5670x; 1.0625x over previous
#include <cuda_runtime.h>
#include <cuda_fp16.h>
#include <stdint.h>
#include <math.h>

// Problem constants
#define BATCH   2
#define SEQ     2048
#define DIMM    2048
#define HEADS   16
#define DHEAD   128
#define INNER   2048
#define TOKENS  (BATCH*SEQ)
#define HIST    512
#define QSCALE  0.08838834764831845f

// Dense GEMM tiling
#define BM 128
#define BN 128
#define BK 32
#define NTHREADS 256

// Flash kernel smem: 5 tiles of 128 rows x 272B (QH, QL, KH, KL, V)
#define FROWB  272
#define FT_SZ  (128 * FROWB)
#define OFF_QH 0
#define OFF_QL (1 * FT_SZ)
#define OFF_KH (2 * FT_SZ)
#define OFF_KL (3 * FT_SZ)
#define OFF_V  (4 * FT_SZ)
#define FSMEM  (5 * FT_SZ)            // 174080

// fp32 scratch
__device__ float g_q[(size_t)TOKENS * INNER];
__device__ float g_k[(size_t)TOKENS * INNER];
// fp16 scratch
__device__ __half g_ah[(size_t)TOKENS * INNER];   // hs split hi; later attn-out (single)
__device__ __half g_al[(size_t)TOKENS * INNER];   // hs split lo
__device__ __half g_wqh[(size_t)INNER * DIMM];    // Q/K weights hi/lo split
__device__ __half g_wql[(size_t)INNER * DIMM];
__device__ __half g_wkh[(size_t)INNER * DIMM];
__device__ __half g_wkl[(size_t)INNER * DIMM];
__device__ __half g_wv[(size_t)INNER * DIMM];     // Wv full fp16 (2-term stage)
__device__ __half g_wo[(size_t)INNER * DIMM];     // Wo full fp16 (1-term stage)
__device__ __half g_qh[(size_t)TOKENS * INNER];
__device__ __half g_ql[(size_t)TOKENS * INNER];
__device__ __half g_kh[(size_t)TOKENS * INNER];
__device__ __half g_kl[(size_t)TOKENS * INNER];
__device__ __half g_vf[(size_t)TOKENS * INNER];   // V single fp16

__device__ __forceinline__ uint32_t smem_u32(const void* p) {
    uint32_t a;
    asm("{ .reg .u64 t; cvta.to.shared.u64 t, %1; cvt.u32.u64 %0, t; }" : "=r"(a) : "l"(p));
    return a;
}

#define CP16(dst, src) \
    asm volatile("cp.async.cg.shared.global [%0], [%1], 16;" \
        :: "r"(dst), "l"(__cvta_generic_to_global(src)) : "memory")
#define CP_COMMIT() asm volatile("cp.async.commit_group;" ::: "memory")
#define CP_WAIT(n)  asm volatile("cp.async.wait_group %0;" :: "n"(n) : "memory")

#define LDSM4(r, a) \
    asm volatile("ldmatrix.sync.aligned.m8n8.x4.shared.b16 {%0,%1,%2,%3}, [%4];" \
        : "=r"((r)[0]), "=r"((r)[1]), "=r"((r)[2]), "=r"((r)[3]) : "r"(a))
#define LDSM4T(r, a) \
    asm volatile("ldmatrix.sync.aligned.m8n8.x4.trans.shared.b16 {%0,%1,%2,%3}, [%4];" \
        : "=r"((r)[0]), "=r"((r)[1]), "=r"((r)[2]), "=r"((r)[3]) : "r"(a))

#define MMA16816(d, a, b0, b1) \
    asm volatile("mma.sync.aligned.m16n8k16.row.col.f32.f16.f16.f32 " \
        "{%0,%1,%2,%3}, {%4,%5,%6,%7}, {%8,%9}, {%0,%1,%2,%3};" \
        : "+f"((d)[0]), "+f"((d)[1]), "+f"((d)[2]), "+f"((d)[3]) \
        : "r"((a)[0]), "r"((a)[1]), "r"((a)[2]), "r"((a)[3]), "r"(b0), "r"(b1))

__device__ __forceinline__ uint32_t packh(float a, float b) {
    __half2 t = __floats2half2_rn(a, b);
    return *reinterpret_cast<uint32_t*>(&t);
}
__device__ __forceinline__ float hhf(float x) {
    return __half2float(__float2half_rn(x));
}

// ---------------------------------------------------------------------------
// fp32 -> fp16 hi/lo split; y-dim selects one of two tensors.
// ---------------------------------------------------------------------------
__global__ void __launch_bounds__(256)
convert_split2(const float* __restrict__ x0, __half* __restrict__ h0,
               __half* __restrict__ l0,
               const float* __restrict__ x1, __half* __restrict__ h1,
               __half* __restrict__ l1)
{
    const float* x = blockIdx.y ? x1 : x0;
    __half* h = blockIdx.y ? h1 : h0;
    __half* l = blockIdx.y ? l1 : l0;
    int i = (blockIdx.x * 256 + threadIdx.x) * 4;
    float4 v = *reinterpret_cast<const float4*>(x + i);
    float a0 = hhf(v.x), a1 = hhf(v.y), a2 = hhf(v.z), a3 = hhf(v.w);
    *reinterpret_cast<uint2*>(h + i) = make_uint2(packh(a0, a1), packh(a2, a3));
    *reinterpret_cast<uint2*>(l + i) =
        make_uint2(packh(v.x - a0, v.y - a1), packh(v.z - a2, v.w - a3));
}

// fp32 -> single fp16; y-dim selects one of two tensors.
__global__ void __launch_bounds__(256)
convert_full2(const float* __restrict__ x0, __half* __restrict__ h0,
              const float* __restrict__ x1, __half* __restrict__ h1)
{
    const float* x = blockIdx.y ? x1 : x0;
    __half* h = blockIdx.y ? h1 : h0;
    int i = (blockIdx.x * 256 + threadIdx.x) * 4;
    float4 v = *reinterpret_cast<const float4*>(x + i);
    *reinterpret_cast<uint2*>(h + i) =
        make_uint2(packh(v.x, v.y), packh(v.z, v.w));
}

// ---------------------------------------------------------------------------
// Dense GEMM tile fill (TERMS as in mma_gemm below)
// ---------------------------------------------------------------------------
template<int TERMS>
__device__ __forceinline__ void fill_stage_bt(uint32_t st,
    const __half* __restrict__ Ah, const __half* __restrict__ Al,
    const __half* __restrict__ Bh, const __half* __restrict__ Bl,
    int row0, int col0, int k0, int lda, int ldb, int tid)
{
    constexpr uint32_t OFFB = (TERMS == 1) ? 10240u : 20480u;
    #pragma unroll
    for (int l = 0; l < ((TERMS >= 2) ? 4 : 2); l++) {
        int c = (tid + l * 256) & 511;
        int r = c >> 2;
        int kc = (c & 3) * 8;
        const __half* src = (l < 2) ? Ah : Al;
        uint32_t dst = st + ((l < 2) ? 0u : 10240u) + r * 80 + kc * 2;
        CP16(dst, &src[(long long)(row0 + r) * lda + k0 + kc]);
    }
    #pragma unroll
    for (int l = 0; l < ((TERMS == 3) ? 4 : 2); l++) {
        int c = (tid + l * 256) & 511;
        int r = c >> 2;
        int kc = (c & 3) * 8;
        const __half* src = (l < 2) ? Bh : Bl;
        uint32_t dst = st + OFFB + ((l < 2) ? 0u : 10240u) + r * 80 + kc * 2;
        CP16(dst, &src[(long long)(col0 + r) * ldb + k0 + kc]);
    }
}

// ---------------------------------------------------------------------------
// Dense GEMM core (shared by single and dual-z kernels)
// ---------------------------------------------------------------------------
template<int TERMS, int OUTM>
__device__ __forceinline__ void gemm_body(
    const __half* __restrict__ Ah, const __half* __restrict__ Al,
    const __half* __restrict__ Bh, const __half* __restrict__ Bl,
    const float* __restrict__ bias,
    float* __restrict__ C, __half* __restrict__ Ch,
    int K, int lda, int ldb, int ldc, char* dynsm)
{
    constexpr uint32_t STAGE = (TERMS == 3) ? 40960u : (TERMS == 2) ? 30720u : 20480u;
    constexpr uint32_t OFFB  = (TERMS == 1) ? 10240u : 20480u;
    const int tid  = threadIdx.x;
    const int wid  = tid >> 5;
    const int lane = tid & 31;
    const int row0 = blockIdx.y * BM;
    const int col0 = blockIdx.x * BN;
    const int wm   = (wid & 3) * 32;
    const int wn   = (wid >> 2) * 64;
    const uint32_t smBase = smem_u32(dynsm);

    float acc[2][8][4];
    #pragma unroll
    for (int i = 0; i < 2; i++)
        #pragma unroll
        for (int j = 0; j < 8; j++)
            #pragma unroll
            for (int t = 0; t < 4; t++) acc[i][j][t] = 0.f;

    const int aRow = wm + (lane & 15);
    const int aColOff = (lane >> 4) << 3;
    const int bRow = wn + (lane & 7) + ((lane >> 4) << 3);
    const int bCol = ((lane >> 3) & 1) << 3;

    const int nch = K / BK;
    fill_stage_bt<TERMS>(smBase, Ah, Al, Bh, Bl, row0, col0, 0, lda, ldb, tid);
    CP_COMMIT();

    for (int ch = 0; ch < nch; ch++) {
        const uint32_t st = smBase + (ch & 1) * STAGE;
        if (ch + 1 < nch) {
            fill_stage_bt<TERMS>(smBase + ((ch + 1) & 1) * STAGE,
                                 Ah, Al, Bh, Bl, row0, col0, (ch + 1) * BK, lda, ldb, tid);
            CP_COMMIT();
            CP_WAIT(1);
        } else {
            CP_WAIT(0);
        }
        __syncthreads();

        #pragma unroll
        for (int kk = 0; kk < BK; kk += 16) {
            uint32_t ah[2][4], al[2][4];
            #pragma unroll
            for (int mi = 0; mi < 2; mi++) {
                uint32_t off = (aRow + mi * 16) * 80 + (kk + aColOff) * 2;
                LDSM4(ah[mi], st + off);
                if (TERMS >= 2) LDSM4(al[mi], st + 10240 + off);
            }
            #pragma unroll
            for (int ng = 0; ng < 4; ng++) {
                uint32_t bh[4], bl[4];
                uint32_t off = (bRow + ng * 16) * 80 + (kk + bCol) * 2;
                LDSM4(bh, st + OFFB + off);
                if (TERMS == 3) LDSM4(bl, st + OFFB + 10240 + off);
                #pragma unroll
                for (int mi = 0; mi < 2; mi++) {
                    #pragma unroll
                    for (int s = 0; s < 2; s++) {
                        float* d = acc[mi][ng * 2 + s];
                        MMA16816(d, ah[mi], bh[s * 2], bh[s * 2 + 1]);
                        if (TERMS == 3)
                            MMA16816(d, ah[mi], bl[s * 2], bl[s * 2 + 1]);
                        if (TERMS >= 2)
                            MMA16816(d, al[mi], bh[s * 2], bh[s * 2 + 1]);
                    }
                }
            }
        }
        __syncthreads();
    }

    #pragma unroll
    for (int mi = 0; mi < 2; mi++) {
        int r = row0 + wm + mi * 16 + (lane >> 2);
        #pragma unroll
        for (int nf = 0; nf < 8; nf++) {
            int c = col0 + wn + nf * 8 + (lane & 3) * 2;
            float b0 = 0.f, b1 = 0.f;
            if (bias) { b0 = bias[c]; b1 = bias[c + 1]; }
            float v00 = acc[mi][nf][0] + b0, v01 = acc[mi][nf][1] + b1;
            float v10 = acc[mi][nf][2] + b0, v11 = acc[mi][nf][3] + b1;
            long long i0 = (long long)r * ldc + c;
            long long i1 = (long long)(r + 8) * ldc + c;
            if (OUTM == 0) {
                *reinterpret_cast<float2*>(C + i0) = make_float2(v00, v01);
                *reinterpret_cast<float2*>(C + i1) = make_float2(v10, v11);
            } else {
                *reinterpret_cast<uint32_t*>(Ch + i0) = packh(v00, v01);
                *reinterpret_cast<uint32_t*>(Ch + i1) = packh(v10, v11);
            }
        }
    }
}

template<int TERMS, int OUTM>
__global__ void __launch_bounds__(NTHREADS, 2)
mma_gemm(const __half* __restrict__ Ah, const __half* __restrict__ Al,
         const __half* __restrict__ Bh, const __half* __restrict__ Bl,
         const float* __restrict__ bias,
         float* __restrict__ C, __half* __restrict__ Ch,
         int K, int lda, int ldb, int ldc)
{
    extern __shared__ __align__(16) char dynsm[];
    gemm_body<TERMS, OUTM>(Ah, Al, Bh, Bl, bias, C, Ch, K, lda, ldb, ldc, dynsm);
}

// Dual GEMM: blockIdx.z selects (B, bias, C) set — merges Q-proj and K-proj
// so the second GEMM's tiles backfill the first one's tail drain.
__global__ void __launch_bounds__(NTHREADS, 2)
mma_gemm_qk(const __half* __restrict__ Ah, const __half* __restrict__ Al,
            const __half* __restrict__ B0h, const __half* __restrict__ B0l,
            const float* __restrict__ bias0, float* __restrict__ C0,
            const __half* __restrict__ B1h, const __half* __restrict__ B1l,
            const float* __restrict__ bias1, float* __restrict__ C1,
            int K, int lda, int ldb, int ldc)
{
    extern __shared__ __align__(16) char dynsm[];
    const bool z = (blockIdx.z != 0);
    gemm_body<3, 0>(Ah, Al, z ? B1h : B0h, z ? B1l : B0l,
                    z ? bias1 : bias0, z ? C1 : C0, nullptr,
                    K, lda, ldb, ldc, dynsm);
}

// ---------------------------------------------------------------------------
// Flash attention: S = Q@K^T (3-term fp16 split), online softmax,
// O = P@V (2-term: P hi/lo x V full fp16). O written single fp16.
// ---------------------------------------------------------------------------
__global__ void __launch_bounds__(256, 1)
flash_kernel(const __half* __restrict__ qh, const __half* __restrict__ ql,
             const __half* __restrict__ kh, const __half* __restrict__ kl,
             const __half* __restrict__ vf,
             __half* __restrict__ oh)
{
    extern __shared__ __align__(16) char fsm[];
    const uint32_t smb = smem_u32(fsm);
    const int tid  = threadIdx.x;
    const int wid  = tid >> 5;
    const int lane = tid & 31;
    const int q0   = blockIdx.x * 128;
    const int bh   = blockIdx.y;
    const long long tokb = (long long)(bh / HEADS) * SEQ;
    const int hcol = (bh % HEADS) * DHEAD;
    const int wm   = wid * 16;

    auto fill = [&](uint32_t off, const __half* __restrict__ src, int rowStart) {
        #pragma unroll
        for (int l = 0; l < 8; l++) {
            int idx = tid + l * 256;
            int r = idx >> 4, c = idx & 15;
            CP16(smb + off + r * FROWB + c * 16,
                 &src[(tokb + rowStart + r) * INNER + hcol + c * 8]);
        }
    };

    fill(OFF_QH, qh, q0); fill(OFF_QL, ql, q0);
    fill(OFF_KH, kh, 0);  fill(OFF_KL, kl, 0);
    CP_COMMIT();
    fill(OFF_V, vf, 0);
    CP_COMMIT();

    float oacc[16][4];
    #pragma unroll
    for (int g = 0; g < 16; g++)
        #pragma unroll
        for (int t = 0; t < 4; t++) oacc[g][t] = 0.f;
    float m0 = -1e30f, m1 = -1e30f, l0 = 0.f, l1 = 0.f;

    for (int it = 0; it < 16; it++) {
        CP_WAIT(1);
        __syncthreads();

        // ---- S = Q @ K^T (3-term) ----
        float sn[16][4];
        #pragma unroll
        for (int j = 0; j < 16; j++)
            #pragma unroll
            for (int t = 0; t < 4; t++) sn[j][t] = 0.f;

        #pragma unroll
        for (int k8 = 0; k8 < 8; k8++) {
            const int kk = k8 * 16;
            uint32_t qfh[4], qfl[4];
            uint32_t qoff = (uint32_t)(wm + (lane & 15)) * FROWB
                          + (uint32_t)(kk + ((lane >> 4) << 3)) * 2;
            LDSM4(qfh, smb + OFF_QH + qoff);
            LDSM4(qfl, smb + OFF_QL + qoff);
            #pragma unroll
            for (int g = 0; g < 8; g++) {
                uint32_t kbh[4], kbl[4];
                uint32_t koff = (uint32_t)(g * 16 + (lane & 7) + ((lane >> 4) << 3)) * FROWB
                              + (uint32_t)(kk + (((lane >> 3) & 1) << 3)) * 2;
                LDSM4(kbh, smb + OFF_KH + koff);
                LDSM4(kbl, smb + OFF_KL + koff);
                #pragma unroll
                for (int s2 = 0; s2 < 2; s2++) {
                    float* d = sn[g * 2 + s2];
                    MMA16816(d, qfh, kbh[s2 * 2], kbh[s2 * 2 + 1]);
                    MMA16816(d, qfh, kbl[s2 * 2], kbl[s2 * 2 + 1]);
                    MMA16816(d, qfl, kbh[s2 * 2], kbh[s2 * 2 + 1]);
                }
            }
        }
        __syncthreads();
        if (it < 15) {
            fill(OFF_KH, kh, (it + 1) * 128);
            fill(OFF_KL, kl, (it + 1) * 128);
            CP_COMMIT();
        }

        // ---- online softmax ----
        float rm0 = -1e30f, rm1 = -1e30f;
        #pragma unroll
        for (int j = 0; j < 16; j++) {
            rm0 = fmaxf(rm0, fmaxf(sn[j][0], sn[j][1]));
            rm1 = fmaxf(rm1, fmaxf(sn[j][2], sn[j][3]));
        }
        rm0 = fmaxf(rm0, __shfl_xor_sync(0xFFFFFFFFu, rm0, 1));
        rm0 = fmaxf(rm0, __shfl_xor_sync(0xFFFFFFFFu, rm0, 2));
        rm1 = fmaxf(rm1, __shfl_xor_sync(0xFFFFFFFFu, rm1, 1));
        rm1 = fmaxf(rm1, __shfl_xor_sync(0xFFFFFFFFu, rm1, 2));
        const float mn0 = fmaxf(m0, rm0), mn1 = fmaxf(m1, rm1);
        const float sc0 = __expf(m0 - mn0), sc1 = __expf(m1 - mn1);
        float rs0 = 0.f, rs1 = 0.f;
        #pragma unroll
        for (int j = 0; j < 16; j++) {
            sn[j][0] = __expf(sn[j][0] - mn0);
            sn[j][1] = __expf(sn[j][1] - mn0);
            sn[j][2] = __expf(sn[j][2] - mn1);
            sn[j][3] = __expf(sn[j][3] - mn1);
            rs0 += sn[j][0] + sn[j][1];
            rs1 += sn[j][2] + sn[j][3];
        }
        rs0 += __shfl_xor_sync(0xFFFFFFFFu, rs0, 1);
        rs0 += __shfl_xor_sync(0xFFFFFFFFu, rs0, 2);
        rs1 += __shfl_xor_sync(0xFFFFFFFFu, rs1, 1);
        rs1 += __shfl_xor_sync(0xFFFFFFFFu, rs1, 2);
        l0 = l0 * sc0 + rs0;  l1 = l1 * sc1 + rs1;
        m0 = mn0;  m1 = mn1;
        #pragma unroll
        for (int g = 0; g < 16; g++) {
            oacc[g][0] *= sc0;  oacc[g][1] *= sc0;
            oacc[g][2] *= sc1;  oacc[g][3] *= sc1;
        }

        if (it < 15) CP_WAIT(1); else CP_WAIT(0);
        __syncthreads();

        // ---- O += P @ V (2-term) ----
        #pragma unroll
        for (int s = 0; s < 8; s++) {
            const float* f0 = sn[2 * s];
            const float* f1 = sn[2 * s + 1];
            uint32_t pah[4], pal[4];
            {
                float h00 = hhf(f0[0]), h01 = hhf(f0[1]), h02 = hhf(f0[2]), h03 = hhf(f0[3]);
                float h10 = hhf(f1[0]), h11 = hhf(f1[1]), h12 = hhf(f1[2]), h13 = hhf(f1[3]);
                pah[0] = packh(h00, h01);  pal[0] = packh(f0[0] - h00, f0[1] - h01);
                pah[1] = packh(h02, h03);  pal[1] = packh(f0[2] - h02, f0[3] - h03);
                pah[2] = packh(h10, h11);  pal[2] = packh(f1[0] - h10, f1[1] - h11);
                pah[3] = packh(h12, h13);  pal[3] = packh(f1[2] - h12, f1[3] - h13);
            }
            #pragma unroll
            for (int g = 0; g < 8; g++) {
                uint32_t vb[4];
                uint32_t voff = (uint32_t)(s * 16 + (lane & 7) + (((lane >> 3) & 1) << 3)) * FROWB
                              + (uint32_t)(g * 16 + ((lane >> 4) << 3)) * 2;
                LDSM4T(vb, smb + OFF_V + voff);
                #pragma unroll
                for (int s2 = 0; s2 < 2; s2++) {
                    float* d = oacc[g * 2 + s2];
                    MMA16816(d, pah, vb[s2 * 2], vb[s2 * 2 + 1]);
                    MMA16816(d, pal, vb[s2 * 2], vb[s2 * 2 + 1]);
                }
            }
        }
        __syncthreads();
        if (it < 15) {
            fill(OFF_V, vf, (it + 1) * 128);
            CP_COMMIT();
        }
    }

    // ---- normalize + write O as single fp16 ----
    const float inv0 = 1.f / l0, inv1 = 1.f / l1;
    const int r0 = q0 + wm + (lane >> 2);
    #pragma unroll
    for (int g = 0; g < 16; g++) {
        const int c = hcol + g * 8 + (lane & 3) * 2;
        long long i0 = (tokb + r0) * INNER + c;
        long long i1 = (tokb + r0 + 8) * INNER + c;
        *reinterpret_cast<uint32_t*>(oh + i0) =
            packh(oacc[g][0] * inv0, oacc[g][1] * inv0);
        *reinterpret_cast<uint32_t*>(oh + i1) =
            packh(oacc[g][2] * inv1, oacc[g][3] * inv1);
    }
}

// ---------------------------------------------------------------------------
// Fused RMSNorm + RoPE + scales; fp32 in, fp16 hi/lo out (q and k).
// ---------------------------------------------------------------------------
__global__ void __launch_bounds__(256)
normrope_kernel(const float* __restrict__ q, const float* __restrict__ k,
                const float* __restrict__ rope,
                const float* __restrict__ wq, const float* __restrict__ wk,
                const float* __restrict__ hks,
                __half* __restrict__ qh, __half* __restrict__ ql,
                __half* __restrict__ kh, __half* __restrict__ kl)
{
    const int tok = blockIdx.x;
    const int s   = tok & (SEQ - 1);
    const bool isK = (blockIdx.y == 1);
    const float* x = (isK ? k : q) + (long long)tok * INNER;
    __half* outh = (isK ? kh : qh) + (long long)tok * INNER;
    __half* outl = (isK ? kl : ql) + (long long)tok * INNER;
    const float* w = isK ? wk : wq;
    const int tid = threadIdx.x;

    float2 vals[4];
    float ss = 0.f;
    #pragma unroll
    for (int l = 0; l < 4; l++) {
        int p = tid + 256 * l;
        float2 vv = *reinterpret_cast<const float2*>(&x[2 * p]);
        ss += vv.x * vv.x + vv.y * vv.y;
        vals[l] = vv;
    }
    #pragma unroll
    for (int off = 16; off; off >>= 1) ss += __shfl_xor_sync(0xFFFFFFFFu, ss, off);
    __shared__ float sred[8];
    if ((tid & 31) == 0) sred[tid >> 5] = ss;
    __syncthreads();
    float tot = 0.f;
    #pragma unroll
    for (int i = 0; i < 8; i++) tot += sred[i];
    const float inv = rsqrtf(tot * (1.f / (float)INNER) + 1e-5f);

    #pragma unroll
    for (int l = 0; l < 4; l++) {
        int p = tid + 256 * l;
        int h = p >> 6;
        int i = p & 63;
        float c  = rope[(long long)s * 256 + 2 * i];
        float sn = rope[(long long)s * 256 + 128 + 2 * i + 1];
        float x1 = vals[l].x * inv * w[2 * p];
        float x2 = vals[l].y * inv * w[2 * p + 1];
        float e = x1 * c - x2 * sn;
        float o = x1 * sn + x2 * c;
        float mult;
        if (isK) {
            mult = (s < HIST) ? (1.f + 9.f / (1.f + __expf(-hks[h]))) : 1.f;
        } else {
            mult = QSCALE;
        }
        e *= mult; o *= mult;
        float eh = hhf(e), oh2 = hhf(o);
        *reinterpret_cast<uint32_t*>(&outh[2 * p]) = packh(eh, oh2);
        *reinterpret_cast<uint32_t*>(&outl[2 * p]) = packh(e - eh, o - oh2);
    }
}

// ---------------------------------------------------------------------------
extern "C" void kernel_launch(void* const* d_in, const int* in_sizes, int n_in,
                              void* d_out, int out_size)
{
    const float* hs   = (const float*)d_in[0];
    const float* rope = (const float*)d_in[1];
    const float* Wq   = (const float*)d_in[2];
    const float* bq   = (const float*)d_in[3];
    const float* Wk   = (const float*)d_in[4];
    const float* bk   = (const float*)d_in[5];
    const float* Wv   = (const float*)d_in[6];
    const float* bv   = (const float*)d_in[7];
    const float* nqw  = (const float*)d_in[8];
    const float* nkw  = (const float*)d_in[9];
    const float* hks  = (const float*)d_in[10];
    const float* Wo   = (const float*)d_in[11];
    const float* bo   = (const float*)d_in[12];
    float* out = (float*)d_out;

    float *q, *k;
    __half *ah, *al, *wqh, *wql, *wkh, *wkl, *wv, *wo;
    __half *qh, *ql, *kh, *kl, *vf;
    cudaGetSymbolAddress((void**)&q,   g_q);
    cudaGetSymbolAddress((void**)&k,   g_k);
    cudaGetSymbolAddress((void**)&ah,  g_ah);
    cudaGetSymbolAddress((void**)&al,  g_al);
    cudaGetSymbolAddress((void**)&wqh, g_wqh);
    cudaGetSymbolAddress((void**)&wql, g_wql);
    cudaGetSymbolAddress((void**)&wkh, g_wkh);
    cudaGetSymbolAddress((void**)&wkl, g_wkl);
    cudaGetSymbolAddress((void**)&wv,  g_wv);
    cudaGetSymbolAddress((void**)&wo,  g_wo);
    cudaGetSymbolAddress((void**)&qh,  g_qh);
    cudaGetSymbolAddress((void**)&ql,  g_ql);
    cudaGetSymbolAddress((void**)&kh,  g_kh);
    cudaGetSymbolAddress((void**)&kl,  g_kl);
    cudaGetSymbolAddress((void**)&vf,  g_vf);

    cudaFuncSetAttribute(mma_gemm_qk,
        cudaFuncAttributeMaxDynamicSharedMemorySize, 81920);
    cudaFuncSetAttribute(mma_gemm<2, 2>,
        cudaFuncAttributeMaxDynamicSharedMemorySize, 61440);
    cudaFuncSetAttribute(mma_gemm<1, 0>,
        cudaFuncAttributeMaxDynamicSharedMemorySize, 40960);
    cudaFuncSetAttribute(flash_kernel,
        cudaFuncAttributeMaxDynamicSharedMemorySize, FSMEM);

    dim3 blk(NTHREADS);

    // 0) converts: hs split; Wq+Wk split (merged); Wv+Wo full (merged)
    convert_split2<<<dim3(TOKENS * DIMM / 1024, 1), 256>>>(
        hs, ah, al, hs, ah, al);
    convert_split2<<<dim3(INNER * DIMM / 1024, 2), 256>>>(
        Wq, wqh, wql, Wk, wkh, wkl);
    convert_full2<<<dim3(INNER * DIMM / 1024, 2), 256>>>(
        Wv, wv, Wo, wo);

    // 1) Q+K projections merged (3-term, z selects), then V (2-term, fp16 out)
    dim3 gqk(INNER / BN, TOKENS / BM, 2);
    mma_gemm_qk<<<gqk, blk, 81920>>>(ah, al,
        wqh, wql, bq, q,
        wkh, wkl, bk, k,
        DIMM, DIMM, DIMM, INNER);
    dim3 g1(INNER / BN, TOKENS / BM, 1);
    mma_gemm<2, 2><<<g1, blk, 61440>>>(ah, al, wv, nullptr, bv, nullptr, vf,
        DIMM, DIMM, DIMM, INNER);

    // 2) RMSNorm + RoPE + scales -> fp16 splits
    normrope_kernel<<<dim3(TOKENS, 2), blk>>>(q, k, rope, nqw, nkw, hks,
                                              qh, ql, kh, kl);

    // 3-5) Flash attention -> attn-out single fp16 into g_ah
    flash_kernel<<<dim3(SEQ / 128, BATCH * HEADS), blk, FSMEM>>>(
        qh, ql, kh, kl, vf, ah);

    // 6) Output projection (1-term, fp32 out + bias)
    dim3 g4(DIMM / BN, TOKENS / BM, 1);
    mma_gemm<1, 0><<<g4, blk, 40960>>>(ah, nullptr, wo, nullptr, bo, out, nullptr,
        INNER, INNER, INNER, DIMM);
}

// round 15
// speedup vs baseline: 3.6926x; 1.0352x over previous
#include <cuda_runtime.h>
#include <cuda_fp16.h>
#include <stdint.h>
#include <math.h>

// Problem constants
#define BATCH   2
#define SEQ     2048
#define DIMM    2048
#define HEADS   16
#define DHEAD   128
#define INNER   2048
#define TOKENS  (BATCH*SEQ)
#define HIST    512
#define QSCALE  0.08838834764831845f

// Dense GEMM tiling
#define BM 128
#define BN 128
#define BK 32
#define NTHREADS 256

// Flash kernel smem: 5 tiles of 128 rows x 272B (QH, QL, KH, KL, V)
#define FROWB  272
#define FT_SZ  (128 * FROWB)
#define OFF_QH 0
#define OFF_QL (1 * FT_SZ)
#define OFF_KH (2 * FT_SZ)
#define OFF_KL (3 * FT_SZ)
#define OFF_V  (4 * FT_SZ)
#define FSMEM  (5 * FT_SZ)            // 174080

// fp32 scratch
__device__ float g_q[(size_t)TOKENS * INNER];
__device__ float g_k[(size_t)TOKENS * INNER];
// fp16 scratch
__device__ __half g_ah[(size_t)TOKENS * INNER];   // hs split hi; later attn-out (single)
__device__ __half g_al[(size_t)TOKENS * INNER];   // hs split lo
__device__ __half g_wqh[(size_t)INNER * DIMM];    // Q/K weights hi/lo split
__device__ __half g_wql[(size_t)INNER * DIMM];
__device__ __half g_wkh[(size_t)INNER * DIMM];
__device__ __half g_wkl[(size_t)INNER * DIMM];
__device__ __half g_wv[(size_t)INNER * DIMM];     // Wv full fp16 (2-term stage)
__device__ __half g_wo[(size_t)INNER * DIMM];     // Wo full fp16 (1-term stage)
__device__ __half g_qh[(size_t)TOKENS * INNER];
__device__ __half g_ql[(size_t)TOKENS * INNER];
__device__ __half g_kh[(size_t)TOKENS * INNER];
__device__ __half g_kl[(size_t)TOKENS * INNER];
__device__ __half g_vf[(size_t)TOKENS * INNER];   // V single fp16

__device__ __forceinline__ uint32_t smem_u32(const void* p) {
    uint32_t a;
    asm("{ .reg .u64 t; cvta.to.shared.u64 t, %1; cvt.u32.u64 %0, t; }" : "=r"(a) : "l"(p));
    return a;
}

#define CP16(dst, src) \
    asm volatile("cp.async.cg.shared.global [%0], [%1], 16;" \
        :: "r"(dst), "l"(__cvta_generic_to_global(src)) : "memory")
#define CP_COMMIT() asm volatile("cp.async.commit_group;" ::: "memory")
#define CP_WAIT(n)  asm volatile("cp.async.wait_group %0;" :: "n"(n) : "memory")

#define LDSM4(r, a) \
    asm volatile("ldmatrix.sync.aligned.m8n8.x4.shared.b16 {%0,%1,%2,%3}, [%4];" \
        : "=r"((r)[0]), "=r"((r)[1]), "=r"((r)[2]), "=r"((r)[3]) : "r"(a))
#define LDSM4T(r, a) \
    asm volatile("ldmatrix.sync.aligned.m8n8.x4.trans.shared.b16 {%0,%1,%2,%3}, [%4];" \
        : "=r"((r)[0]), "=r"((r)[1]), "=r"((r)[2]), "=r"((r)[3]) : "r"(a))

#define MMA16816(d, a, b0, b1) \
    asm volatile("mma.sync.aligned.m16n8k16.row.col.f32.f16.f16.f32 " \
        "{%0,%1,%2,%3}, {%4,%5,%6,%7}, {%8,%9}, {%0,%1,%2,%3};" \
        : "+f"((d)[0]), "+f"((d)[1]), "+f"((d)[2]), "+f"((d)[3]) \
        : "r"((a)[0]), "r"((a)[1]), "r"((a)[2]), "r"((a)[3]), "r"(b0), "r"(b1))

__device__ __forceinline__ uint32_t packh(float a, float b) {
    __half2 t = __floats2half2_rn(a, b);
    return *reinterpret_cast<uint32_t*>(&t);
}
__device__ __forceinline__ float hhf(float x) {
    return __half2float(__float2half_rn(x));
}

// ---------------------------------------------------------------------------
// fp32 -> fp16 hi/lo split; y selects hs / Wq / Wk (hs has 2x blocks).
// ---------------------------------------------------------------------------
__global__ void __launch_bounds__(256)
convert_split3(const float* __restrict__ x0, __half* __restrict__ h0,
               __half* __restrict__ l0, int n0,
               const float* __restrict__ x1, __half* __restrict__ h1,
               __half* __restrict__ l1, int n1,
               const float* __restrict__ x2, __half* __restrict__ h2,
               __half* __restrict__ l2, int n2)
{
    const float* x; __half *h, *l; int n;
    if (blockIdx.y == 0)      { x = x0; h = h0; l = l0; n = n0; }
    else if (blockIdx.y == 1) { x = x1; h = h1; l = l1; n = n1; }
    else                      { x = x2; h = h2; l = l2; n = n2; }
    if ((int)blockIdx.x >= n) return;
    int i = (blockIdx.x * 256 + threadIdx.x) * 4;
    float4 v = *reinterpret_cast<const float4*>(x + i);
    float a0 = hhf(v.x), a1 = hhf(v.y), a2 = hhf(v.z), a3 = hhf(v.w);
    *reinterpret_cast<uint2*>(h + i) = make_uint2(packh(a0, a1), packh(a2, a3));
    *reinterpret_cast<uint2*>(l + i) =
        make_uint2(packh(v.x - a0, v.y - a1), packh(v.z - a2, v.w - a3));
}

// fp32 -> single fp16; y-dim selects one of two tensors.
__global__ void __launch_bounds__(256)
convert_full2(const float* __restrict__ x0, __half* __restrict__ h0,
              const float* __restrict__ x1, __half* __restrict__ h1)
{
    const float* x = blockIdx.y ? x1 : x0;
    __half* h = blockIdx.y ? h1 : h0;
    int i = (blockIdx.x * 256 + threadIdx.x) * 4;
    float4 v = *reinterpret_cast<const float4*>(x + i);
    *reinterpret_cast<uint2*>(h + i) =
        make_uint2(packh(v.x, v.y), packh(v.z, v.w));
}

// ---------------------------------------------------------------------------
// Dense GEMM tile fill (TERMS as in gemm_body below)
// ---------------------------------------------------------------------------
template<int TERMS>
__device__ __forceinline__ void fill_stage_bt(uint32_t st,
    const __half* __restrict__ Ah, const __half* __restrict__ Al,
    const __half* __restrict__ Bh, const __half* __restrict__ Bl,
    int row0, int col0, int k0, int lda, int ldb, int tid)
{
    constexpr uint32_t OFFB = (TERMS == 1) ? 10240u : 20480u;
    #pragma unroll
    for (int l = 0; l < ((TERMS >= 2) ? 4 : 2); l++) {
        int c = (tid + l * 256) & 511;
        int r = c >> 2;
        int kc = (c & 3) * 8;
        const __half* src = (l < 2) ? Ah : Al;
        uint32_t dst = st + ((l < 2) ? 0u : 10240u) + r * 80 + kc * 2;
        CP16(dst, &src[(long long)(row0 + r) * lda + k0 + kc]);
    }
    #pragma unroll
    for (int l = 0; l < ((TERMS == 3) ? 4 : 2); l++) {
        int c = (tid + l * 256) & 511;
        int r = c >> 2;
        int kc = (c & 3) * 8;
        const __half* src = (l < 2) ? Bh : Bl;
        uint32_t dst = st + OFFB + ((l < 2) ? 0u : 10240u) + r * 80 + kc * 2;
        CP16(dst, &src[(long long)(col0 + r) * ldb + k0 + kc]);
    }
}

// ---------------------------------------------------------------------------
// Dense GEMM core (explicit row0/col0 so callers can flatten grids)
// ---------------------------------------------------------------------------
template<int TERMS, int OUTM>
__device__ __forceinline__ void gemm_body(
    const __half* __restrict__ Ah, const __half* __restrict__ Al,
    const __half* __restrict__ Bh, const __half* __restrict__ Bl,
    const float* __restrict__ bias,
    float* __restrict__ C, __half* __restrict__ Ch,
    int K, int lda, int ldb, int ldc, int row0, int col0, char* dynsm)
{
    constexpr uint32_t STAGE = (TERMS == 3) ? 40960u : (TERMS == 2) ? 30720u : 20480u;
    constexpr uint32_t OFFB  = (TERMS == 1) ? 10240u : 20480u;
    const int tid  = threadIdx.x;
    const int wid  = tid >> 5;
    const int lane = tid & 31;
    const int wm   = (wid & 3) * 32;
    const int wn   = (wid >> 2) * 64;
    const uint32_t smBase = smem_u32(dynsm);

    float acc[2][8][4];
    #pragma unroll
    for (int i = 0; i < 2; i++)
        #pragma unroll
        for (int j = 0; j < 8; j++)
            #pragma unroll
            for (int t = 0; t < 4; t++) acc[i][j][t] = 0.f;

    const int aRow = wm + (lane & 15);
    const int aColOff = (lane >> 4) << 3;
    const int bRow = wn + (lane & 7) + ((lane >> 4) << 3);
    const int bCol = ((lane >> 3) & 1) << 3;

    const int nch = K / BK;
    fill_stage_bt<TERMS>(smBase, Ah, Al, Bh, Bl, row0, col0, 0, lda, ldb, tid);
    CP_COMMIT();

    for (int ch = 0; ch < nch; ch++) {
        const uint32_t st = smBase + (ch & 1) * STAGE;
        if (ch + 1 < nch) {
            fill_stage_bt<TERMS>(smBase + ((ch + 1) & 1) * STAGE,
                                 Ah, Al, Bh, Bl, row0, col0, (ch + 1) * BK, lda, ldb, tid);
            CP_COMMIT();
            CP_WAIT(1);
        } else {
            CP_WAIT(0);
        }
        __syncthreads();

        #pragma unroll
        for (int kk = 0; kk < BK; kk += 16) {
            uint32_t ah[2][4], al[2][4];
            #pragma unroll
            for (int mi = 0; mi < 2; mi++) {
                uint32_t off = (aRow + mi * 16) * 80 + (kk + aColOff) * 2;
                LDSM4(ah[mi], st + off);
                if (TERMS >= 2) LDSM4(al[mi], st + 10240 + off);
            }
            #pragma unroll
            for (int ng = 0; ng < 4; ng++) {
                uint32_t bh[4], bl[4];
                uint32_t off = (bRow + ng * 16) * 80 + (kk + bCol) * 2;
                LDSM4(bh, st + OFFB + off);
                if (TERMS == 3) LDSM4(bl, st + OFFB + 10240 + off);
                #pragma unroll
                for (int mi = 0; mi < 2; mi++) {
                    #pragma unroll
                    for (int s = 0; s < 2; s++) {
                        float* d = acc[mi][ng * 2 + s];
                        MMA16816(d, ah[mi], bh[s * 2], bh[s * 2 + 1]);
                        if (TERMS == 3)
                            MMA16816(d, ah[mi], bl[s * 2], bl[s * 2 + 1]);
                        if (TERMS >= 2)
                            MMA16816(d, al[mi], bh[s * 2], bh[s * 2 + 1]);
                    }
                }
            }
        }
        __syncthreads();
    }

    #pragma unroll
    for (int mi = 0; mi < 2; mi++) {
        int r = row0 + wm + mi * 16 + (lane >> 2);
        #pragma unroll
        for (int nf = 0; nf < 8; nf++) {
            int c = col0 + wn + nf * 8 + (lane & 3) * 2;
            float b0 = 0.f, b1 = 0.f;
            if (bias) { b0 = bias[c]; b1 = bias[c + 1]; }
            float v00 = acc[mi][nf][0] + b0, v01 = acc[mi][nf][1] + b1;
            float v10 = acc[mi][nf][2] + b0, v11 = acc[mi][nf][3] + b1;
            long long i0 = (long long)r * ldc + c;
            long long i1 = (long long)(r + 8) * ldc + c;
            if (OUTM == 0) {
                *reinterpret_cast<float2*>(C + i0) = make_float2(v00, v01);
                *reinterpret_cast<float2*>(C + i1) = make_float2(v10, v11);
            } else {
                *reinterpret_cast<uint32_t*>(Ch + i0) = packh(v00, v01);
                *reinterpret_cast<uint32_t*>(Ch + i1) = packh(v10, v11);
            }
        }
    }
}

// ---------------------------------------------------------------------------
// Fused QKV projection launch: flat 1D grid of 1536 tiles.
//   t in [0,512)    : Q projection  (3-term, fp32 out)
//   t in [512,1024) : K projection  (3-term, fp32 out)
//   t in [1024,1536): V projection  (2-term, fp16 out) — short tiles fill tail
// ---------------------------------------------------------------------------
__global__ void __launch_bounds__(NTHREADS, 2)
mma_gemm_qkv(const __half* __restrict__ Ah, const __half* __restrict__ Al,
             const __half* __restrict__ wqh, const __half* __restrict__ wql,
             const float* __restrict__ bq, float* __restrict__ q,
             const __half* __restrict__ wkh, const __half* __restrict__ wkl,
             const float* __restrict__ bk, float* __restrict__ k,
             const __half* __restrict__ wv, const float* __restrict__ bv,
             __half* __restrict__ vf)
{
    extern __shared__ __align__(16) char dynsm[];
    const int t = blockIdx.x;
    const int lt = t & 511;
    const int col0 = (lt & 15) * BN;
    const int row0 = (lt >> 4) * BM;
    if (t < 1024) {
        const bool isK = (t >= 512);
        gemm_body<3, 0>(Ah, Al, isK ? wkh : wqh, isK ? wkl : wql,
                        isK ? bk : bq, isK ? k : q, nullptr,
                        DIMM, DIMM, DIMM, INNER, row0, col0, dynsm);
    } else {
        gemm_body<2, 2>(Ah, Al, wv, nullptr, bv, nullptr, vf,
                        DIMM, DIMM, DIMM, INNER, row0, col0, dynsm);
    }
}

// Single GEMM (out-projection)
template<int TERMS, int OUTM>
__global__ void __launch_bounds__(NTHREADS, 2)
mma_gemm(const __half* __restrict__ Ah, const __half* __restrict__ Al,
         const __half* __restrict__ Bh, const __half* __restrict__ Bl,
         const float* __restrict__ bias,
         float* __restrict__ C, __half* __restrict__ Ch,
         int K, int lda, int ldb, int ldc)
{
    extern __shared__ __align__(16) char dynsm[];
    gemm_body<TERMS, OUTM>(Ah, Al, Bh, Bl, bias, C, Ch, K, lda, ldb, ldc,
                           blockIdx.y * BM, blockIdx.x * BN, dynsm);
}

// ---------------------------------------------------------------------------
// Flash attention: S = Q@K^T (3-term fp16 split), online softmax,
// O = P@V (2-term: P hi/lo x V full fp16). O written single fp16.
// ---------------------------------------------------------------------------
__global__ void __launch_bounds__(256, 1)
flash_kernel(const __half* __restrict__ qh, const __half* __restrict__ ql,
             const __half* __restrict__ kh, const __half* __restrict__ kl,
             const __half* __restrict__ vf,
             __half* __restrict__ oh)
{
    extern __shared__ __align__(16) char fsm[];
    const uint32_t smb = smem_u32(fsm);
    const int tid  = threadIdx.x;
    const int wid  = tid >> 5;
    const int lane = tid & 31;
    const int q0   = blockIdx.x * 128;
    const int bh   = blockIdx.y;
    const long long tokb = (long long)(bh / HEADS) * SEQ;
    const int hcol = (bh % HEADS) * DHEAD;
    const int wm   = wid * 16;

    auto fill = [&](uint32_t off, const __half* __restrict__ src, int rowStart) {
        #pragma unroll
        for (int l = 0; l < 8; l++) {
            int idx = tid + l * 256;
            int r = idx >> 4, c = idx & 15;
            CP16(smb + off + r * FROWB + c * 16,
                 &src[(tokb + rowStart + r) * INNER + hcol + c * 8]);
        }
    };

    fill(OFF_QH, qh, q0); fill(OFF_QL, ql, q0);
    fill(OFF_KH, kh, 0);  fill(OFF_KL, kl, 0);
    CP_COMMIT();
    fill(OFF_V, vf, 0);
    CP_COMMIT();

    float oacc[16][4];
    #pragma unroll
    for (int g = 0; g < 16; g++)
        #pragma unroll
        for (int t = 0; t < 4; t++) oacc[g][t] = 0.f;
    float m0 = -1e30f, m1 = -1e30f, l0 = 0.f, l1 = 0.f;

    for (int it = 0; it < 16; it++) {
        CP_WAIT(1);
        __syncthreads();

        // ---- S = Q @ K^T (3-term) ----
        float sn[16][4];
        #pragma unroll
        for (int j = 0; j < 16; j++)
            #pragma unroll
            for (int t = 0; t < 4; t++) sn[j][t] = 0.f;

        #pragma unroll
        for (int k8 = 0; k8 < 8; k8++) {
            const int kk = k8 * 16;
            uint32_t qfh[4], qfl[4];
            uint32_t qoff = (uint32_t)(wm + (lane & 15)) * FROWB
                          + (uint32_t)(kk + ((lane >> 4) << 3)) * 2;
            LDSM4(qfh, smb + OFF_QH + qoff);
            LDSM4(qfl, smb + OFF_QL + qoff);
            #pragma unroll
            for (int g = 0; g < 8; g++) {
                uint32_t kbh[4], kbl[4];
                uint32_t koff = (uint32_t)(g * 16 + (lane & 7) + ((lane >> 4) << 3)) * FROWB
                              + (uint32_t)(kk + (((lane >> 3) & 1) << 3)) * 2;
                LDSM4(kbh, smb + OFF_KH + koff);
                LDSM4(kbl, smb + OFF_KL + koff);
                #pragma unroll
                for (int s2 = 0; s2 < 2; s2++) {
                    float* d = sn[g * 2 + s2];
                    MMA16816(d, qfh, kbh[s2 * 2], kbh[s2 * 2 + 1]);
                    MMA16816(d, qfh, kbl[s2 * 2], kbl[s2 * 2 + 1]);
                    MMA16816(d, qfl, kbh[s2 * 2], kbh[s2 * 2 + 1]);
                }
            }
        }
        __syncthreads();
        if (it < 15) {
            fill(OFF_KH, kh, (it + 1) * 128);
            fill(OFF_KL, kl, (it + 1) * 128);
            CP_COMMIT();
        }

        // ---- online softmax ----
        float rm0 = -1e30f, rm1 = -1e30f;
        #pragma unroll
        for (int j = 0; j < 16; j++) {
            rm0 = fmaxf(rm0, fmaxf(sn[j][0], sn[j][1]));
            rm1 = fmaxf(rm1, fmaxf(sn[j][2], sn[j][3]));
        }
        rm0 = fmaxf(rm0, __shfl_xor_sync(0xFFFFFFFFu, rm0, 1));
        rm0 = fmaxf(rm0, __shfl_xor_sync(0xFFFFFFFFu, rm0, 2));
        rm1 = fmaxf(rm1, __shfl_xor_sync(0xFFFFFFFFu, rm1, 1));
        rm1 = fmaxf(rm1, __shfl_xor_sync(0xFFFFFFFFu, rm1, 2));
        const float mn0 = fmaxf(m0, rm0), mn1 = fmaxf(m1, rm1);
        const float sc0 = __expf(m0 - mn0), sc1 = __expf(m1 - mn1);
        float rs0 = 0.f, rs1 = 0.f;
        #pragma unroll
        for (int j = 0; j < 16; j++) {
            sn[j][0] = __expf(sn[j][0] - mn0);
            sn[j][1] = __expf(sn[j][1] - mn0);
            sn[j][2] = __expf(sn[j][2] - mn1);
            sn[j][3] = __expf(sn[j][3] - mn1);
            rs0 += sn[j][0] + sn[j][1];
            rs1 += sn[j][2] + sn[j][3];
        }
        rs0 += __shfl_xor_sync(0xFFFFFFFFu, rs0, 1);
        rs0 += __shfl_xor_sync(0xFFFFFFFFu, rs0, 2);
        rs1 += __shfl_xor_sync(0xFFFFFFFFu, rs1, 1);
        rs1 += __shfl_xor_sync(0xFFFFFFFFu, rs1, 2);
        l0 = l0 * sc0 + rs0;  l1 = l1 * sc1 + rs1;
        m0 = mn0;  m1 = mn1;
        #pragma unroll
        for (int g = 0; g < 16; g++) {
            oacc[g][0] *= sc0;  oacc[g][1] *= sc0;
            oacc[g][2] *= sc1;  oacc[g][3] *= sc1;
        }

        if (it < 15) CP_WAIT(1); else CP_WAIT(0);
        __syncthreads();

        // ---- O += P @ V (2-term) ----
        #pragma unroll
        for (int s = 0; s < 8; s++) {
            const float* f0 = sn[2 * s];
            const float* f1 = sn[2 * s + 1];
            uint32_t pah[4], pal[4];
            {
                float h00 = hhf(f0[0]), h01 = hhf(f0[1]), h02 = hhf(f0[2]), h03 = hhf(f0[3]);
                float h10 = hhf(f1[0]), h11 = hhf(f1[1]), h12 = hhf(f1[2]), h13 = hhf(f1[3]);
                pah[0] = packh(h00, h01);  pal[0] = packh(f0[0] - h00, f0[1] - h01);
                pah[1] = packh(h02, h03);  pal[1] = packh(f0[2] - h02, f0[3] - h03);
                pah[2] = packh(h10, h11);  pal[2] = packh(f1[0] - h10, f1[1] - h11);
                pah[3] = packh(h12, h13);  pal[3] = packh(f1[2] - h12, f1[3] - h13);
            }
            #pragma unroll
            for (int g = 0; g < 8; g++) {
                uint32_t vb[4];
                uint32_t voff = (uint32_t)(s * 16 + (lane & 7) + (((lane >> 3) & 1) << 3)) * FROWB
                              + (uint32_t)(g * 16 + ((lane >> 4) << 3)) * 2;
                LDSM4T(vb, smb + OFF_V + voff);
                #pragma unroll
                for (int s2 = 0; s2 < 2; s2++) {
                    float* d = oacc[g * 2 + s2];
                    MMA16816(d, pah, vb[s2 * 2], vb[s2 * 2 + 1]);
                    MMA16816(d, pal, vb[s2 * 2], vb[s2 * 2 + 1]);
                }
            }
        }
        __syncthreads();
        if (it < 15) {
            fill(OFF_V, vf, (it + 1) * 128);
            CP_COMMIT();
        }
    }

    // ---- normalize + write O as single fp16 ----
    const float inv0 = 1.f / l0, inv1 = 1.f / l1;
    const int r0 = q0 + wm + (lane >> 2);
    #pragma unroll
    for (int g = 0; g < 16; g++) {
        const int c = hcol + g * 8 + (lane & 3) * 2;
        long long i0 = (tokb + r0) * INNER + c;
        long long i1 = (tokb + r0 + 8) * INNER + c;
        *reinterpret_cast<uint32_t*>(oh + i0) =
            packh(oacc[g][0] * inv0, oacc[g][1] * inv0);
        *reinterpret_cast<uint32_t*>(oh + i1) =
            packh(oacc[g][2] * inv1, oacc[g][3] * inv1);
    }
}

// ---------------------------------------------------------------------------
// Fused RMSNorm + RoPE + scales; fp32 in, fp16 hi/lo out (q and k).
// ---------------------------------------------------------------------------
__global__ void __launch_bounds__(256)
normrope_kernel(const float* __restrict__ q, const float* __restrict__ k,
                const float* __restrict__ rope,
                const float* __restrict__ wq, const float* __restrict__ wk,
                const float* __restrict__ hks,
                __half* __restrict__ qh, __half* __restrict__ ql,
                __half* __restrict__ kh, __half* __restrict__ kl)
{
    const int tok = blockIdx.x;
    const int s   = tok & (SEQ - 1);
    const bool isK = (blockIdx.y == 1);
    const float* x = (isK ? k : q) + (long long)tok * INNER;
    __half* outh = (isK ? kh : qh) + (long long)tok * INNER;
    __half* outl = (isK ? kl : ql) + (long long)tok * INNER;
    const float* w = isK ? wk : wq;
    const int tid = threadIdx.x;

    float2 vals[4];
    float ss = 0.f;
    #pragma unroll
    for (int l = 0; l < 4; l++) {
        int p = tid + 256 * l;
        float2 vv = *reinterpret_cast<const float2*>(&x[2 * p]);
        ss += vv.x * vv.x + vv.y * vv.y;
        vals[l] = vv;
    }
    #pragma unroll
    for (int off = 16; off; off >>= 1) ss += __shfl_xor_sync(0xFFFFFFFFu, ss, off);
    __shared__ float sred[8];
    if ((tid & 31) == 0) sred[tid >> 5] = ss;
    __syncthreads();
    float tot = 0.f;
    #pragma unroll
    for (int i = 0; i < 8; i++) tot += sred[i];
    const float inv = rsqrtf(tot * (1.f / (float)INNER) + 1e-5f);

    #pragma unroll
    for (int l = 0; l < 4; l++) {
        int p = tid + 256 * l;
        int h = p >> 6;
        int i = p & 63;
        float c  = rope[(long long)s * 256 + 2 * i];
        float sn = rope[(long long)s * 256 + 128 + 2 * i + 1];
        float x1 = vals[l].x * inv * w[2 * p];
        float x2 = vals[l].y * inv * w[2 * p + 1];
        float e = x1 * c - x2 * sn;
        float o = x1 * sn + x2 * c;
        float mult;
        if (isK) {
            mult = (s < HIST) ? (1.f + 9.f / (1.f + __expf(-hks[h]))) : 1.f;
        } else {
            mult = QSCALE;
        }
        e *= mult; o *= mult;
        float eh = hhf(e), oh2 = hhf(o);
        *reinterpret_cast<uint32_t*>(&outh[2 * p]) = packh(eh, oh2);
        *reinterpret_cast<uint32_t*>(&outl[2 * p]) = packh(e - eh, o - oh2);
    }
}

// ---------------------------------------------------------------------------
extern "C" void kernel_launch(void* const* d_in, const int* in_sizes, int n_in,
                              void* d_out, int out_size)
{
    const float* hs   = (const float*)d_in[0];
    const float* rope = (const float*)d_in[1];
    const float* Wq   = (const float*)d_in[2];
    const float* bq   = (const float*)d_in[3];
    const float* Wk   = (const float*)d_in[4];
    const float* bk   = (const float*)d_in[5];
    const float* Wv   = (const float*)d_in[6];
    const float* bv   = (const float*)d_in[7];
    const float* nqw  = (const float*)d_in[8];
    const float* nkw  = (const float*)d_in[9];
    const float* hks  = (const float*)d_in[10];
    const float* Wo   = (const float*)d_in[11];
    const float* bo   = (const float*)d_in[12];
    float* out = (float*)d_out;

    float *q, *k;
    __half *ah, *al, *wqh, *wql, *wkh, *wkl, *wv, *wo;
    __half *qh, *ql, *kh, *kl, *vf;
    cudaGetSymbolAddress((void**)&q,   g_q);
    cudaGetSymbolAddress((void**)&k,   g_k);
    cudaGetSymbolAddress((void**)&ah,  g_ah);
    cudaGetSymbolAddress((void**)&al,  g_al);
    cudaGetSymbolAddress((void**)&wqh, g_wqh);
    cudaGetSymbolAddress((void**)&wql, g_wql);
    cudaGetSymbolAddress((void**)&wkh, g_wkh);
    cudaGetSymbolAddress((void**)&wkl, g_wkl);
    cudaGetSymbolAddress((void**)&wv,  g_wv);
    cudaGetSymbolAddress((void**)&wo,  g_wo);
    cudaGetSymbolAddress((void**)&qh,  g_qh);
    cudaGetSymbolAddress((void**)&ql,  g_ql);
    cudaGetSymbolAddress((void**)&kh,  g_kh);
    cudaGetSymbolAddress((void**)&kl,  g_kl);
    cudaGetSymbolAddress((void**)&vf,  g_vf);

    cudaFuncSetAttribute(mma_gemm_qkv,
        cudaFuncAttributeMaxDynamicSharedMemorySize, 81920);
    cudaFuncSetAttribute(mma_gemm<1, 0>,
        cudaFuncAttributeMaxDynamicSharedMemorySize, 40960);
    cudaFuncSetAttribute(flash_kernel,
        cudaFuncAttributeMaxDynamicSharedMemorySize, FSMEM);

    dim3 blk(NTHREADS);

    // 0) converts: hs+Wq+Wk splits merged; Wv+Wo full merged
    const int nHS = TOKENS * DIMM / 1024;   // 8192 blocks
    const int nW  = INNER * DIMM / 1024;    // 4096 blocks
    convert_split3<<<dim3(nHS, 3), 256>>>(hs, ah, al, nHS,
                                          Wq, wqh, wql, nW,
                                          Wk, wkh, wkl, nW);
    convert_full2<<<dim3(nW, 2), 256>>>(Wv, wv, Wo, wo);

    // 1) QKV projections fused into one launch (V tiles fill the tail)
    mma_gemm_qkv<<<1536, blk, 81920>>>(ah, al,
        wqh, wql, bq, q,
        wkh, wkl, bk, k,
        wv, bv, vf);

    // 2) RMSNorm + RoPE + scales -> fp16 splits
    normrope_kernel<<<dim3(TOKENS, 2), blk>>>(q, k, rope, nqw, nkw, hks,
                                              qh, ql, kh, kl);

    // 3-5) Flash attention -> attn-out single fp16 into g_ah
    flash_kernel<<<dim3(SEQ / 128, BATCH * HEADS), blk, FSMEM>>>(
        qh, ql, kh, kl, vf, ah);

    // 6) Output projection (1-term, fp32 out + bias)
    dim3 g4(DIMM / BN, TOKENS / BM, 1);
    mma_gemm<1, 0><<<g4, blk, 40960>>>(ah, nullptr, wo, nullptr, bo, out, nullptr,
        INNER, INNER, INNER, DIMM);
}